// round 2
// baseline (speedup 1.0000x reference)
#include <cuda_runtime.h>
#include <cuda_bf16.h>
#include <math.h>

#define NN   50000
#define EE   1600000
#define HH   32
#define DOUT 128
#define EPS  1e-5f
#define SLOPE 0.1f

// ---------------------------------------------------------------------------
// Scratch (device globals — no allocations allowed). ~650 MB total.
// ---------------------------------------------------------------------------
static __device__ float g_ea[(size_t)EE * HH];        // edge embeddings   [E,32] 205 MB
static __device__ float g_C [(size_t)2 * EE * HH];    // Cf,Cs (per layer) 410 MB
static __device__ float g_hA[(size_t)NN * HH];        // node features ping
static __device__ float g_hB[(size_t)NN * HH];        // node features pong
static __device__ float g_P [(size_t)4 * NN * HH];    // Af,Bf,As,Bs [N,32]x4

// ---------------------------------------------------------------------------
// Kernel 1: out[M,32] = lrelu(bn( in[M,128] @ w[32,128]^T + b ))
// Tile: 64 rows x 32 ch per block of 256 threads; thread = (c, rowgroup of 8).
// ---------------------------------------------------------------------------
__global__ __launch_bounds__(256) void lin128_bn_lrelu_kernel(
    const float4* __restrict__ in4, int M,
    const float4* __restrict__ w4,                    // [32 rows][32 float4]
    const float* __restrict__ b,  const float* __restrict__ g,
    const float* __restrict__ be, const float* __restrict__ mm,
    const float* __restrict__ vv,
    float* __restrict__ out)
{
    __shared__ float4 wp[32 * 32];   // wp[k4*32 + c] = w[c][4k4 .. 4k4+3]
    __shared__ float4 xs4[64 * 8];   // 64 rows x 32 k-floats (8 float4) per chunk

    const int t = threadIdx.x;
    for (int i = t; i < 1024; i += 256) {
        int k4 = i >> 5, c = i & 31;
        wp[i] = w4[c * 32 + k4];
    }

    const int r0 = blockIdx.x * 64;
    const int c  = t & 31;
    const int rg = t >> 5;           // warp id 0..7 -> rows rg*8 .. rg*8+7

    float acc[8];
#pragma unroll
    for (int i = 0; i < 8; i++) acc[i] = 0.f;

    for (int kk4 = 0; kk4 < 32; kk4 += 8) {          // 4 chunks of 32 k-floats
        __syncthreads();                              // also covers wp staging (1st iter)
#pragma unroll
        for (int j = 0; j < 2; j++) {
            int idx = t + j * 256;
            int r = idx >> 3, q = idx & 7;
            int gr = r0 + r;
            xs4[idx] = (gr < M) ? in4[(size_t)gr * 32 + kk4 + q]
                                : make_float4(0.f, 0.f, 0.f, 0.f);
        }
        __syncthreads();
#pragma unroll
        for (int k4 = 0; k4 < 8; k4++) {
            float4 wv = wp[(kk4 + k4) * 32 + c];
#pragma unroll
            for (int i = 0; i < 8; i++) {
                float4 xv = xs4[(rg * 8 + i) * 8 + k4];   // broadcast within warp
                acc[i] = fmaf(xv.x, wv.x,
                         fmaf(xv.y, wv.y,
                         fmaf(xv.z, wv.z,
                         fmaf(xv.w, wv.w, acc[i]))));
            }
        }
    }

    const float scale = g[c] * rsqrtf(vv[c] + EPS);
    const float shift = be[c] - mm[c] * scale;
    const float bc    = b[c];
#pragma unroll
    for (int i = 0; i < 8; i++) {
        int row = r0 + rg * 8 + i;
        if (row < M) {
            float val = (acc[i] + bc) * scale + shift;
            out[(size_t)row * HH + c] = val > 0.f ? val : SLOPE * val;
        }
    }
}

// ---------------------------------------------------------------------------
// Kernel 2a: four projections  o_m[M,32] = in[M,32] @ w_m[32,32]^T
// Weight rows have stride 96 floats (24 float4). No bias (node projections).
// Tile: 32 rows per block of 256 threads; thread = (c, rowgroup of 4).
// ---------------------------------------------------------------------------
__global__ __launch_bounds__(256) void proj4_kernel(
    const float4* __restrict__ in4, int M,
    const float4* __restrict__ w0, const float4* __restrict__ w1,
    const float4* __restrict__ w2, const float4* __restrict__ w3,
    float* __restrict__ o0, float* __restrict__ o1,
    float* __restrict__ o2, float* __restrict__ o3)
{
    __shared__ float4 wp[4][256];   // [m][k4*32 + c]
    __shared__ float4 xs4[32 * 8];  // 32 rows x 32 k (8 float4)

    const int t = threadIdx.x;
    {
        int k4 = t >> 5, c = t & 31;
        wp[0][t] = w0[c * 24 + k4];
        wp[1][t] = w1[c * 24 + k4];
        wp[2][t] = w2[c * 24 + k4];
        wp[3][t] = w3[c * 24 + k4];
    }
    const int r0 = blockIdx.x * 32;
    {
        int r = t >> 3, q = t & 7;
        int gr = r0 + r;
        xs4[t] = (gr < M) ? in4[(size_t)gr * 8 + q]
                          : make_float4(0.f, 0.f, 0.f, 0.f);
    }
    __syncthreads();

    const int c  = t & 31;
    const int rg = t >> 5;          // rows rg*4 .. rg*4+3

    float acc[4][4];
#pragma unroll
    for (int m = 0; m < 4; m++)
#pragma unroll
        for (int i = 0; i < 4; i++) acc[m][i] = 0.f;

#pragma unroll
    for (int k4 = 0; k4 < 8; k4++) {
        float4 xv[4];
#pragma unroll
        for (int i = 0; i < 4; i++) xv[i] = xs4[(rg * 4 + i) * 8 + k4];
#pragma unroll
        for (int m = 0; m < 4; m++) {
            float4 wv = wp[m][k4 * 32 + c];
#pragma unroll
            for (int i = 0; i < 4; i++) {
                acc[m][i] = fmaf(xv[i].x, wv.x,
                            fmaf(xv[i].y, wv.y,
                            fmaf(xv[i].z, wv.z,
                            fmaf(xv[i].w, wv.w, acc[m][i]))));
            }
        }
    }

#pragma unroll
    for (int i = 0; i < 4; i++) {
        int row = r0 + rg * 4 + i;
        if (row < M) {
            size_t o = (size_t)row * HH + c;
            o0[o] = acc[0][i];
            o1[o] = acc[1][i];
            o2[o] = acc[2][i];
            o3[o] = acc[3][i];
        }
    }
}

// ---------------------------------------------------------------------------
// Kernel 2b: two projections with bias  o_m[M,32] = in[M,32] @ w_m[32,32]^T + b_m
// (edge projections, one layer at a time; C buffer is reused across layers)
// ---------------------------------------------------------------------------
__global__ __launch_bounds__(256) void proj2_kernel(
    const float4* __restrict__ in4, int M,
    const float4* __restrict__ w0, const float4* __restrict__ w1,
    const float* __restrict__ b0, const float* __restrict__ b1,
    float* __restrict__ o0, float* __restrict__ o1)
{
    __shared__ float4 wp[2][256];
    __shared__ float4 xs4[32 * 8];

    const int t = threadIdx.x;
    {
        int k4 = t >> 5, c = t & 31;
        wp[0][t] = w0[c * 24 + k4];
        wp[1][t] = w1[c * 24 + k4];
    }
    const int r0 = blockIdx.x * 32;
    {
        int r = t >> 3, q = t & 7;
        int gr = r0 + r;
        xs4[t] = (gr < M) ? in4[(size_t)gr * 8 + q]
                          : make_float4(0.f, 0.f, 0.f, 0.f);
    }
    __syncthreads();

    const int c  = t & 31;
    const int rg = t >> 5;

    float acc[2][4];
#pragma unroll
    for (int m = 0; m < 2; m++)
#pragma unroll
        for (int i = 0; i < 4; i++) acc[m][i] = 0.f;

#pragma unroll
    for (int k4 = 0; k4 < 8; k4++) {
        float4 xv[4];
#pragma unroll
        for (int i = 0; i < 4; i++) xv[i] = xs4[(rg * 4 + i) * 8 + k4];
#pragma unroll
        for (int m = 0; m < 2; m++) {
            float4 wv = wp[m][k4 * 32 + c];
#pragma unroll
            for (int i = 0; i < 4; i++) {
                acc[m][i] = fmaf(xv[i].x, wv.x,
                            fmaf(xv[i].y, wv.y,
                            fmaf(xv[i].z, wv.z,
                            fmaf(xv[i].w, wv.w, acc[m][i]))));
            }
        }
    }

    const float bb0 = b0[c];
    const float bb1 = b1[c];
#pragma unroll
    for (int i = 0; i < 4; i++) {
        int row = r0 + rg * 4 + i;
        if (row < M) {
            size_t o = (size_t)row * HH + c;
            o0[o] = acc[0][i] + bb0;
            o1[o] = acc[1][i] + bb1;
        }
    }
}

// ---------------------------------------------------------------------------
// Kernel 3: per-(edge,channel) gated message + scatter-add.
// f = Af[dst]+Bf[src]+Cf[e]; s = As[dst]+Bs[src]+Cs[e]
// msg = sigmoid(f) * softplus(s); hnext[dst] += msg (atomic)
// ---------------------------------------------------------------------------
__global__ __launch_bounds__(256) void edge_layer_kernel(
    const int* __restrict__ ei,               // [2,E]
    const float* __restrict__ Af, const float* __restrict__ Bf,
    const float* __restrict__ As, const float* __restrict__ Bs,
    const float* __restrict__ Cf, const float* __restrict__ Cs,
    float* __restrict__ hnext)
{
    int idx = blockIdx.x * 256 + threadIdx.x;
    if (idx >= EE * HH) return;
    int e = idx >> 5;
    int c = idx & 31;
    int src = ei[e];
    int dst = ei[EE + e];

    size_t od = (size_t)dst * HH + c;
    size_t os = (size_t)src * HH + c;
    float f = Af[od] + Bf[os] + Cf[idx];
    float s = As[od] + Bs[os] + Cs[idx];

    float sig = 1.f / (1.f + __expf(-f));
    float sp  = fmaxf(s, 0.f) + log1pf(__expf(-fabsf(s)));
    atomicAdd(&hnext[od], sig * sp);
}

// ---------------------------------------------------------------------------
// Kernel 4: out[N,128] = lrelu(bn( h[N,32] @ w_out[128,32]^T + b ))
// ---------------------------------------------------------------------------
__global__ __launch_bounds__(256) void out_kernel(
    const float4* __restrict__ h4,
    const float4* __restrict__ w4,            // [128 rows][8 float4]
    const float* __restrict__ b,  const float* __restrict__ g,
    const float* __restrict__ be, const float* __restrict__ mm,
    const float* __restrict__ vv,
    float* __restrict__ out)
{
    __shared__ float4 wp[8 * 128];   // wp[k4*128 + c]
    __shared__ float4 xs4[16 * 8];

    const int t = threadIdx.x;
#pragma unroll
    for (int j = 0; j < 4; j++) {
        int i = t + j * 256;
        int k4 = i >> 7, c = i & 127;
        wp[i] = w4[c * 8 + k4];
    }
    const int r0 = blockIdx.x * 16;
    if (t < 128) {
        int r = t >> 3, q = t & 7;
        int gr = r0 + r;
        xs4[t] = (gr < NN) ? h4[(size_t)gr * 8 + q]
                           : make_float4(0.f, 0.f, 0.f, 0.f);
    }
    __syncthreads();

    const int c  = t & 127;
    const int rg = t >> 7;           // 0..1 -> rows rg*8 .. rg*8+7

    float acc[8];
#pragma unroll
    for (int i = 0; i < 8; i++) acc[i] = 0.f;

#pragma unroll
    for (int k4 = 0; k4 < 8; k4++) {
        float4 wv = wp[k4 * 128 + c];
#pragma unroll
        for (int i = 0; i < 8; i++) {
            float4 xv = xs4[(rg * 8 + i) * 8 + k4];
            acc[i] = fmaf(xv.x, wv.x,
                     fmaf(xv.y, wv.y,
                     fmaf(xv.z, wv.z,
                     fmaf(xv.w, wv.w, acc[i]))));
        }
    }

    const float scale = g[c] * rsqrtf(vv[c] + EPS);
    const float shift = be[c] - mm[c] * scale;
    const float bc    = b[c];
#pragma unroll
    for (int i = 0; i < 8; i++) {
        int row = r0 + rg * 8 + i;
        if (row < NN) {
            float val = (acc[i] + bc) * scale + shift;
            out[(size_t)row * DOUT + c] = val > 0.f ? val : SLOPE * val;
        }
    }
}

// ---------------------------------------------------------------------------
// Launch
// ---------------------------------------------------------------------------
extern "C" void kernel_launch(void* const* d_in, const int* in_sizes, int n_in,
                              void* d_out, int out_size)
{
    const float* x     = (const float*)d_in[0];
    const int*   ei    = (const int*)  d_in[1];
    const float* eattr = (const float*)d_in[2];
    const float* w_in  = (const float*)d_in[3];
    const float* b_in  = (const float*)d_in[4];
    const float* g_in  = (const float*)d_in[5];
    const float* be_in = (const float*)d_in[6];
    const float* m_in  = (const float*)d_in[7];
    const float* v_in  = (const float*)d_in[8];
    const float* w_e   = (const float*)d_in[9];
    const float* b_e   = (const float*)d_in[10];
    const float* g_e   = (const float*)d_in[11];
    const float* be_e  = (const float*)d_in[12];
    const float* m_e   = (const float*)d_in[13];
    const float* v_e   = (const float*)d_in[14];
    const float* wf    = (const float*)d_in[15];   // [2,32,96]
    const float* bf    = (const float*)d_in[16];   // [2,32]
    const float* ws    = (const float*)d_in[17];
    const float* bs    = (const float*)d_in[18];
    const float* w_out = (const float*)d_in[19];   // [128,32]
    const float* b_out = (const float*)d_in[20];
    const float* g_out = (const float*)d_in[21];
    const float* be_out= (const float*)d_in[22];
    const float* m_out = (const float*)d_in[23];
    const float* v_out = (const float*)d_in[24];
    float* out = (float*)d_out;

    float *ea, *C, *hA, *hB, *P;
    cudaGetSymbolAddress((void**)&ea, g_ea);
    cudaGetSymbolAddress((void**)&C,  g_C);
    cudaGetSymbolAddress((void**)&hA, g_hA);
    cudaGetSymbolAddress((void**)&hB, g_hB);
    cudaGetSymbolAddress((void**)&P,  g_P);

    const size_t EH = (size_t)EE * HH;
    const size_t NH = (size_t)NN * HH;
    float* Cf = C;
    float* Cs = C + EH;
    float* Af = P;
    float* Bf = P + NH;
    float* As = P + 2 * NH;
    float* Bs = P + 3 * NH;

    // 1) node embedding  h0 = lrelu(bn(x @ w_in^T + b_in))
    lin128_bn_lrelu_kernel<<<(NN + 63) / 64, 256>>>(
        (const float4*)x, NN, (const float4*)w_in,
        b_in, g_in, be_in, m_in, v_in, hA);

    // 2) edge embedding  ea = lrelu(bn(edge_attr @ w_e^T + b_e))
    lin128_bn_lrelu_kernel<<<(EE + 63) / 64, 256>>>(
        (const float4*)eattr, EE, (const float4*)w_e,
        b_e, g_e, be_e, m_e, v_e, ea);

    // ---- layer 0 ----
    // edge projections: C = ea @ W_e-part^T + bias  (wf[l][o][64+k], rowstride 96)
    proj2_kernel<<<(EE + 31) / 32, 256>>>(
        (const float4*)ea, EE,
        (const float4*)(wf + 64), (const float4*)(ws + 64),
        bf, bs, Cf, Cs);
    // node projections: Af,Bf,As,Bs = h @ W-part^T
    proj4_kernel<<<(NN + 31) / 32, 256>>>(
        (const float4*)hA, NN,
        (const float4*)(wf),      (const float4*)(wf + 32),
        (const float4*)(ws),      (const float4*)(ws + 32),
        Af, Bf, As, Bs);
    cudaMemcpyAsync(hB, hA, NH * sizeof(float), cudaMemcpyDeviceToDevice, 0);
    edge_layer_kernel<<<(EE * HH + 255) / 256, 256>>>(
        ei, Af, Bf, As, Bs, Cf, Cs, hB);

    // ---- layer 1 ----
    proj2_kernel<<<(EE + 31) / 32, 256>>>(
        (const float4*)ea, EE,
        (const float4*)(wf + 3072 + 64), (const float4*)(ws + 3072 + 64),
        bf + 32, bs + 32, Cf, Cs);
    proj4_kernel<<<(NN + 31) / 32, 256>>>(
        (const float4*)hB, NN,
        (const float4*)(wf + 3072),      (const float4*)(wf + 3072 + 32),
        (const float4*)(ws + 3072),      (const float4*)(ws + 3072 + 32),
        Af, Bf, As, Bs);
    cudaMemcpyAsync(hA, hB, NH * sizeof(float), cudaMemcpyDeviceToDevice, 0);
    edge_layer_kernel<<<(EE * HH + 255) / 256, 256>>>(
        ei, Af, Bf, As, Bs, Cf, Cs, hA);

    // 4) output  out = lrelu(bn(h @ w_out^T + b_out))
    out_kernel<<<(NN + 15) / 16, 256>>>(
        (const float4*)hA, (const float4*)w_out,
        b_out, g_out, be_out, m_out, v_out, out);
}

// round 3
// speedup vs baseline: 1.2423x; 1.2423x over previous
#include <cuda_runtime.h>
#include <cuda_bf16.h>
#include <math.h>

#define NN   50000
#define EE   1600000
#define HH   32
#define DOUT 128
#define EPS  1e-5f
#define SLOPE 0.1f

// ---------------------------------------------------------------------------
// Scratch (device globals — no allocations allowed). ~231 MB total.
// ---------------------------------------------------------------------------
static __device__ float g_ea[(size_t)EE * HH];        // edge embeddings [E,32] 205 MB
static __device__ float g_hA[(size_t)NN * HH];        // node features ping
static __device__ float g_hB[(size_t)NN * HH];        // node features pong
static __device__ float g_Pd[(size_t)NN * 64];        // [Af|As] per node 12.8 MB
static __device__ float g_Ps[(size_t)NN * 64];        // [Bf|Bs] per node 12.8 MB

// ---------------------------------------------------------------------------
// Kernel 1: out[M,32] = lrelu(bn( in[M,128] @ w[32,128]^T + b ))
// Tile: 64 rows x 32 ch per block of 256 threads; thread = (c, rowgroup of 8).
// ---------------------------------------------------------------------------
template <bool FULL>
__global__ __launch_bounds__(256) void lin128_bn_lrelu_kernel(
    const float4* __restrict__ in4, int M,
    const float4* __restrict__ w4,                    // [32 rows][32 float4]
    const float* __restrict__ b,  const float* __restrict__ g,
    const float* __restrict__ be, const float* __restrict__ mm,
    const float* __restrict__ vv,
    float* __restrict__ out)
{
    __shared__ float4 wp[32 * 32];   // wp[k4*32 + c] = w[c][4k4 .. 4k4+3]
    __shared__ float4 xs4[64 * 8];   // 64 rows x 32 k-floats (8 float4) per chunk

    const int t = threadIdx.x;
    for (int i = t; i < 1024; i += 256) {
        int k4 = i >> 5, c = i & 31;
        wp[i] = w4[c * 32 + k4];
    }

    const int r0 = blockIdx.x * 64;
    const int c  = t & 31;
    const int rg = t >> 5;           // warp id 0..7 -> rows rg*8 .. rg*8+7

    float acc[8];
#pragma unroll
    for (int i = 0; i < 8; i++) acc[i] = 0.f;

    for (int kk4 = 0; kk4 < 32; kk4 += 8) {          // 4 chunks of 32 k-floats
        __syncthreads();                              // also covers wp staging (1st iter)
#pragma unroll
        for (int j = 0; j < 2; j++) {
            int idx = t + j * 256;
            int r = idx >> 3, q = idx & 7;
            int gr = r0 + r;
            if (FULL) {
                xs4[idx] = in4[(size_t)gr * 32 + kk4 + q];
            } else {
                xs4[idx] = (gr < M) ? in4[(size_t)gr * 32 + kk4 + q]
                                    : make_float4(0.f, 0.f, 0.f, 0.f);
            }
        }
        __syncthreads();
#pragma unroll
        for (int k4 = 0; k4 < 8; k4++) {
            float4 wv = wp[(kk4 + k4) * 32 + c];
#pragma unroll
            for (int i = 0; i < 8; i++) {
                float4 xv = xs4[(rg * 8 + i) * 8 + k4];   // broadcast within warp
                acc[i] = fmaf(xv.x, wv.x,
                         fmaf(xv.y, wv.y,
                         fmaf(xv.z, wv.z,
                         fmaf(xv.w, wv.w, acc[i]))));
            }
        }
    }

    const float scale = g[c] * rsqrtf(vv[c] + EPS);
    const float shift = be[c] - mm[c] * scale;
    const float bc    = b[c];
#pragma unroll
    for (int i = 0; i < 8; i++) {
        int row = r0 + rg * 8 + i;
        if (FULL || row < M) {
            float val = (acc[i] + bc) * scale + shift;
            out[(size_t)row * HH + c] = val > 0.f ? val : SLOPE * val;
        }
    }
}

// ---------------------------------------------------------------------------
// Kernel 2: node projections, packed output.
//   Pd[row, 0:32] = h @ Wf_dst^T ; Pd[row,32:64] = h @ Ws_dst^T
//   Ps[row, 0:32] = h @ Wf_src^T ; Ps[row,32:64] = h @ Ws_src^T
// Weight rows have stride 96 floats (24 float4).
// Tile: 32 rows per block of 256 threads; thread = (c, rowgroup of 4).
// ---------------------------------------------------------------------------
__global__ __launch_bounds__(256) void proj4_kernel(
    const float4* __restrict__ in4, int M,
    const float4* __restrict__ wfd, const float4* __restrict__ wfs,
    const float4* __restrict__ wsd, const float4* __restrict__ wss,
    float* __restrict__ Pd, float* __restrict__ Ps)
{
    __shared__ float4 wp[4][256];   // [m][k4*32 + c]
    __shared__ float4 xs4[32 * 8];  // 32 rows x 32 k (8 float4)

    const int t = threadIdx.x;
    {
        int k4 = t >> 5, c = t & 31;
        wp[0][t] = wfd[c * 24 + k4];
        wp[1][t] = wsd[c * 24 + k4];
        wp[2][t] = wfs[c * 24 + k4];
        wp[3][t] = wss[c * 24 + k4];
    }
    const int r0 = blockIdx.x * 32;
    {
        int r = t >> 3, q = t & 7;
        int gr = r0 + r;
        xs4[t] = (gr < M) ? in4[(size_t)gr * 8 + q]
                          : make_float4(0.f, 0.f, 0.f, 0.f);
    }
    __syncthreads();

    const int c  = t & 31;
    const int rg = t >> 5;          // rows rg*4 .. rg*4+3

    float acc[4][4];
#pragma unroll
    for (int m = 0; m < 4; m++)
#pragma unroll
        for (int i = 0; i < 4; i++) acc[m][i] = 0.f;

#pragma unroll
    for (int k4 = 0; k4 < 8; k4++) {
        float4 xv[4];
#pragma unroll
        for (int i = 0; i < 4; i++) xv[i] = xs4[(rg * 4 + i) * 8 + k4];
#pragma unroll
        for (int m = 0; m < 4; m++) {
            float4 wv = wp[m][k4 * 32 + c];
#pragma unroll
            for (int i = 0; i < 4; i++) {
                acc[m][i] = fmaf(xv[i].x, wv.x,
                            fmaf(xv[i].y, wv.y,
                            fmaf(xv[i].z, wv.z,
                            fmaf(xv[i].w, wv.w, acc[m][i]))));
            }
        }
    }

#pragma unroll
    for (int i = 0; i < 4; i++) {
        int row = r0 + rg * 4 + i;
        if (row < M) {
            size_t o = (size_t)row * 64 + c;
            Pd[o]      = acc[0][i];   // Af
            Pd[o + 32] = acc[1][i];   // As
            Ps[o]      = acc[2][i];   // Bf
            Ps[o + 32] = acc[3][i];   // Bs
        }
    }
}

// ---------------------------------------------------------------------------
// Kernel 3 (FUSED): per 32-edge tile:
//   Cf,Cs = ea_tile @ {Wf_e, Ws_e}^T  (in-register GEMM, no DRAM round-trip)
//   f = Af[dst]+Bf[src]+Cf+bf ; s = As[dst]+Bs[src]+Cs+bs
//   hnext[dst] += sigmoid(f) * softplus(s)   (atomic)
// Thread = (c, rowgroup of 4 edges). Warp lanes span channels -> coalesced
// gathers (128B line per node) and coalesced atomics.
// ---------------------------------------------------------------------------
__global__ __launch_bounds__(256) void fused_edge_kernel(
    const int* __restrict__ ei,               // [2,E]
    const float4* __restrict__ ea4,           // [E][8]
    const float4* __restrict__ wfe,           // e-part of wf, row stride 24 f4
    const float4* __restrict__ wse,
    const float* __restrict__ bf, const float* __restrict__ bs,
    const float* __restrict__ Pd, const float* __restrict__ Ps,
    float* __restrict__ hnext)
{
    __shared__ float4 wp[2][256];   // [m][k4*32 + c]
    __shared__ float4 xs4[32 * 8];  // 32 edges x 32 k
    __shared__ int    s_src[32], s_dst[32];

    const int t = threadIdx.x;
    const int e0 = blockIdx.x * 32;
    {
        int k4 = t >> 5, c = t & 31;
        wp[0][t] = wfe[c * 24 + k4];
        wp[1][t] = wse[c * 24 + k4];
    }
    {
        int r = t >> 3, q = t & 7;
        xs4[t] = ea4[(size_t)(e0 + r) * 8 + q];
    }
    if (t < 32)       s_src[t]      = ei[e0 + t];
    else if (t < 64)  s_dst[t - 32] = ei[(size_t)EE + e0 + (t - 32)];
    __syncthreads();

    const int c  = t & 31;
    const int rg = t >> 5;          // edges rg*4 .. rg*4+3

    float accf[4], accs[4];
#pragma unroll
    for (int i = 0; i < 4; i++) { accf[i] = 0.f; accs[i] = 0.f; }

#pragma unroll
    for (int k4 = 0; k4 < 8; k4++) {
        float4 xv[4];
#pragma unroll
        for (int i = 0; i < 4; i++) xv[i] = xs4[(rg * 4 + i) * 8 + k4];
        float4 wvf = wp[0][k4 * 32 + c];
        float4 wvs = wp[1][k4 * 32 + c];
#pragma unroll
        for (int i = 0; i < 4; i++) {
            accf[i] = fmaf(xv[i].x, wvf.x,
                      fmaf(xv[i].y, wvf.y,
                      fmaf(xv[i].z, wvf.z,
                      fmaf(xv[i].w, wvf.w, accf[i]))));
            accs[i] = fmaf(xv[i].x, wvs.x,
                      fmaf(xv[i].y, wvs.y,
                      fmaf(xv[i].z, wvs.z,
                      fmaf(xv[i].w, wvs.w, accs[i]))));
        }
    }

    const float bfc = bf[c];
    const float bsc = bs[c];
#pragma unroll
    for (int i = 0; i < 4; i++) {
        int el  = rg * 4 + i;
        int src = s_src[el];
        int dst = s_dst[el];
        size_t od = (size_t)dst * 64 + c;
        size_t os = (size_t)src * 64 + c;
        float f = Pd[od]      + Ps[os]      + accf[i] + bfc;
        float s = Pd[od + 32] + Ps[os + 32] + accs[i] + bsc;
        float sig = 1.f / (1.f + __expf(-f));
        float sp  = fmaxf(s, 0.f) + log1pf(__expf(-fabsf(s)));
        atomicAdd(&hnext[(size_t)dst * HH + c], sig * sp);
    }
}

// ---------------------------------------------------------------------------
// Kernel 4: out[N,128] = lrelu(bn( h[N,32] @ w_out[128,32]^T + b ))
// ---------------------------------------------------------------------------
__global__ __launch_bounds__(256) void out_kernel(
    const float4* __restrict__ h4,
    const float4* __restrict__ w4,            // [128 rows][8 float4]
    const float* __restrict__ b,  const float* __restrict__ g,
    const float* __restrict__ be, const float* __restrict__ mm,
    const float* __restrict__ vv,
    float* __restrict__ out)
{
    __shared__ float4 wp[8 * 128];   // wp[k4*128 + c]
    __shared__ float4 xs4[16 * 8];

    const int t = threadIdx.x;
#pragma unroll
    for (int j = 0; j < 4; j++) {
        int i = t + j * 256;
        int k4 = i >> 7, c = i & 127;
        wp[i] = w4[c * 8 + k4];
    }
    const int r0 = blockIdx.x * 16;
    if (t < 128) {
        int r = t >> 3, q = t & 7;
        int gr = r0 + r;
        xs4[t] = (gr < NN) ? h4[(size_t)gr * 8 + q]
                           : make_float4(0.f, 0.f, 0.f, 0.f);
    }
    __syncthreads();

    const int c  = t & 127;
    const int rg = t >> 7;           // 0..1 -> rows rg*8 .. rg*8+7

    float acc[8];
#pragma unroll
    for (int i = 0; i < 8; i++) acc[i] = 0.f;

#pragma unroll
    for (int k4 = 0; k4 < 8; k4++) {
        float4 wv = wp[k4 * 128 + c];
#pragma unroll
        for (int i = 0; i < 8; i++) {
            float4 xv = xs4[(rg * 8 + i) * 8 + k4];
            acc[i] = fmaf(xv.x, wv.x,
                     fmaf(xv.y, wv.y,
                     fmaf(xv.z, wv.z,
                     fmaf(xv.w, wv.w, acc[i]))));
        }
    }

    const float scale = g[c] * rsqrtf(vv[c] + EPS);
    const float shift = be[c] - mm[c] * scale;
    const float bc    = b[c];
#pragma unroll
    for (int i = 0; i < 8; i++) {
        int row = r0 + rg * 8 + i;
        if (row < NN) {
            float val = (acc[i] + bc) * scale + shift;
            out[(size_t)row * DOUT + c] = val > 0.f ? val : SLOPE * val;
        }
    }
}

// ---------------------------------------------------------------------------
// Launch
// ---------------------------------------------------------------------------
extern "C" void kernel_launch(void* const* d_in, const int* in_sizes, int n_in,
                              void* d_out, int out_size)
{
    const float* x     = (const float*)d_in[0];
    const int*   ei    = (const int*)  d_in[1];
    const float* eattr = (const float*)d_in[2];
    const float* w_in  = (const float*)d_in[3];
    const float* b_in  = (const float*)d_in[4];
    const float* g_in  = (const float*)d_in[5];
    const float* be_in = (const float*)d_in[6];
    const float* m_in  = (const float*)d_in[7];
    const float* v_in  = (const float*)d_in[8];
    const float* w_e   = (const float*)d_in[9];
    const float* b_e   = (const float*)d_in[10];
    const float* g_e   = (const float*)d_in[11];
    const float* be_e  = (const float*)d_in[12];
    const float* m_e   = (const float*)d_in[13];
    const float* v_e   = (const float*)d_in[14];
    const float* wf    = (const float*)d_in[15];   // [2,32,96]
    const float* bf    = (const float*)d_in[16];   // [2,32]
    const float* ws    = (const float*)d_in[17];
    const float* bs    = (const float*)d_in[18];
    const float* w_out = (const float*)d_in[19];   // [128,32]
    const float* b_out = (const float*)d_in[20];
    const float* g_out = (const float*)d_in[21];
    const float* be_out= (const float*)d_in[22];
    const float* m_out = (const float*)d_in[23];
    const float* v_out = (const float*)d_in[24];
    float* out = (float*)d_out;

    float *ea, *hA, *hB, *Pd, *Ps;
    cudaGetSymbolAddress((void**)&ea, g_ea);
    cudaGetSymbolAddress((void**)&hA, g_hA);
    cudaGetSymbolAddress((void**)&hB, g_hB);
    cudaGetSymbolAddress((void**)&Pd, g_Pd);
    cudaGetSymbolAddress((void**)&Ps, g_Ps);

    const size_t NH = (size_t)NN * HH;

    // 1) node embedding  h0 = lrelu(bn(x @ w_in^T + b_in))
    lin128_bn_lrelu_kernel<false><<<(NN + 63) / 64, 256>>>(
        (const float4*)x, NN, (const float4*)w_in,
        b_in, g_in, be_in, m_in, v_in, hA);

    // 2) edge embedding  ea = lrelu(bn(edge_attr @ w_e^T + b_e))  (E % 64 == 0)
    lin128_bn_lrelu_kernel<true><<<EE / 64, 256>>>(
        (const float4*)eattr, EE, (const float4*)w_e,
        b_e, g_e, be_e, m_e, v_e, ea);

    // ---- layer 0 ----
    proj4_kernel<<<(NN + 31) / 32, 256>>>(
        (const float4*)hA, NN,
        (const float4*)(wf),      (const float4*)(wf + 32),
        (const float4*)(ws),      (const float4*)(ws + 32),
        Pd, Ps);
    cudaMemcpyAsync(hB, hA, NH * sizeof(float), cudaMemcpyDeviceToDevice, 0);
    fused_edge_kernel<<<EE / 32, 256>>>(
        ei, (const float4*)ea,
        (const float4*)(wf + 64), (const float4*)(ws + 64),
        bf, bs, Pd, Ps, hB);

    // ---- layer 1 ----
    proj4_kernel<<<(NN + 31) / 32, 256>>>(
        (const float4*)hB, NN,
        (const float4*)(wf + 3072),      (const float4*)(wf + 3072 + 32),
        (const float4*)(ws + 3072),      (const float4*)(ws + 3072 + 32),
        Pd, Ps);
    cudaMemcpyAsync(hA, hB, NH * sizeof(float), cudaMemcpyDeviceToDevice, 0);
    fused_edge_kernel<<<EE / 32, 256>>>(
        ei, (const float4*)ea,
        (const float4*)(wf + 3072 + 64), (const float4*)(ws + 3072 + 64),
        bf + 32, bs + 32, Pd, Ps, hA);

    // 4) output  out = lrelu(bn(h @ w_out^T + b_out))
    out_kernel<<<(NN + 15) / 16, 256>>>(
        (const float4*)hA, (const float4*)w_out,
        b_out, g_out, be_out, m_out, v_out, out);
}

// round 4
// speedup vs baseline: 1.6799x; 1.3522x over previous
#include <cuda_runtime.h>
#include <cuda_bf16.h>
#include <math.h>

#define NN   50000
#define EE   1600000
#define HH   32
#define DOUT 128
#define EPS  1e-5f
#define SLOPE 0.1f

// ---------------------------------------------------------------------------
// Scratch (device globals — no allocations allowed). ~231 MB total.
// ---------------------------------------------------------------------------
static __device__ float g_ea[(size_t)EE * HH];        // edge embeddings [E,32] 205 MB
static __device__ float g_hA[(size_t)NN * HH];        // node features ping
static __device__ float g_hB[(size_t)NN * HH];        // node features pong
static __device__ float g_Pd[(size_t)NN * 64];        // (Af,As) interleaved per node
static __device__ float g_Ps[(size_t)NN * 64];        // (Bf,Bs) interleaved per node

// ---------------------------------------------------------------------------
// tf32 helpers
// ---------------------------------------------------------------------------
__device__ __forceinline__ unsigned f2tf32(float f) {
    unsigned u;
    asm("cvt.rna.tf32.f32 %0, %1;" : "=r"(u) : "f"(f));
    return u;
}
__device__ __forceinline__ void mma_tf32(
    float& d0, float& d1, float& d2, float& d3,
    unsigned a0, unsigned a1, unsigned a2, unsigned a3,
    unsigned b0, unsigned b1)
{
    asm volatile(
        "mma.sync.aligned.m16n8k8.row.col.f32.tf32.tf32.f32 "
        "{%0,%1,%2,%3}, {%4,%5,%6,%7}, {%8,%9}, {%0,%1,%2,%3};\n"
        : "+f"(d0), "+f"(d1), "+f"(d2), "+f"(d3)
        : "r"(a0), "r"(a1), "r"(a2), "r"(a3), "r"(b0), "r"(b1));
}

// ---------------------------------------------------------------------------
// Kernel 1 (tf32 tensor-core): out[M,32] = lrelu(bn( in[M,128] @ w[32,128]^T + b ))
// Block: 256 threads = 8 warps; each warp: 32 rows (2 m-tiles) x 32 ch (4 n-tiles).
// K staged in 4 chunks of 32. smem: A[256][36], W[32][36] (conflict-free frags).
// ---------------------------------------------------------------------------
template <bool FULL>
__global__ __launch_bounds__(256) void embed_tf32_kernel(
    const float4* __restrict__ in4, int M,
    const float* __restrict__ w,                      // [32][128] row-major
    const float* __restrict__ b,  const float* __restrict__ g,
    const float* __restrict__ be, const float* __restrict__ mm,
    const float* __restrict__ vv,
    float* __restrict__ out)
{
    __shared__ unsigned As[256 * 36];   // 36 KB
    __shared__ unsigned Ws[32 * 36];    // 4.5 KB
    __shared__ float s_scale[32], s_shift[32], s_bias[32];

    const int t    = threadIdx.x;
    const int lane = t & 31;
    const int wid  = t >> 5;
    const int gq   = lane >> 2;   // group id 0..7
    const int c4   = lane & 3;    // thread-in-group 0..3
    const int r0   = blockIdx.x * 256;
    const int wr   = wid * 32;    // warp's row base within block

    if (t < 32) {
        float sc = g[t] * rsqrtf(vv[t] + EPS);
        s_scale[t] = sc;
        s_shift[t] = be[t] - mm[t] * sc;
        s_bias[t]  = b[t];
    }

    float d[2][4][4];
#pragma unroll
    for (int mt = 0; mt < 2; mt++)
#pragma unroll
        for (int nt = 0; nt < 4; nt++)
#pragma unroll
            for (int i = 0; i < 4; i++) d[mt][nt][i] = 0.f;

    for (int ck = 0; ck < 4; ck++) {
        __syncthreads();
        // stage W chunk: 32 ch x 32 k
        for (int i = t; i < 1024; i += 256) {
            int ch = i >> 5, k = i & 31;
            Ws[ch * 36 + k] = f2tf32(w[ch * 128 + ck * 32 + k]);
        }
        // stage A chunk: 256 rows x 32 k
#pragma unroll
        for (int j = 0; j < 8; j++) {
            int idx = t + j * 256;
            int r = idx >> 3, q = idx & 7;
            int gr = r0 + r;
            float4 v = (FULL || gr < M) ? in4[(size_t)gr * 32 + ck * 8 + q]
                                        : make_float4(0.f, 0.f, 0.f, 0.f);
            unsigned* p = &As[r * 36 + q * 4];
            p[0] = f2tf32(v.x); p[1] = f2tf32(v.y);
            p[2] = f2tf32(v.z); p[3] = f2tf32(v.w);
        }
        __syncthreads();

#pragma unroll
        for (int k8 = 0; k8 < 4; k8++) {
            const int kk = k8 * 8;
            unsigned b0[4], b1[4];
#pragma unroll
            for (int nt = 0; nt < 4; nt++) {
                int n = nt * 8 + gq;
                b0[nt] = Ws[n * 36 + kk + c4];
                b1[nt] = Ws[n * 36 + kk + c4 + 4];
            }
#pragma unroll
            for (int mt = 0; mt < 2; mt++) {
                int rlo = wr + mt * 16 + gq;
                unsigned a0 = As[rlo * 36 + kk + c4];
                unsigned a1 = As[(rlo + 8) * 36 + kk + c4];
                unsigned a2 = As[rlo * 36 + kk + c4 + 4];
                unsigned a3 = As[(rlo + 8) * 36 + kk + c4 + 4];
#pragma unroll
                for (int nt = 0; nt < 4; nt++)
                    mma_tf32(d[mt][nt][0], d[mt][nt][1], d[mt][nt][2], d[mt][nt][3],
                             a0, a1, a2, a3, b0[nt], b1[nt]);
            }
        }
    }

    // epilogue: bias + BN + lrelu, float2 stores
#pragma unroll
    for (int mt = 0; mt < 2; mt++) {
#pragma unroll
        for (int nt = 0; nt < 4; nt++) {
            int col = nt * 8 + 2 * c4;
            float sc0 = s_scale[col],     sh0 = s_shift[col],     bb0 = s_bias[col];
            float sc1 = s_scale[col + 1], sh1 = s_shift[col + 1], bb1 = s_bias[col + 1];
            int rlo = r0 + wr + mt * 16 + gq;
#pragma unroll
            for (int h = 0; h < 2; h++) {      // h=0 -> d0,d1 ; h=1 -> d2,d3
                int row = rlo + h * 8;
                if (FULL || row < M) {
                    float v0 = (d[mt][nt][2 * h]     + bb0) * sc0 + sh0;
                    float v1 = (d[mt][nt][2 * h + 1] + bb1) * sc1 + sh1;
                    v0 = v0 > 0.f ? v0 : SLOPE * v0;
                    v1 = v1 > 0.f ? v1 : SLOPE * v1;
                    *(float2*)&out[(size_t)row * HH + col] = make_float2(v0, v1);
                }
            }
        }
    }
}

// ---------------------------------------------------------------------------
// Kernel 2: node projections, interleaved packed output.
//   Pd[row*64 + 2c] = (h@Wf_dst^T)[c] ; Pd[..+1] = (h@Ws_dst^T)[c]
//   Ps[row*64 + 2c] = (h@Wf_src^T)[c] ; Ps[..+1] = (h@Ws_src^T)[c]
// Weight rows have stride 96 floats (24 float4).
// ---------------------------------------------------------------------------
__global__ __launch_bounds__(256) void proj4_kernel(
    const float4* __restrict__ in4, int M,
    const float4* __restrict__ wfd, const float4* __restrict__ wfs,
    const float4* __restrict__ wsd, const float4* __restrict__ wss,
    float* __restrict__ Pd, float* __restrict__ Ps)
{
    __shared__ float4 wp[4][256];   // [m][k4*32 + c]
    __shared__ float4 xs4[32 * 8];

    const int t = threadIdx.x;
    {
        int k4 = t >> 5, c = t & 31;
        wp[0][t] = wfd[c * 24 + k4];
        wp[1][t] = wsd[c * 24 + k4];
        wp[2][t] = wfs[c * 24 + k4];
        wp[3][t] = wss[c * 24 + k4];
    }
    const int r0 = blockIdx.x * 32;
    {
        int r = t >> 3, q = t & 7;
        int gr = r0 + r;
        xs4[t] = (gr < M) ? in4[(size_t)gr * 8 + q]
                          : make_float4(0.f, 0.f, 0.f, 0.f);
    }
    __syncthreads();

    const int c  = t & 31;
    const int rg = t >> 5;

    float acc[4][4];
#pragma unroll
    for (int m = 0; m < 4; m++)
#pragma unroll
        for (int i = 0; i < 4; i++) acc[m][i] = 0.f;

#pragma unroll
    for (int k4 = 0; k4 < 8; k4++) {
        float4 xv[4];
#pragma unroll
        for (int i = 0; i < 4; i++) xv[i] = xs4[(rg * 4 + i) * 8 + k4];
#pragma unroll
        for (int m = 0; m < 4; m++) {
            float4 wv = wp[m][k4 * 32 + c];
#pragma unroll
            for (int i = 0; i < 4; i++) {
                acc[m][i] = fmaf(xv[i].x, wv.x,
                            fmaf(xv[i].y, wv.y,
                            fmaf(xv[i].z, wv.z,
                            fmaf(xv[i].w, wv.w, acc[m][i]))));
            }
        }
    }

#pragma unroll
    for (int i = 0; i < 4; i++) {
        int row = r0 + rg * 4 + i;
        if (row < M) {
            size_t o = (size_t)row * 64 + 2 * c;
            *(float2*)&Pd[o] = make_float2(acc[0][i], acc[1][i]);  // (Af, As)
            *(float2*)&Ps[o] = make_float2(acc[2][i], acc[3][i]);  // (Bf, Bs)
        }
    }
}

// ---------------------------------------------------------------------------
// Kernel 3 (FUSED): 64 edges per block, 8 per thread.
//   Cf,Cs = ea_tile @ {Wf_e, Ws_e}^T  (in-register GEMM)
//   f = Af[dst]+Bf[src]+Cf+bf ; s = As[dst]+Bs[src]+Cs+bs
//   hnext[dst] += sigmoid(f)*softplus(s)   (atomic)
// ---------------------------------------------------------------------------
__global__ __launch_bounds__(256) void fused_edge_kernel(
    const int* __restrict__ ei,               // [2,E]
    const float4* __restrict__ ea4,           // [E][8]
    const float4* __restrict__ wfe,           // e-part of wf, row stride 24 f4
    const float4* __restrict__ wse,
    const float* __restrict__ bf, const float* __restrict__ bs,
    const float* __restrict__ Pd, const float* __restrict__ Ps,
    float* __restrict__ hnext)
{
    __shared__ float4 wp[2][256];   // [m][k4*32 + c]
    __shared__ float4 xs4[64 * 8];  // 64 edges x 32 k
    __shared__ int    s_src[64], s_dst[64];

    const int t  = threadIdx.x;
    const int e0 = blockIdx.x * 64;
    {
        int k4 = t >> 5, c = t & 31;
        wp[0][t] = wfe[c * 24 + k4];
        wp[1][t] = wse[c * 24 + k4];
    }
#pragma unroll
    for (int j = 0; j < 2; j++) {
        int idx = t + j * 256;
        int r = idx >> 3, q = idx & 7;
        xs4[idx] = ea4[(size_t)(e0 + r) * 8 + q];
    }
    if (t < 64)        s_src[t]      = ei[e0 + t];
    else if (t < 128)  s_dst[t - 64] = ei[(size_t)EE + e0 + (t - 64)];
    __syncthreads();

    const int c  = t & 31;
    const int rg = t >> 5;          // edges rg*8 .. rg*8+7

    float accf[8], accs[8];
#pragma unroll
    for (int i = 0; i < 8; i++) { accf[i] = 0.f; accs[i] = 0.f; }

#pragma unroll
    for (int k4 = 0; k4 < 8; k4++) {
        float4 wvf = wp[0][k4 * 32 + c];
        float4 wvs = wp[1][k4 * 32 + c];
#pragma unroll
        for (int i = 0; i < 8; i++) {
            float4 xv = xs4[(rg * 8 + i) * 8 + k4];   // broadcast within warp
            accf[i] = fmaf(xv.x, wvf.x,
                      fmaf(xv.y, wvf.y,
                      fmaf(xv.z, wvf.z,
                      fmaf(xv.w, wvf.w, accf[i]))));
            accs[i] = fmaf(xv.x, wvs.x,
                      fmaf(xv.y, wvs.y,
                      fmaf(xv.z, wvs.z,
                      fmaf(xv.w, wvs.w, accs[i]))));
        }
    }

    const float bfc = bf[c];
    const float bsc = bs[c];
#pragma unroll
    for (int i = 0; i < 8; i++) {
        int el  = rg * 8 + i;
        int src = s_src[el];
        int dst = s_dst[el];
        float2 pd = *(const float2*)&Pd[(size_t)dst * 64 + 2 * c];  // (Af, As)
        float2 ps = *(const float2*)&Ps[(size_t)src * 64 + 2 * c];  // (Bf, Bs)
        float f = pd.x + ps.x + accf[i] + bfc;
        float s = pd.y + ps.y + accs[i] + bsc;
        float sig = 1.f / (1.f + __expf(-f));
        float sp  = fmaxf(s, 0.f) + log1pf(__expf(-fabsf(s)));
        atomicAdd(&hnext[(size_t)dst * HH + c], sig * sp);
    }
}

// ---------------------------------------------------------------------------
// Kernel 4: out[N,128] = lrelu(bn( h[N,32] @ w_out[128,32]^T + b ))
// ---------------------------------------------------------------------------
__global__ __launch_bounds__(256) void out_kernel(
    const float4* __restrict__ h4,
    const float4* __restrict__ w4,            // [128 rows][8 float4]
    const float* __restrict__ b,  const float* __restrict__ g,
    const float* __restrict__ be, const float* __restrict__ mm,
    const float* __restrict__ vv,
    float* __restrict__ out)
{
    __shared__ float4 wp[8 * 128];
    __shared__ float4 xs4[16 * 8];

    const int t = threadIdx.x;
#pragma unroll
    for (int j = 0; j < 4; j++) {
        int i = t + j * 256;
        int k4 = i >> 7, c = i & 127;
        wp[i] = w4[c * 8 + k4];
    }
    const int r0 = blockIdx.x * 16;
    if (t < 128) {
        int r = t >> 3, q = t & 7;
        int gr = r0 + r;
        xs4[t] = (gr < NN) ? h4[(size_t)gr * 8 + q]
                           : make_float4(0.f, 0.f, 0.f, 0.f);
    }
    __syncthreads();

    const int c  = t & 127;
    const int rg = t >> 7;

    float acc[8];
#pragma unroll
    for (int i = 0; i < 8; i++) acc[i] = 0.f;

#pragma unroll
    for (int k4 = 0; k4 < 8; k4++) {
        float4 wv = wp[k4 * 128 + c];
#pragma unroll
        for (int i = 0; i < 8; i++) {
            float4 xv = xs4[(rg * 8 + i) * 8 + k4];
            acc[i] = fmaf(xv.x, wv.x,
                     fmaf(xv.y, wv.y,
                     fmaf(xv.z, wv.z,
                     fmaf(xv.w, wv.w, acc[i]))));
        }
    }

    const float scale = g[c] * rsqrtf(vv[c] + EPS);
    const float shift = be[c] - mm[c] * scale;
    const float bc    = b[c];
#pragma unroll
    for (int i = 0; i < 8; i++) {
        int row = r0 + rg * 8 + i;
        if (row < NN) {
            float val = (acc[i] + bc) * scale + shift;
            out[(size_t)row * DOUT + c] = val > 0.f ? val : SLOPE * val;
        }
    }
}

// ---------------------------------------------------------------------------
// Launch
// ---------------------------------------------------------------------------
extern "C" void kernel_launch(void* const* d_in, const int* in_sizes, int n_in,
                              void* d_out, int out_size)
{
    const float* x     = (const float*)d_in[0];
    const int*   ei    = (const int*)  d_in[1];
    const float* eattr = (const float*)d_in[2];
    const float* w_in  = (const float*)d_in[3];
    const float* b_in  = (const float*)d_in[4];
    const float* g_in  = (const float*)d_in[5];
    const float* be_in = (const float*)d_in[6];
    const float* m_in  = (const float*)d_in[7];
    const float* v_in  = (const float*)d_in[8];
    const float* w_e   = (const float*)d_in[9];
    const float* b_e   = (const float*)d_in[10];
    const float* g_e   = (const float*)d_in[11];
    const float* be_e  = (const float*)d_in[12];
    const float* m_e   = (const float*)d_in[13];
    const float* v_e   = (const float*)d_in[14];
    const float* wf    = (const float*)d_in[15];   // [2,32,96]
    const float* bf    = (const float*)d_in[16];   // [2,32]
    const float* ws    = (const float*)d_in[17];
    const float* bs    = (const float*)d_in[18];
    const float* w_out = (const float*)d_in[19];   // [128,32]
    const float* b_out = (const float*)d_in[20];
    const float* g_out = (const float*)d_in[21];
    const float* be_out= (const float*)d_in[22];
    const float* m_out = (const float*)d_in[23];
    const float* v_out = (const float*)d_in[24];
    float* out = (float*)d_out;

    float *ea, *hA, *hB, *Pd, *Ps;
    cudaGetSymbolAddress((void**)&ea, g_ea);
    cudaGetSymbolAddress((void**)&hA, g_hA);
    cudaGetSymbolAddress((void**)&hB, g_hB);
    cudaGetSymbolAddress((void**)&Pd, g_Pd);
    cudaGetSymbolAddress((void**)&Ps, g_Ps);

    const size_t NH = (size_t)NN * HH;

    // 1) node embedding (tf32 tensor cores)
    embed_tf32_kernel<false><<<(NN + 255) / 256, 256>>>(
        (const float4*)x, NN, w_in,
        b_in, g_in, be_in, m_in, v_in, hA);

    // 2) edge embedding (tf32 tensor cores; E % 256 == 0)
    embed_tf32_kernel<true><<<EE / 256, 256>>>(
        (const float4*)eattr, EE, w_e,
        b_e, g_e, be_e, m_e, v_e, ea);

    // ---- layer 0 ----
    proj4_kernel<<<(NN + 31) / 32, 256>>>(
        (const float4*)hA, NN,
        (const float4*)(wf),      (const float4*)(wf + 32),
        (const float4*)(ws),      (const float4*)(ws + 32),
        Pd, Ps);
    cudaMemcpyAsync(hB, hA, NH * sizeof(float), cudaMemcpyDeviceToDevice, 0);
    fused_edge_kernel<<<EE / 64, 256>>>(
        ei, (const float4*)ea,
        (const float4*)(wf + 64), (const float4*)(ws + 64),
        bf, bs, Pd, Ps, hB);

    // ---- layer 1 ----
    proj4_kernel<<<(NN + 31) / 32, 256>>>(
        (const float4*)hB, NN,
        (const float4*)(wf + 3072),      (const float4*)(wf + 3072 + 32),
        (const float4*)(ws + 3072),      (const float4*)(ws + 3072 + 32),
        Pd, Ps);
    cudaMemcpyAsync(hA, hB, NH * sizeof(float), cudaMemcpyDeviceToDevice, 0);
    fused_edge_kernel<<<EE / 64, 256>>>(
        ei, (const float4*)ea,
        (const float4*)(wf + 3072 + 64), (const float4*)(ws + 3072 + 64),
        bf + 32, bs + 32, Pd, Ps, hA);

    // 4) output
    out_kernel<<<(NN + 15) / 16, 256>>>(
        (const float4*)hA, (const float4*)w_out,
        b_out, g_out, be_out, m_out, v_out, out);
}

// round 5
// speedup vs baseline: 2.4713x; 1.4711x over previous
#include <cuda_runtime.h>
#include <cuda_fp16.h>
#include <math.h>

#define NN   50000
#define EE   1600000
#define HH   32
#define DOUT 128
#define EPS  1e-5f
#define SLOPE 0.1f

// ---------------------------------------------------------------------------
// Scratch (device globals). ~142 MB total.
// ---------------------------------------------------------------------------
static __device__ uint4 g_eah[(size_t)EE * 4];        // edge embeddings fp16 [E,32] 102 MB
static __device__ float g_hA[(size_t)NN * HH];        // node features ping
static __device__ float g_hB[(size_t)NN * HH];        // node features pong
static __device__ float g_Pd[(size_t)NN * 64];        // (Af+bf, As+bs) interleaved
static __device__ float g_Ps[(size_t)NN * 64];        // (Bf, Bs) interleaved

// ---------------------------------------------------------------------------
// MMA helpers
// ---------------------------------------------------------------------------
__device__ __forceinline__ unsigned f2tf32(float f) {
    unsigned u;
    asm("cvt.rna.tf32.f32 %0, %1;" : "=r"(u) : "f"(f));
    return u;
}
__device__ __forceinline__ void mma_tf32(
    float& d0, float& d1, float& d2, float& d3,
    unsigned a0, unsigned a1, unsigned a2, unsigned a3,
    unsigned b0, unsigned b1)
{
    asm volatile(
        "mma.sync.aligned.m16n8k8.row.col.f32.tf32.tf32.f32 "
        "{%0,%1,%2,%3}, {%4,%5,%6,%7}, {%8,%9}, {%0,%1,%2,%3};\n"
        : "+f"(d0), "+f"(d1), "+f"(d2), "+f"(d3)
        : "r"(a0), "r"(a1), "r"(a2), "r"(a3), "r"(b0), "r"(b1));
}
__device__ __forceinline__ void mma_f16(
    float* d, unsigned a0, unsigned a1, unsigned a2, unsigned a3,
    unsigned b0, unsigned b1)
{
    asm volatile(
        "mma.sync.aligned.m16n8k16.row.col.f32.f16.f16.f32 "
        "{%0,%1,%2,%3}, {%4,%5,%6,%7}, {%8,%9}, {%0,%1,%2,%3};\n"
        : "+f"(d[0]), "+f"(d[1]), "+f"(d[2]), "+f"(d[3])
        : "r"(a0), "r"(a1), "r"(a2), "r"(a3), "r"(b0), "r"(b1));
}
__device__ __forceinline__ unsigned pack_h2(float lo, float hi) {
    __half2 h = __floats2half2_rn(lo, hi);
    return *(unsigned*)&h;
}

// ---------------------------------------------------------------------------
// Kernel 1 (tf32): out[M,32] = lrelu(bn( in[M,128] @ w[32,128]^T + b ))
// HALF: store fp16 (for edge embeddings), else fp32.
// ---------------------------------------------------------------------------
template <bool FULL, bool HALF>
__global__ __launch_bounds__(256) void embed_tf32_kernel(
    const float4* __restrict__ in4, int M,
    const float* __restrict__ w,                      // [32][128] row-major
    const float* __restrict__ b,  const float* __restrict__ g,
    const float* __restrict__ be, const float* __restrict__ mm,
    const float* __restrict__ vv,
    void* __restrict__ outv)
{
    __shared__ unsigned As[256 * 36];
    __shared__ unsigned Ws[32 * 36];
    __shared__ float s_scale[32], s_shift[32], s_bias[32];

    const int t    = threadIdx.x;
    const int lane = t & 31;
    const int wid  = t >> 5;
    const int gq   = lane >> 2;
    const int c4   = lane & 3;
    const int r0   = blockIdx.x * 256;
    const int wr   = wid * 32;

    if (t < 32) {
        float sc = g[t] * rsqrtf(vv[t] + EPS);
        s_scale[t] = sc;
        s_shift[t] = be[t] - mm[t] * sc;
        s_bias[t]  = b[t];
    }

    float d[2][4][4];
#pragma unroll
    for (int mt = 0; mt < 2; mt++)
#pragma unroll
        for (int nt = 0; nt < 4; nt++)
#pragma unroll
            for (int i = 0; i < 4; i++) d[mt][nt][i] = 0.f;

    for (int ck = 0; ck < 4; ck++) {
        __syncthreads();
        for (int i = t; i < 1024; i += 256) {
            int ch = i >> 5, k = i & 31;
            Ws[ch * 36 + k] = f2tf32(w[ch * 128 + ck * 32 + k]);
        }
#pragma unroll
        for (int j = 0; j < 8; j++) {
            int idx = t + j * 256;
            int r = idx >> 3, q = idx & 7;
            int gr = r0 + r;
            float4 v = (FULL || gr < M) ? in4[(size_t)gr * 32 + ck * 8 + q]
                                        : make_float4(0.f, 0.f, 0.f, 0.f);
            unsigned* p = &As[r * 36 + q * 4];
            p[0] = f2tf32(v.x); p[1] = f2tf32(v.y);
            p[2] = f2tf32(v.z); p[3] = f2tf32(v.w);
        }
        __syncthreads();

#pragma unroll
        for (int k8 = 0; k8 < 4; k8++) {
            const int kk = k8 * 8;
            unsigned b0[4], b1[4];
#pragma unroll
            for (int nt = 0; nt < 4; nt++) {
                int n = nt * 8 + gq;
                b0[nt] = Ws[n * 36 + kk + c4];
                b1[nt] = Ws[n * 36 + kk + c4 + 4];
            }
#pragma unroll
            for (int mt = 0; mt < 2; mt++) {
                int rlo = wr + mt * 16 + gq;
                unsigned a0 = As[rlo * 36 + kk + c4];
                unsigned a1 = As[(rlo + 8) * 36 + kk + c4];
                unsigned a2 = As[rlo * 36 + kk + c4 + 4];
                unsigned a3 = As[(rlo + 8) * 36 + kk + c4 + 4];
#pragma unroll
                for (int nt = 0; nt < 4; nt++)
                    mma_tf32(d[mt][nt][0], d[mt][nt][1], d[mt][nt][2], d[mt][nt][3],
                             a0, a1, a2, a3, b0[nt], b1[nt]);
            }
        }
    }

#pragma unroll
    for (int mt = 0; mt < 2; mt++) {
#pragma unroll
        for (int nt = 0; nt < 4; nt++) {
            int col = nt * 8 + 2 * c4;
            float sc0 = s_scale[col],     sh0 = s_shift[col],     bb0 = s_bias[col];
            float sc1 = s_scale[col + 1], sh1 = s_shift[col + 1], bb1 = s_bias[col + 1];
            int rlo = r0 + wr + mt * 16 + gq;
#pragma unroll
            for (int h = 0; h < 2; h++) {
                int row = rlo + h * 8;
                if (FULL || row < M) {
                    float v0 = (d[mt][nt][2 * h]     + bb0) * sc0 + sh0;
                    float v1 = (d[mt][nt][2 * h + 1] + bb1) * sc1 + sh1;
                    v0 = v0 > 0.f ? v0 : SLOPE * v0;
                    v1 = v1 > 0.f ? v1 : SLOPE * v1;
                    if (HALF) {
                        *((unsigned*)outv + ((size_t)row * HH + col) / 2) = pack_h2(v0, v1);
                    } else {
                        *(float2*)((float*)outv + (size_t)row * HH + col) = make_float2(v0, v1);
                    }
                }
            }
        }
    }
}

// ---------------------------------------------------------------------------
// Kernel 2: node projections, interleaved + dst-side bias folded.
//   Pd[row*64+2c] = (h@Wf_dst^T)[c] + bf[c] ; +1 -> (h@Ws_dst^T)[c] + bs[c]
//   Ps[row*64+2c] = (h@Wf_src^T)[c]         ; +1 -> (h@Ws_src^T)[c]
// ---------------------------------------------------------------------------
__global__ __launch_bounds__(256) void proj4_kernel(
    const float4* __restrict__ in4, int M,
    const float4* __restrict__ wfd, const float4* __restrict__ wfs,
    const float4* __restrict__ wsd, const float4* __restrict__ wss,
    const float* __restrict__ bf, const float* __restrict__ bs,
    float* __restrict__ Pd, float* __restrict__ Ps)
{
    __shared__ float4 wp[4][256];
    __shared__ float4 xs4[32 * 8];

    const int t = threadIdx.x;
    {
        int k4 = t >> 5, c = t & 31;
        wp[0][t] = wfd[c * 24 + k4];
        wp[1][t] = wsd[c * 24 + k4];
        wp[2][t] = wfs[c * 24 + k4];
        wp[3][t] = wss[c * 24 + k4];
    }
    const int r0 = blockIdx.x * 32;
    {
        int r = t >> 3, q = t & 7;
        int gr = r0 + r;
        xs4[t] = (gr < M) ? in4[(size_t)gr * 8 + q]
                          : make_float4(0.f, 0.f, 0.f, 0.f);
    }
    __syncthreads();

    const int c  = t & 31;
    const int rg = t >> 5;

    float acc[4][4];
#pragma unroll
    for (int m = 0; m < 4; m++)
#pragma unroll
        for (int i = 0; i < 4; i++) acc[m][i] = 0.f;

#pragma unroll
    for (int k4 = 0; k4 < 8; k4++) {
        float4 xv[4];
#pragma unroll
        for (int i = 0; i < 4; i++) xv[i] = xs4[(rg * 4 + i) * 8 + k4];
#pragma unroll
        for (int m = 0; m < 4; m++) {
            float4 wv = wp[m][k4 * 32 + c];
#pragma unroll
            for (int i = 0; i < 4; i++) {
                acc[m][i] = fmaf(xv[i].x, wv.x,
                            fmaf(xv[i].y, wv.y,
                            fmaf(xv[i].z, wv.z,
                            fmaf(xv[i].w, wv.w, acc[m][i]))));
            }
        }
    }

    const float bfc = bf[c], bsc = bs[c];
#pragma unroll
    for (int i = 0; i < 4; i++) {
        int row = r0 + rg * 4 + i;
        if (row < M) {
            size_t o = (size_t)row * 64 + 2 * c;
            *(float2*)&Pd[o] = make_float2(acc[0][i] + bfc, acc[1][i] + bsc);
            *(float2*)&Ps[o] = make_float2(acc[2][i], acc[3][i]);
        }
    }
}

// ---------------------------------------------------------------------------
// Kernel 3 (fp16 tensor-core fused edge layer): 128 edges/block, 8 warps.
//   D[128,64] = EA_f16[128,32] @ W2_f16[32,64]  (cols 0-31: Wf_e, 32-63: Ws_e)
//   f = D[:,c] + Pd[dst].f + Ps[src].f ; s = D[:,c+32] + Pd[dst].s + Ps[src].s
//   hnext[dst,c] += sigmoid(f)*softplus(s)
// ---------------------------------------------------------------------------
__global__ __launch_bounds__(256) void fused_edge_mma_kernel(
    const int* __restrict__ ei,               // [2,E]
    const uint4* __restrict__ ea16,           // [E][4] (fp16 [E,32])
    const float* __restrict__ wfe,            // wf + l*3072 + 64 (row stride 96)
    const float* __restrict__ wse,
    const float* __restrict__ Pd, const float* __restrict__ Ps,
    float* __restrict__ hnext)
{
    __shared__ unsigned sA[128 * 20];          // fp16 EA tile, 40-half row stride
    __shared__ unsigned sB0[2][8][32];         // B frags, lane-indexed
    __shared__ unsigned sB1[2][8][32];
    __shared__ int s_src[128], s_dst[128];

    const int t  = threadIdx.x;
    const int e0 = blockIdx.x * 128;

    // stage EA tile (128 rows x 4 uint4)
#pragma unroll
    for (int j = 0; j < 2; j++) {
        int idx = t + j * 256;
        int r = idx >> 2, q = idx & 3;
        uint4 v = ea16[(size_t)(e0 + r) * 4 + q];
        *(uint4*)&sA[r * 20 + q * 4] = v;
    }
    // stage edge indices
    if (t < 128)       s_src[t]       = ei[e0 + t];
    else               s_dst[t - 128] = ei[(size_t)EE + e0 + (t - 128)];
    // stage B fragments (convert fp32 weights -> fp16 pairs)
#pragma unroll
    for (int i = t; i < 512; i += 256) {
        int kc = i >> 8, nt = (i >> 5) & 7, ln = i & 31;
        int gq = ln >> 2, c4 = ln & 3;
        int n  = nt * 8 + gq;
        const float* wrow = (n < 32) ? (wfe + n * 96) : (wse + (n - 32) * 96);
        int k0 = kc * 16 + 2 * c4;
        sB0[kc][nt][ln] = pack_h2(wrow[k0],     wrow[k0 + 1]);
        sB1[kc][nt][ln] = pack_h2(wrow[k0 + 8], wrow[k0 + 9]);
    }
    __syncthreads();

    const int lane = t & 31;
    const int wid  = t >> 5;
    const int gq   = lane >> 2;
    const int c4   = lane & 3;
    const int m0   = wid * 16;      // warp's 16-edge tile

    float d[8][4];
#pragma unroll
    for (int nt = 0; nt < 8; nt++)
#pragma unroll
        for (int i = 0; i < 4; i++) d[nt][i] = 0.f;

#pragma unroll
    for (int kc = 0; kc < 2; kc++) {
        int base = (m0 + gq) * 20 + kc * 8 + c4;
        unsigned a0 = sA[base];
        unsigned a1 = sA[base + 8 * 20];
        unsigned a2 = sA[base + 4];
        unsigned a3 = sA[base + 8 * 20 + 4];
#pragma unroll
        for (int nt = 0; nt < 8; nt++)
            mma_f16(d[nt], a0, a1, a2, a3, sB0[kc][nt][lane], sB1[kc][nt][lane]);
    }

    // epilogue: gather + gate + atomic scatter
#pragma unroll
    for (int h = 0; h < 2; h++) {
        int el  = m0 + gq + h * 8;
        int dst = s_dst[el];
        int src = s_src[el];
        const float4* pd4 = (const float4*)(Pd + (size_t)dst * 64);
        const float4* ps4 = (const float4*)(Ps + (size_t)src * 64);
        float* hp = hnext + (size_t)dst * HH;
#pragma unroll
        for (int nt = 0; nt < 4; nt++) {
            int c0 = nt * 8 + 2 * c4;
            float4 pd = pd4[nt * 4 + c4];   // (Af+bf, As+bs, Af'+bf', As'+bs')
            float4 ps = ps4[nt * 4 + c4];   // (Bf, Bs, Bf', Bs')
            float f0 = d[nt][2 * h]         + pd.x + ps.x;
            float s0 = d[nt + 4][2 * h]     + pd.y + ps.y;
            float f1 = d[nt][2 * h + 1]     + pd.z + ps.z;
            float s1 = d[nt + 4][2 * h + 1] + pd.w + ps.w;
            float sg0 = __fdividef(1.f, 1.f + __expf(-f0));
            float sg1 = __fdividef(1.f, 1.f + __expf(-f1));
            float sp0 = fmaxf(s0, 0.f) + __logf(1.f + __expf(-fabsf(s0)));
            float sp1 = fmaxf(s1, 0.f) + __logf(1.f + __expf(-fabsf(s1)));
            atomicAdd(hp + c0,     sg0 * sp0);
            atomicAdd(hp + c0 + 1, sg1 * sp1);
        }
    }
}

// ---------------------------------------------------------------------------
// Kernel 4: out[N,128] = lrelu(bn( h[N,32] @ w_out[128,32]^T + b ))
// ---------------------------------------------------------------------------
__global__ __launch_bounds__(256) void out_kernel(
    const float4* __restrict__ h4,
    const float4* __restrict__ w4,
    const float* __restrict__ b,  const float* __restrict__ g,
    const float* __restrict__ be, const float* __restrict__ mm,
    const float* __restrict__ vv,
    float* __restrict__ out)
{
    __shared__ float4 wp[8 * 128];
    __shared__ float4 xs4[16 * 8];

    const int t = threadIdx.x;
#pragma unroll
    for (int j = 0; j < 4; j++) {
        int i = t + j * 256;
        int k4 = i >> 7, c = i & 127;
        wp[i] = w4[c * 8 + k4];
    }
    const int r0 = blockIdx.x * 16;
    if (t < 128) {
        int r = t >> 3, q = t & 7;
        int gr = r0 + r;
        xs4[t] = (gr < NN) ? h4[(size_t)gr * 8 + q]
                           : make_float4(0.f, 0.f, 0.f, 0.f);
    }
    __syncthreads();

    const int c  = t & 127;
    const int rg = t >> 7;

    float acc[8];
#pragma unroll
    for (int i = 0; i < 8; i++) acc[i] = 0.f;

#pragma unroll
    for (int k4 = 0; k4 < 8; k4++) {
        float4 wv = wp[k4 * 128 + c];
#pragma unroll
        for (int i = 0; i < 8; i++) {
            float4 xv = xs4[(rg * 8 + i) * 8 + k4];
            acc[i] = fmaf(xv.x, wv.x,
                     fmaf(xv.y, wv.y,
                     fmaf(xv.z, wv.z,
                     fmaf(xv.w, wv.w, acc[i]))));
        }
    }

    const float scale = g[c] * rsqrtf(vv[c] + EPS);
    const float shift = be[c] - mm[c] * scale;
    const float bc    = b[c];
#pragma unroll
    for (int i = 0; i < 8; i++) {
        int row = r0 + rg * 8 + i;
        if (row < NN) {
            float val = (acc[i] + bc) * scale + shift;
            out[(size_t)row * DOUT + c] = val > 0.f ? val : SLOPE * val;
        }
    }
}

// ---------------------------------------------------------------------------
// Launch
// ---------------------------------------------------------------------------
extern "C" void kernel_launch(void* const* d_in, const int* in_sizes, int n_in,
                              void* d_out, int out_size)
{
    const float* x     = (const float*)d_in[0];
    const int*   ei    = (const int*)  d_in[1];
    const float* eattr = (const float*)d_in[2];
    const float* w_in  = (const float*)d_in[3];
    const float* b_in  = (const float*)d_in[4];
    const float* g_in  = (const float*)d_in[5];
    const float* be_in = (const float*)d_in[6];
    const float* m_in  = (const float*)d_in[7];
    const float* v_in  = (const float*)d_in[8];
    const float* w_e   = (const float*)d_in[9];
    const float* b_e   = (const float*)d_in[10];
    const float* g_e   = (const float*)d_in[11];
    const float* be_e  = (const float*)d_in[12];
    const float* m_e   = (const float*)d_in[13];
    const float* v_e   = (const float*)d_in[14];
    const float* wf    = (const float*)d_in[15];   // [2,32,96]
    const float* bf    = (const float*)d_in[16];   // [2,32]
    const float* ws    = (const float*)d_in[17];
    const float* bs    = (const float*)d_in[18];
    const float* w_out = (const float*)d_in[19];   // [128,32]
    const float* b_out = (const float*)d_in[20];
    const float* g_out = (const float*)d_in[21];
    const float* be_out= (const float*)d_in[22];
    const float* m_out = (const float*)d_in[23];
    const float* v_out = (const float*)d_in[24];
    float* out = (float*)d_out;

    uint4* eah; float *hA, *hB, *Pd, *Ps;
    cudaGetSymbolAddress((void**)&eah, g_eah);
    cudaGetSymbolAddress((void**)&hA,  g_hA);
    cudaGetSymbolAddress((void**)&hB,  g_hB);
    cudaGetSymbolAddress((void**)&Pd,  g_Pd);
    cudaGetSymbolAddress((void**)&Ps,  g_Ps);

    const size_t NH = (size_t)NN * HH;

    // 1) node embedding (tf32, fp32 out)
    embed_tf32_kernel<false, false><<<(NN + 255) / 256, 256>>>(
        (const float4*)x, NN, w_in,
        b_in, g_in, be_in, m_in, v_in, hA);

    // 2) edge embedding (tf32, fp16 out; E % 256 == 0)
    embed_tf32_kernel<true, true><<<EE / 256, 256>>>(
        (const float4*)eattr, EE, w_e,
        b_e, g_e, be_e, m_e, v_e, eah);

    // ---- layer 0 ----
    proj4_kernel<<<(NN + 31) / 32, 256>>>(
        (const float4*)hA, NN,
        (const float4*)(wf),      (const float4*)(wf + 32),
        (const float4*)(ws),      (const float4*)(ws + 32),
        bf, bs, Pd, Ps);
    cudaMemcpyAsync(hB, hA, NH * sizeof(float), cudaMemcpyDeviceToDevice, 0);
    fused_edge_mma_kernel<<<EE / 128, 256>>>(
        ei, eah, wf + 64, ws + 64, Pd, Ps, hB);

    // ---- layer 1 ----
    proj4_kernel<<<(NN + 31) / 32, 256>>>(
        (const float4*)hB, NN,
        (const float4*)(wf + 3072),      (const float4*)(wf + 3072 + 32),
        (const float4*)(ws + 3072),      (const float4*)(ws + 3072 + 32),
        bf + 32, bs + 32, Pd, Ps);
    cudaMemcpyAsync(hA, hB, NH * sizeof(float), cudaMemcpyDeviceToDevice, 0);
    fused_edge_mma_kernel<<<EE / 128, 256>>>(
        ei, eah, wf + 3072 + 64, ws + 3072 + 64, Pd, Ps, hA);

    // 4) output
    out_kernel<<<(NN + 15) / 16, 256>>>(
        (const float4*)hA, (const float4*)w_out,
        b_out, g_out, be_out, m_out, v_out, out);
}

// round 8
// speedup vs baseline: 2.7719x; 1.1216x over previous
#include <cuda_runtime.h>
#include <cuda_fp16.h>
#include <stdint.h>
#include <math.h>

#define NN   50000
#define EE   1600000
#define HH   32
#define DOUT 128
#define EPS  1e-5f
#define SLOPE 0.1f

// ---------------------------------------------------------------------------
// Scratch (device globals). ~128 MB total.
// ---------------------------------------------------------------------------
static __device__ uint4    g_eah[(size_t)EE * 4];     // edge embeddings fp16 [E,32]
static __device__ float    g_hA[(size_t)NN * HH];     // node features ping
static __device__ float    g_hB[(size_t)NN * HH];     // node features pong
static __device__ float    g_Pd[(size_t)NN * 64];     // (Af+bf, As+bs) fp32 interleaved
static __device__ unsigned g_Ps[(size_t)NN * 32];     // (Bf, Bs) half2 per channel

// ---------------------------------------------------------------------------
// helpers
// ---------------------------------------------------------------------------
__device__ __forceinline__ unsigned pack_h2(float lo, float hi) {
    __half2 h = __floats2half2_rn(lo, hi);
    return *(unsigned*)&h;
}
__device__ __forceinline__ void mma_f16(
    float* d, unsigned a0, unsigned a1, unsigned a2, unsigned a3,
    unsigned b0, unsigned b1)
{
    asm volatile(
        "mma.sync.aligned.m16n8k16.row.col.f32.f16.f16.f32 "
        "{%0,%1,%2,%3}, {%4,%5,%6,%7}, {%8,%9}, {%0,%1,%2,%3};\n"
        : "+f"(d[0]), "+f"(d[1]), "+f"(d[2]), "+f"(d[3])
        : "r"(a0), "r"(a1), "r"(a2), "r"(a3), "r"(b0), "r"(b1));
}
__device__ __forceinline__ unsigned smem_u32(const void* p) {
    unsigned a;
    asm("{ .reg .u64 t; cvta.to.shared.u64 t, %1; cvt.u32.u64 %0, t; }"
        : "=r"(a) : "l"(p));
    return a;
}

// ---------------------------------------------------------------------------
// Kernel 1 (fp16 MMA streaming): out[M,32] = lrelu(bn( in[M,128] @ w[32,128]^T + b ))
// 128 rows/block, 8 warps (16 rows each). A via ldmatrix, conflict-free
// (row stride 136 halves -> 4-bank shift/row). HALF: fp16 output.
// ---------------------------------------------------------------------------
template <bool FULL, bool HALF>
__global__ __launch_bounds__(256) void embed_f16_kernel(
    const float4* __restrict__ in4, int M,
    const float* __restrict__ w,                      // [32][128] row-major
    const float* __restrict__ b,  const float* __restrict__ g,
    const float* __restrict__ be, const float* __restrict__ mm,
    const float* __restrict__ vv,
    void* __restrict__ outv)
{
    __shared__ unsigned sX[128 * 68];        // fp16 rows, stride 68 uints
    __shared__ unsigned sB0[8][4][32];       // B frags, lane-indexed
    __shared__ unsigned sB1[8][4][32];
    __shared__ float s_scale[32], s_shift[32], s_bias[32];

    const int t    = threadIdx.x;
    const int lane = t & 31;
    const int wid  = t >> 5;
    const int gq   = lane >> 2;
    const int c4   = lane & 3;
    const int r0   = blockIdx.x * 128;
    const int m0   = wid * 16;

    if (t < 32) {
        float sc = g[t] * rsqrtf(vv[t] + EPS);
        s_scale[t] = sc;
        s_shift[t] = be[t] - mm[t] * sc;
        s_bias[t]  = b[t];
    }

    // stage B fragments (fp32 -> fp16)
#pragma unroll
    for (int i = t; i < 1024; i += 256) {
        int kc = i >> 7, nt = (i >> 5) & 3, ln = i & 31;
        int g2 = ln >> 2, c2 = ln & 3;
        const float* wrow = w + (nt * 8 + g2) * 128;
        int k0 = kc * 16 + 2 * c2;
        sB0[kc][nt][ln] = pack_h2(wrow[k0],     wrow[k0 + 1]);
        sB1[kc][nt][ln] = pack_h2(wrow[k0 + 8], wrow[k0 + 9]);
    }
    // stage X (fp32 -> fp16): one row per warp per j, coalesced 512B
#pragma unroll
    for (int j = 0; j < 16; j++) {
        int idx = t + j * 256;
        int r = idx >> 5, q = idx & 31;
        int gr = r0 + r;
        float4 v = (FULL || gr < M) ? in4[(size_t)gr * 32 + q]
                                    : make_float4(0.f, 0.f, 0.f, 0.f);
        sX[r * 68 + q * 2]     = pack_h2(v.x, v.y);
        sX[r * 68 + q * 2 + 1] = pack_h2(v.z, v.w);
    }
    __syncthreads();

    // ldmatrix address (fixed per thread, advance by kc)
    const int mi     = lane >> 3;
    const int rowoff = ((mi & 1) << 3) + (lane & 7);
    const int ku     = (mi >> 1) << 2;     // uint offset: 0 or 4
    unsigned abase = smem_u32(sX) + (unsigned)(((m0 + rowoff) * 68 + ku) * 4);

    float d[4][4];
#pragma unroll
    for (int nt = 0; nt < 4; nt++)
#pragma unroll
        for (int i = 0; i < 4; i++) d[nt][i] = 0.f;

#pragma unroll
    for (int kc = 0; kc < 8; kc++) {
        unsigned a0, a1, a2, a3;
        asm volatile("ldmatrix.sync.aligned.m8n8.x4.shared.b16 {%0,%1,%2,%3}, [%4];"
            : "=r"(a0), "=r"(a1), "=r"(a2), "=r"(a3)
            : "r"(abase + kc * 32));
#pragma unroll
        for (int nt = 0; nt < 4; nt++)
            mma_f16(d[nt], a0, a1, a2, a3, sB0[kc][nt][lane], sB1[kc][nt][lane]);
    }

    // epilogue: bias + BN + lrelu
#pragma unroll
    for (int nt = 0; nt < 4; nt++) {
        int col = nt * 8 + 2 * c4;
        float sc0 = s_scale[col],     sh0 = s_shift[col],     bb0 = s_bias[col];
        float sc1 = s_scale[col + 1], sh1 = s_shift[col + 1], bb1 = s_bias[col + 1];
#pragma unroll
        for (int h = 0; h < 2; h++) {
            int row = r0 + m0 + gq + h * 8;
            if (FULL || row < M) {
                float v0 = (d[nt][2 * h]     + bb0) * sc0 + sh0;
                float v1 = (d[nt][2 * h + 1] + bb1) * sc1 + sh1;
                v0 = v0 > 0.f ? v0 : SLOPE * v0;
                v1 = v1 > 0.f ? v1 : SLOPE * v1;
                if (HALF) {
                    ((unsigned*)outv)[(size_t)row * 16 + (col >> 1)] = pack_h2(v0, v1);
                } else {
                    *(float2*)((float*)outv + (size_t)row * HH + col) = make_float2(v0, v1);
                }
            }
        }
    }
}

// ---------------------------------------------------------------------------
// Kernel 2: node projections.
//   Pd[row*64+2c] = (h@Wf_dst^T)[c]+bf[c] ; +1 -> (h@Ws_dst^T)[c]+bs[c]  (fp32)
//   Ps[row*32+c]  = half2( (h@Wf_src^T)[c], (h@Ws_src^T)[c] )            (fp16)
// ---------------------------------------------------------------------------
__global__ __launch_bounds__(256) void proj4_kernel(
    const float4* __restrict__ in4, int M,
    const float4* __restrict__ wfd, const float4* __restrict__ wfs,
    const float4* __restrict__ wsd, const float4* __restrict__ wss,
    const float* __restrict__ bf, const float* __restrict__ bs,
    float* __restrict__ Pd, unsigned* __restrict__ Ps)
{
    __shared__ float4 wp[4][256];
    __shared__ float4 xs4[32 * 8];

    const int t = threadIdx.x;
    {
        int k4 = t >> 5, c = t & 31;
        wp[0][t] = wfd[c * 24 + k4];
        wp[1][t] = wsd[c * 24 + k4];
        wp[2][t] = wfs[c * 24 + k4];
        wp[3][t] = wss[c * 24 + k4];
    }
    const int r0 = blockIdx.x * 32;
    {
        int r = t >> 3, q = t & 7;
        int gr = r0 + r;
        xs4[t] = (gr < M) ? in4[(size_t)gr * 8 + q]
                          : make_float4(0.f, 0.f, 0.f, 0.f);
    }
    __syncthreads();

    const int c  = t & 31;
    const int rg = t >> 5;

    float acc[4][4];
#pragma unroll
    for (int m = 0; m < 4; m++)
#pragma unroll
        for (int i = 0; i < 4; i++) acc[m][i] = 0.f;

#pragma unroll
    for (int k4 = 0; k4 < 8; k4++) {
        float4 xv[4];
#pragma unroll
        for (int i = 0; i < 4; i++) xv[i] = xs4[(rg * 4 + i) * 8 + k4];
#pragma unroll
        for (int m = 0; m < 4; m++) {
            float4 wv = wp[m][k4 * 32 + c];
#pragma unroll
            for (int i = 0; i < 4; i++) {
                acc[m][i] = fmaf(xv[i].x, wv.x,
                            fmaf(xv[i].y, wv.y,
                            fmaf(xv[i].z, wv.z,
                            fmaf(xv[i].w, wv.w, acc[m][i]))));
            }
        }
    }

    const float bfc = bf[c], bsc = bs[c];
#pragma unroll
    for (int i = 0; i < 4; i++) {
        int row = r0 + rg * 4 + i;
        if (row < M) {
            *(float2*)&Pd[(size_t)row * 64 + 2 * c] =
                make_float2(acc[0][i] + bfc, acc[1][i] + bsc);
            Ps[(size_t)row * 32 + c] = pack_h2(acc[2][i], acc[3][i]);
        }
    }
}

// ---------------------------------------------------------------------------
// Kernel 3 (fp16 tensor-core fused edge layer): 128 edges/block, 8 warps.
//   D[128,64] = EA_f16[128,32] @ [Wf_e|Ws_e][32,64]
//   f = D[:,c] + Pd[dst] + Ps[src] ; s = D[:,c+32] + ...
//   hnext[dst,c] += sigmoid(f)*softplus(s)
// ---------------------------------------------------------------------------
__global__ __launch_bounds__(256) void fused_edge_mma_kernel(
    const int* __restrict__ ei,               // [2,E]
    const uint4* __restrict__ ea16,           // [E][4] (fp16 [E,32])
    const float* __restrict__ wfe,            // wf + l*3072 + 64 (row stride 96)
    const float* __restrict__ wse,
    const float* __restrict__ Pd, const unsigned* __restrict__ Ps,
    float* __restrict__ hnext)
{
    __shared__ unsigned sA[128 * 20];          // fp16 EA tile, 40-half row stride
    __shared__ unsigned sB0[2][8][32];
    __shared__ unsigned sB1[2][8][32];
    __shared__ int s_src[128], s_dst[128];

    const int t  = threadIdx.x;
    const int e0 = blockIdx.x * 128;

#pragma unroll
    for (int j = 0; j < 2; j++) {
        int idx = t + j * 256;
        int r = idx >> 2, q = idx & 3;
        uint4 v = ea16[(size_t)(e0 + r) * 4 + q];
        *(uint4*)&sA[r * 20 + q * 4] = v;
    }
    if (t < 128)       s_src[t]       = ei[e0 + t];
    else               s_dst[t - 128] = ei[(size_t)EE + e0 + (t - 128)];
#pragma unroll
    for (int i = t; i < 512; i += 256) {
        int kc = i >> 8, nt = (i >> 5) & 7, ln = i & 31;
        int g2 = ln >> 2, c2 = ln & 3;
        int n  = nt * 8 + g2;
        const float* wrow = (n < 32) ? (wfe + n * 96) : (wse + (n - 32) * 96);
        int k0 = kc * 16 + 2 * c2;
        sB0[kc][nt][ln] = pack_h2(wrow[k0],     wrow[k0 + 1]);
        sB1[kc][nt][ln] = pack_h2(wrow[k0 + 8], wrow[k0 + 9]);
    }
    __syncthreads();

    const int lane = t & 31;
    const int wid  = t >> 5;
    const int gq   = lane >> 2;
    const int c4   = lane & 3;
    const int m0   = wid * 16;

    float d[8][4];
#pragma unroll
    for (int nt = 0; nt < 8; nt++)
#pragma unroll
        for (int i = 0; i < 4; i++) d[nt][i] = 0.f;

#pragma unroll
    for (int kc = 0; kc < 2; kc++) {
        int base = (m0 + gq) * 20 + kc * 8 + c4;
        unsigned a0 = sA[base];
        unsigned a1 = sA[base + 8 * 20];
        unsigned a2 = sA[base + 4];
        unsigned a3 = sA[base + 8 * 20 + 4];
#pragma unroll
        for (int nt = 0; nt < 8; nt++)
            mma_f16(d[nt], a0, a1, a2, a3, sB0[kc][nt][lane], sB1[kc][nt][lane]);
    }

    // epilogue: gather + gate + atomic scatter
#pragma unroll
    for (int h = 0; h < 2; h++) {
        int el  = m0 + gq + h * 8;
        int dst = s_dst[el];
        int src = s_src[el];
        const float4* pd4 = (const float4*)(Pd + (size_t)dst * 64);
        const uint2*  ps2 = (const uint2*)(Ps + (size_t)src * 32);
        float* hp = hnext + (size_t)dst * HH;
#pragma unroll
        for (int nt = 0; nt < 4; nt++) {
            int c0 = nt * 8 + 2 * c4;
            float4 pd = pd4[nt * 4 + c4];     // (Af+bf, As+bs) for c0, c0+1
            uint2  pv = ps2[nt * 4 + c4];     // half2 (Bf,Bs) for c0, c0+1
            float2 q0 = __half22float2(*(__half2*)&pv.x);
            float2 q1 = __half22float2(*(__half2*)&pv.y);
            float f0 = d[nt][2 * h]         + pd.x + q0.x;
            float s0 = d[nt + 4][2 * h]     + pd.y + q0.y;
            float f1 = d[nt][2 * h + 1]     + pd.z + q1.x;
            float s1 = d[nt + 4][2 * h + 1] + pd.w + q1.y;
            float sg0 = __fdividef(1.f, 1.f + __expf(-f0));
            float sg1 = __fdividef(1.f, 1.f + __expf(-f1));
            float sp0 = fmaxf(s0, 0.f) + __logf(1.f + __expf(-fabsf(s0)));
            float sp1 = fmaxf(s1, 0.f) + __logf(1.f + __expf(-fabsf(s1)));
            atomicAdd(hp + c0,     sg0 * sp0);
            atomicAdd(hp + c0 + 1, sg1 * sp1);
        }
    }
}

// ---------------------------------------------------------------------------
// Kernel 4: out[N,128] = lrelu(bn( h[N,32] @ w_out[128,32]^T + b ))
// ---------------------------------------------------------------------------
__global__ __launch_bounds__(256) void out_kernel(
    const float4* __restrict__ h4,
    const float4* __restrict__ w4,
    const float* __restrict__ b,  const float* __restrict__ g,
    const float* __restrict__ be, const float* __restrict__ mm,
    const float* __restrict__ vv,
    float* __restrict__ out)
{
    __shared__ float4 wp[8 * 128];
    __shared__ float4 xs4[16 * 8];

    const int t = threadIdx.x;
#pragma unroll
    for (int j = 0; j < 4; j++) {
        int i = t + j * 256;
        int k4 = i >> 7, c = i & 127;
        wp[i] = w4[c * 8 + k4];
    }
    const int r0 = blockIdx.x * 16;
    if (t < 128) {
        int r = t >> 3, q = t & 7;
        int gr = r0 + r;
        xs4[t] = (gr < NN) ? h4[(size_t)gr * 8 + q]
                           : make_float4(0.f, 0.f, 0.f, 0.f);
    }
    __syncthreads();

    const int c  = t & 127;
    const int rg = t >> 7;

    float acc[8];
#pragma unroll
    for (int i = 0; i < 8; i++) acc[i] = 0.f;

#pragma unroll
    for (int k4 = 0; k4 < 8; k4++) {
        float4 wv = wp[k4 * 128 + c];
#pragma unroll
        for (int i = 0; i < 8; i++) {
            float4 xv = xs4[(rg * 8 + i) * 8 + k4];
            acc[i] = fmaf(xv.x, wv.x,
                     fmaf(xv.y, wv.y,
                     fmaf(xv.z, wv.z,
                     fmaf(xv.w, wv.w, acc[i]))));
        }
    }

    const float scale = g[c] * rsqrtf(vv[c] + EPS);
    const float shift = be[c] - mm[c] * scale;
    const float bc    = b[c];
#pragma unroll
    for (int i = 0; i < 8; i++) {
        int row = r0 + rg * 8 + i;
        if (row < NN) {
            float val = (acc[i] + bc) * scale + shift;
            out[(size_t)row * DOUT + c] = val > 0.f ? val : SLOPE * val;
        }
    }
}

// ---------------------------------------------------------------------------
// Launch
// ---------------------------------------------------------------------------
extern "C" void kernel_launch(void* const* d_in, const int* in_sizes, int n_in,
                              void* d_out, int out_size)
{
    const float* x     = (const float*)d_in[0];
    const int*   ei    = (const int*)  d_in[1];
    const float* eattr = (const float*)d_in[2];
    const float* w_in  = (const float*)d_in[3];
    const float* b_in  = (const float*)d_in[4];
    const float* g_in  = (const float*)d_in[5];
    const float* be_in = (const float*)d_in[6];
    const float* m_in  = (const float*)d_in[7];
    const float* v_in  = (const float*)d_in[8];
    const float* w_e   = (const float*)d_in[9];
    const float* b_e   = (const float*)d_in[10];
    const float* g_e   = (const float*)d_in[11];
    const float* be_e  = (const float*)d_in[12];
    const float* m_e   = (const float*)d_in[13];
    const float* v_e   = (const float*)d_in[14];
    const float* wf    = (const float*)d_in[15];   // [2,32,96]
    const float* bf    = (const float*)d_in[16];   // [2,32]
    const float* ws    = (const float*)d_in[17];
    const float* bs    = (const float*)d_in[18];
    const float* w_out = (const float*)d_in[19];   // [128,32]
    const float* b_out = (const float*)d_in[20];
    const float* g_out = (const float*)d_in[21];
    const float* be_out= (const float*)d_in[22];
    const float* m_out = (const float*)d_in[23];
    const float* v_out = (const float*)d_in[24];
    float* out = (float*)d_out;

    uint4* eah; float *hA, *hB, *Pd; unsigned* Ps;
    cudaGetSymbolAddress((void**)&eah, g_eah);
    cudaGetSymbolAddress((void**)&hA,  g_hA);
    cudaGetSymbolAddress((void**)&hB,  g_hB);
    cudaGetSymbolAddress((void**)&Pd,  g_Pd);
    cudaGetSymbolAddress((void**)&Ps,  g_Ps);

    const size_t NH = (size_t)NN * HH;

    // 1) node embedding (fp16 MMA, fp32 out)
    embed_f16_kernel<false, false><<<(NN + 127) / 128, 256>>>(
        (const float4*)x, NN, w_in,
        b_in, g_in, be_in, m_in, v_in, hA);

    // 2) edge embedding (fp16 MMA, fp16 out; E % 128 == 0)
    embed_f16_kernel<true, true><<<EE / 128, 256>>>(
        (const float4*)eattr, EE, w_e,
        b_e, g_e, be_e, m_e, v_e, eah);

    // ---- layer 0 ----
    proj4_kernel<<<(NN + 31) / 32, 256>>>(
        (const float4*)hA, NN,
        (const float4*)(wf),      (const float4*)(wf + 32),
        (const float4*)(ws),      (const float4*)(ws + 32),
        bf, bs, Pd, Ps);
    cudaMemcpyAsync(hB, hA, NH * sizeof(float), cudaMemcpyDeviceToDevice, 0);
    fused_edge_mma_kernel<<<EE / 128, 256>>>(
        ei, eah, wf + 64, ws + 64, Pd, Ps, hB);

    // ---- layer 1 ----
    proj4_kernel<<<(NN + 31) / 32, 256>>>(
        (const float4*)hB, NN,
        (const float4*)(wf + 3072),      (const float4*)(wf + 3072 + 32),
        (const float4*)(ws + 3072),      (const float4*)(ws + 3072 + 32),
        bf + 32, bs + 32, Pd, Ps);
    cudaMemcpyAsync(hA, hB, NH * sizeof(float), cudaMemcpyDeviceToDevice, 0);
    fused_edge_mma_kernel<<<EE / 128, 256>>>(
        ei, eah, wf + 3072 + 64, ws + 3072 + 64, Pd, Ps, hA);

    // 4) output
    out_kernel<<<(NN + 15) / 16, 256>>>(
        (const float4*)hA, (const float4*)w_out,
        b_out, g_out, be_out, m_out, v_out, out);
}

// round 10
// speedup vs baseline: 3.0375x; 1.0958x over previous
#include <cuda_runtime.h>
#include <cuda_fp16.h>
#include <stdint.h>
#include <math.h>

#define NN   50000
#define EE   1600000
#define HH   32
#define DOUT 128
#define EPS  1e-5f
#define SLOPE 0.1f

// ---------------------------------------------------------------------------
// Scratch (device globals). ~128 MB total.
// ---------------------------------------------------------------------------
static __device__ uint4    g_eah[(size_t)EE * 4];     // edge embeddings fp16 [E,32]
static __device__ float    g_hA[(size_t)NN * HH];     // node features ping
static __device__ float    g_hB[(size_t)NN * HH];     // node features pong
static __device__ float    g_Pd[(size_t)NN * 64];     // (Af+bf, As+bs) fp32 interleaved
static __device__ unsigned g_Ps[(size_t)NN * 32];     // (Bf, Bs) half2 per channel

// ---------------------------------------------------------------------------
// helpers
// ---------------------------------------------------------------------------
__device__ __forceinline__ unsigned pack_h2(float lo, float hi) {
    __half2 h = __floats2half2_rn(lo, hi);
    return *(unsigned*)&h;
}
__device__ __forceinline__ void mma_f16(
    float* d, unsigned a0, unsigned a1, unsigned a2, unsigned a3,
    unsigned b0, unsigned b1)
{
    asm volatile(
        "mma.sync.aligned.m16n8k16.row.col.f32.f16.f16.f32 "
        "{%0,%1,%2,%3}, {%4,%5,%6,%7}, {%8,%9}, {%0,%1,%2,%3};\n"
        : "+f"(d[0]), "+f"(d[1]), "+f"(d[2]), "+f"(d[3])
        : "r"(a0), "r"(a1), "r"(a2), "r"(a3), "r"(b0), "r"(b1));
}
__device__ __forceinline__ unsigned smem_u32(const void* p) {
    unsigned a;
    asm("{ .reg .u64 t; cvta.to.shared.u64 t, %1; cvt.u32.u64 %0, t; }"
        : "=r"(a) : "l"(p));
    return a;
}

// ---------------------------------------------------------------------------
// Kernel 1 (fp16 MMA streaming): out[M,32] = lrelu(bn( in[M,128] @ w[32,128]^T + b ))
// ---------------------------------------------------------------------------
template <bool FULL, bool HALF>
__global__ __launch_bounds__(256) void embed_f16_kernel(
    const float4* __restrict__ in4, int M,
    const float* __restrict__ w,                      // [32][128] row-major
    const float* __restrict__ b,  const float* __restrict__ g,
    const float* __restrict__ be, const float* __restrict__ mm,
    const float* __restrict__ vv,
    void* __restrict__ outv)
{
    __shared__ unsigned sX[128 * 68];        // fp16 rows, stride 68 uints
    __shared__ unsigned sB0[8][4][32];       // B frags, lane-indexed
    __shared__ unsigned sB1[8][4][32];
    __shared__ float s_scale[32], s_shift[32], s_bias[32];

    const int t    = threadIdx.x;
    const int lane = t & 31;
    const int wid  = t >> 5;
    const int gq   = lane >> 2;
    const int c4   = lane & 3;
    const int r0   = blockIdx.x * 128;
    const int m0   = wid * 16;

    if (t < 32) {
        float sc = g[t] * rsqrtf(vv[t] + EPS);
        s_scale[t] = sc;
        s_shift[t] = be[t] - mm[t] * sc;
        s_bias[t]  = b[t];
    }

    // stage B fragments (fp32 -> fp16)
#pragma unroll
    for (int i = t; i < 1024; i += 256) {
        int kc = i >> 7, nt = (i >> 5) & 3, ln = i & 31;
        int g2 = ln >> 2, c2 = ln & 3;
        const float* wrow = w + (nt * 8 + g2) * 128;
        int k0 = kc * 16 + 2 * c2;
        sB0[kc][nt][ln] = pack_h2(wrow[k0],     wrow[k0 + 1]);
        sB1[kc][nt][ln] = pack_h2(wrow[k0 + 8], wrow[k0 + 9]);
    }
    // stage X (fp32 -> fp16)
#pragma unroll
    for (int j = 0; j < 16; j++) {
        int idx = t + j * 256;
        int r = idx >> 5, q = idx & 31;
        int gr = r0 + r;
        float4 v = (FULL || gr < M) ? in4[(size_t)gr * 32 + q]
                                    : make_float4(0.f, 0.f, 0.f, 0.f);
        sX[r * 68 + q * 2]     = pack_h2(v.x, v.y);
        sX[r * 68 + q * 2 + 1] = pack_h2(v.z, v.w);
    }
    __syncthreads();

    const int mi     = lane >> 3;
    const int rowoff = ((mi & 1) << 3) + (lane & 7);
    const int ku     = (mi >> 1) << 2;
    unsigned abase = smem_u32(sX) + (unsigned)(((m0 + rowoff) * 68 + ku) * 4);

    float d[4][4];
#pragma unroll
    for (int nt = 0; nt < 4; nt++)
#pragma unroll
        for (int i = 0; i < 4; i++) d[nt][i] = 0.f;

#pragma unroll
    for (int kc = 0; kc < 8; kc++) {
        unsigned a0, a1, a2, a3;
        asm volatile("ldmatrix.sync.aligned.m8n8.x4.shared.b16 {%0,%1,%2,%3}, [%4];"
            : "=r"(a0), "=r"(a1), "=r"(a2), "=r"(a3)
            : "r"(abase + kc * 32));
#pragma unroll
        for (int nt = 0; nt < 4; nt++)
            mma_f16(d[nt], a0, a1, a2, a3, sB0[kc][nt][lane], sB1[kc][nt][lane]);
    }

#pragma unroll
    for (int nt = 0; nt < 4; nt++) {
        int col = nt * 8 + 2 * c4;
        float sc0 = s_scale[col],     sh0 = s_shift[col],     bb0 = s_bias[col];
        float sc1 = s_scale[col + 1], sh1 = s_shift[col + 1], bb1 = s_bias[col + 1];
#pragma unroll
        for (int h = 0; h < 2; h++) {
            int row = r0 + m0 + gq + h * 8;
            if (FULL || row < M) {
                float v0 = (d[nt][2 * h]     + bb0) * sc0 + sh0;
                float v1 = (d[nt][2 * h + 1] + bb1) * sc1 + sh1;
                v0 = v0 > 0.f ? v0 : SLOPE * v0;
                v1 = v1 > 0.f ? v1 : SLOPE * v1;
                if (HALF) {
                    ((unsigned*)outv)[(size_t)row * 16 + (col >> 1)] = pack_h2(v0, v1);
                } else {
                    *(float2*)((float*)outv + (size_t)row * HH + col) = make_float2(v0, v1);
                }
            }
        }
    }
}

// ---------------------------------------------------------------------------
// Kernel 2: node projections (unchanged layouts).
// ---------------------------------------------------------------------------
__global__ __launch_bounds__(256) void proj4_kernel(
    const float4* __restrict__ in4, int M,
    const float4* __restrict__ wfd, const float4* __restrict__ wfs,
    const float4* __restrict__ wsd, const float4* __restrict__ wss,
    const float* __restrict__ bf, const float* __restrict__ bs,
    float* __restrict__ Pd, unsigned* __restrict__ Ps)
{
    __shared__ float4 wp[4][256];
    __shared__ float4 xs4[32 * 8];

    const int t = threadIdx.x;
    {
        int k4 = t >> 5, c = t & 31;
        wp[0][t] = wfd[c * 24 + k4];
        wp[1][t] = wsd[c * 24 + k4];
        wp[2][t] = wfs[c * 24 + k4];
        wp[3][t] = wss[c * 24 + k4];
    }
    const int r0 = blockIdx.x * 32;
    {
        int r = t >> 3, q = t & 7;
        int gr = r0 + r;
        xs4[t] = (gr < M) ? in4[(size_t)gr * 8 + q]
                          : make_float4(0.f, 0.f, 0.f, 0.f);
    }
    __syncthreads();

    const int c  = t & 31;
    const int rg = t >> 5;

    float acc[4][4];
#pragma unroll
    for (int m = 0; m < 4; m++)
#pragma unroll
        for (int i = 0; i < 4; i++) acc[m][i] = 0.f;

#pragma unroll
    for (int k4 = 0; k4 < 8; k4++) {
        float4 xv[4];
#pragma unroll
        for (int i = 0; i < 4; i++) xv[i] = xs4[(rg * 4 + i) * 8 + k4];
#pragma unroll
        for (int m = 0; m < 4; m++) {
            float4 wv = wp[m][k4 * 32 + c];
#pragma unroll
            for (int i = 0; i < 4; i++) {
                acc[m][i] = fmaf(xv[i].x, wv.x,
                            fmaf(xv[i].y, wv.y,
                            fmaf(xv[i].z, wv.z,
                            fmaf(xv[i].w, wv.w, acc[m][i]))));
            }
        }
    }

    const float bfc = bf[c], bsc = bs[c];
#pragma unroll
    for (int i = 0; i < 4; i++) {
        int row = r0 + rg * 4 + i;
        if (row < M) {
            *(float2*)&Pd[(size_t)row * 64 + 2 * c] =
                make_float2(acc[0][i] + bfc, acc[1][i] + bsc);
            Ps[(size_t)row * 32 + c] = pack_h2(acc[2][i], acc[3][i]);
        }
    }
}

// ---------------------------------------------------------------------------
// Kernel 3 (fused edge layer, coalesced epilogue + vector reductions):
//   pass 1: D[128,64] = EA_f16 @ [Wf_e|Ws_e]  (MMA, EA tile in union.A)
//   sync, then D staged into union.D (aliases EA tile — dead after MMA)
//   pass 2: 8 lanes/edge, 4 ch/lane: coalesced gathers, gate,
//           red.global.add.v4.f32 into hnext[dst].
// Smem: union 34816 + sB 4096 + idx 1024 = 39936 B (< 48K static limit).
// ---------------------------------------------------------------------------
__global__ __launch_bounds__(256) void fused_edge_mma_kernel(
    const int* __restrict__ ei,               // [2,E]
    const uint4* __restrict__ ea16,           // [E][4] (fp16 [E,32])
    const float* __restrict__ wfe,            // wf + l*3072 + 64 (row stride 96)
    const float* __restrict__ wse,
    const float* __restrict__ Pd, const unsigned* __restrict__ Ps,
    float* __restrict__ hnext)
{
    __shared__ union {
        unsigned A[128 * 20];                  // fp16 EA tile (phase 1)
        float    D[128 * 68];                  // D tile (phase 2)
    } u;
    __shared__ unsigned sB0[2][8][32];
    __shared__ unsigned sB1[2][8][32];
    __shared__ int s_src[128], s_dst[128];

    const int t  = threadIdx.x;
    const int e0 = blockIdx.x * 128;

#pragma unroll
    for (int j = 0; j < 2; j++) {
        int idx = t + j * 256;
        int r = idx >> 2, q = idx & 3;
        uint4 v = ea16[(size_t)(e0 + r) * 4 + q];
        *(uint4*)&u.A[r * 20 + q * 4] = v;
    }
    if (t < 128)       s_src[t]       = ei[e0 + t];
    else               s_dst[t - 128] = ei[(size_t)EE + e0 + (t - 128)];
#pragma unroll
    for (int i = t; i < 512; i += 256) {
        int kc = i >> 8, nt = (i >> 5) & 7, ln = i & 31;
        int g2 = ln >> 2, c2 = ln & 3;
        int n  = nt * 8 + g2;
        const float* wrow = (n < 32) ? (wfe + n * 96) : (wse + (n - 32) * 96);
        int k0 = kc * 16 + 2 * c2;
        sB0[kc][nt][ln] = pack_h2(wrow[k0],     wrow[k0 + 1]);
        sB1[kc][nt][ln] = pack_h2(wrow[k0 + 8], wrow[k0 + 9]);
    }
    __syncthreads();

    const int lane = t & 31;
    const int wid  = t >> 5;
    const int gq   = lane >> 2;
    const int c4   = lane & 3;
    const int m0   = wid * 16;

    float d[8][4];
#pragma unroll
    for (int nt = 0; nt < 8; nt++)
#pragma unroll
        for (int i = 0; i < 4; i++) d[nt][i] = 0.f;

#pragma unroll
    for (int kc = 0; kc < 2; kc++) {
        int base = (m0 + gq) * 20 + kc * 8 + c4;
        unsigned a0 = u.A[base];
        unsigned a1 = u.A[base + 8 * 20];
        unsigned a2 = u.A[base + 4];
        unsigned a3 = u.A[base + 8 * 20 + 4];
#pragma unroll
        for (int nt = 0; nt < 8; nt++)
            mma_f16(d[nt], a0, a1, a2, a3, sB0[kc][nt][lane], sB1[kc][nt][lane]);
    }

    // all warps done reading u.A before overwriting it as u.D
    __syncthreads();

    // stage D to smem (cols 0-31: f, 32-63: s)
    {
        const int row0 = m0 + gq;
#pragma unroll
        for (int nt = 0; nt < 8; nt++) {
            int col = nt * 8 + 2 * c4;
            *(float2*)&u.D[row0 * 68 + col]       = make_float2(d[nt][0], d[nt][1]);
            *(float2*)&u.D[(row0 + 8) * 68 + col] = make_float2(d[nt][2], d[nt][3]);
        }
    }
    __syncthreads();

    // pass 2: edge-coalesced gather + gate + vector reduction
    const int l  = t & 7;            // lane-in-edge: channels 4l..4l+3
    const int eb = t >> 3;           // 0..31
#pragma unroll
    for (int it = 0; it < 4; it++) {
        int e   = eb + it * 32;
        int dst = s_dst[e];
        int src = s_src[e];
        float4 F = *(float4*)&u.D[e * 68 + 4 * l];
        float4 S = *(float4*)&u.D[e * 68 + 32 + 4 * l];
        float4 pd0 = *(const float4*)&Pd[(size_t)dst * 64 + 8 * l];
        float4 pd1 = *(const float4*)&Pd[(size_t)dst * 64 + 8 * l + 4];
        uint4  pv  = *(const uint4*)&Ps[(size_t)src * 32 + 4 * l];
        float2 q0 = __half22float2(*(__half2*)&pv.x);
        float2 q1 = __half22float2(*(__half2*)&pv.y);
        float2 q2 = __half22float2(*(__half2*)&pv.z);
        float2 q3 = __half22float2(*(__half2*)&pv.w);

        float f0 = F.x + pd0.x + q0.x,  s0 = S.x + pd0.y + q0.y;
        float f1 = F.y + pd0.z + q1.x,  s1 = S.y + pd0.w + q1.y;
        float f2 = F.z + pd1.x + q2.x,  s2 = S.z + pd1.y + q2.y;
        float f3 = F.w + pd1.z + q3.x,  s3 = S.w + pd1.w + q3.y;

        float m0_ = __fdividef(1.f, 1.f + __expf(-f0)) *
                    (fmaxf(s0, 0.f) + __logf(1.f + __expf(-fabsf(s0))));
        float m1_ = __fdividef(1.f, 1.f + __expf(-f1)) *
                    (fmaxf(s1, 0.f) + __logf(1.f + __expf(-fabsf(s1))));
        float m2_ = __fdividef(1.f, 1.f + __expf(-f2)) *
                    (fmaxf(s2, 0.f) + __logf(1.f + __expf(-fabsf(s2))));
        float m3_ = __fdividef(1.f, 1.f + __expf(-f3)) *
                    (fmaxf(s3, 0.f) + __logf(1.f + __expf(-fabsf(s3))));

        asm volatile("red.global.add.v4.f32 [%0], {%1,%2,%3,%4};"
            :: "l"(hnext + (size_t)dst * HH + 4 * l),
               "f"(m0_), "f"(m1_), "f"(m2_), "f"(m3_)
            : "memory");
    }
}

// ---------------------------------------------------------------------------
// Kernel 4: out[N,128] = lrelu(bn( h[N,32] @ w_out[128,32]^T + b ))
// ---------------------------------------------------------------------------
__global__ __launch_bounds__(256) void out_kernel(
    const float4* __restrict__ h4,
    const float4* __restrict__ w4,
    const float* __restrict__ b,  const float* __restrict__ g,
    const float* __restrict__ be, const float* __restrict__ mm,
    const float* __restrict__ vv,
    float* __restrict__ out)
{
    __shared__ float4 wp[8 * 128];
    __shared__ float4 xs4[16 * 8];

    const int t = threadIdx.x;
#pragma unroll
    for (int j = 0; j < 4; j++) {
        int i = t + j * 256;
        int k4 = i >> 7, c = i & 127;
        wp[i] = w4[c * 8 + k4];
    }
    const int r0 = blockIdx.x * 16;
    if (t < 128) {
        int r = t >> 3, q = t & 7;
        int gr = r0 + r;
        xs4[t] = (gr < NN) ? h4[(size_t)gr * 8 + q]
                           : make_float4(0.f, 0.f, 0.f, 0.f);
    }
    __syncthreads();

    const int c  = t & 127;
    const int rg = t >> 7;

    float acc[8];
#pragma unroll
    for (int i = 0; i < 8; i++) acc[i] = 0.f;

#pragma unroll
    for (int k4 = 0; k4 < 8; k4++) {
        float4 wv = wp[k4 * 128 + c];
#pragma unroll
        for (int i = 0; i < 8; i++) {
            float4 xv = xs4[(rg * 8 + i) * 8 + k4];
            acc[i] = fmaf(xv.x, wv.x,
                     fmaf(xv.y, wv.y,
                     fmaf(xv.z, wv.z,
                     fmaf(xv.w, wv.w, acc[i]))));
        }
    }

    const float scale = g[c] * rsqrtf(vv[c] + EPS);
    const float shift = be[c] - mm[c] * scale;
    const float bc    = b[c];
#pragma unroll
    for (int i = 0; i < 8; i++) {
        int row = r0 + rg * 8 + i;
        if (row < NN) {
            float val = (acc[i] + bc) * scale + shift;
            out[(size_t)row * DOUT + c] = val > 0.f ? val : SLOPE * val;
        }
    }
}

// ---------------------------------------------------------------------------
// Launch
// ---------------------------------------------------------------------------
extern "C" void kernel_launch(void* const* d_in, const int* in_sizes, int n_in,
                              void* d_out, int out_size)
{
    const float* x     = (const float*)d_in[0];
    const int*   ei    = (const int*)  d_in[1];
    const float* eattr = (const float*)d_in[2];
    const float* w_in  = (const float*)d_in[3];
    const float* b_in  = (const float*)d_in[4];
    const float* g_in  = (const float*)d_in[5];
    const float* be_in = (const float*)d_in[6];
    const float* m_in  = (const float*)d_in[7];
    const float* v_in  = (const float*)d_in[8];
    const float* w_e   = (const float*)d_in[9];
    const float* b_e   = (const float*)d_in[10];
    const float* g_e   = (const float*)d_in[11];
    const float* be_e  = (const float*)d_in[12];
    const float* m_e   = (const float*)d_in[13];
    const float* v_e   = (const float*)d_in[14];
    const float* wf    = (const float*)d_in[15];   // [2,32,96]
    const float* bf    = (const float*)d_in[16];   // [2,32]
    const float* ws    = (const float*)d_in[17];
    const float* bs    = (const float*)d_in[18];
    const float* w_out = (const float*)d_in[19];   // [128,32]
    const float* b_out = (const float*)d_in[20];
    const float* g_out = (const float*)d_in[21];
    const float* be_out= (const float*)d_in[22];
    const float* m_out = (const float*)d_in[23];
    const float* v_out = (const float*)d_in[24];
    float* out = (float*)d_out;

    uint4* eah; float *hA, *hB, *Pd; unsigned* Ps;
    cudaGetSymbolAddress((void**)&eah, g_eah);
    cudaGetSymbolAddress((void**)&hA,  g_hA);
    cudaGetSymbolAddress((void**)&hB,  g_hB);
    cudaGetSymbolAddress((void**)&Pd,  g_Pd);
    cudaGetSymbolAddress((void**)&Ps,  g_Ps);

    const size_t NH = (size_t)NN * HH;

    // 1) node embedding (fp16 MMA, fp32 out)
    embed_f16_kernel<false, false><<<(NN + 127) / 128, 256>>>(
        (const float4*)x, NN, w_in,
        b_in, g_in, be_in, m_in, v_in, hA);

    // 2) edge embedding (fp16 MMA, fp16 out; E % 128 == 0)
    embed_f16_kernel<true, true><<<EE / 128, 256>>>(
        (const float4*)eattr, EE, w_e,
        b_e, g_e, be_e, m_e, v_e, eah);

    // ---- layer 0 ----
    proj4_kernel<<<(NN + 31) / 32, 256>>>(
        (const float4*)hA, NN,
        (const float4*)(wf),      (const float4*)(wf + 32),
        (const float4*)(ws),      (const float4*)(ws + 32),
        bf, bs, Pd, Ps);
    cudaMemcpyAsync(hB, hA, NH * sizeof(float), cudaMemcpyDeviceToDevice, 0);
    fused_edge_mma_kernel<<<EE / 128, 256>>>(
        ei, eah, wf + 64, ws + 64, Pd, Ps, hB);

    // ---- layer 1 ----
    proj4_kernel<<<(NN + 31) / 32, 256>>>(
        (const float4*)hB, NN,
        (const float4*)(wf + 3072),      (const float4*)(wf + 3072 + 32),
        (const float4*)(ws + 3072),      (const float4*)(ws + 3072 + 32),
        bf + 32, bs + 32, Pd, Ps);
    cudaMemcpyAsync(hA, hB, NH * sizeof(float), cudaMemcpyDeviceToDevice, 0);
    fused_edge_mma_kernel<<<EE / 128, 256>>>(
        ei, eah, wf + 3072 + 64, ws + 3072 + 64, Pd, Ps, hA);

    // 4) output
    out_kernel<<<(NN + 15) / 16, 256>>>(
        (const float4*)hA, (const float4*)w_out,
        b_out, g_out, be_out, m_out, v_out, out);
}

// round 11
// speedup vs baseline: 3.1559x; 1.0390x over previous
#include <cuda_runtime.h>
#include <cuda_fp16.h>
#include <stdint.h>
#include <math.h>

#define NN   50000
#define EE   1600000
#define HH   32
#define DOUT 128
#define EPS  1e-5f
#define SLOPE 0.1f

// ---------------------------------------------------------------------------
// Scratch (device globals). ~122 MB total.
// ---------------------------------------------------------------------------
static __device__ uint4    g_eah[(size_t)EE * 4];     // edge embeddings fp16 [E,32]
static __device__ float    g_hA[(size_t)NN * HH];     // node features (in-place residual)
static __device__ float    g_Pd[(size_t)NN * 64];     // [Af+bf | As+bs] fp32, de-interleaved
static __device__ unsigned g_Ps[(size_t)NN * 32];     // (Bf, Bs) half2 per channel

// ---------------------------------------------------------------------------
// helpers
// ---------------------------------------------------------------------------
__device__ __forceinline__ unsigned pack_h2(float lo, float hi) {
    __half2 h = __floats2half2_rn(lo, hi);
    return *(unsigned*)&h;
}
__device__ __forceinline__ void mma_f16(
    float* d, unsigned a0, unsigned a1, unsigned a2, unsigned a3,
    unsigned b0, unsigned b1)
{
    asm volatile(
        "mma.sync.aligned.m16n8k16.row.col.f32.f16.f16.f32 "
        "{%0,%1,%2,%3}, {%4,%5,%6,%7}, {%8,%9}, {%0,%1,%2,%3};\n"
        : "+f"(d[0]), "+f"(d[1]), "+f"(d[2]), "+f"(d[3])
        : "r"(a0), "r"(a1), "r"(a2), "r"(a3), "r"(b0), "r"(b1));
}
__device__ __forceinline__ unsigned smem_u32(const void* p) {
    unsigned a;
    asm("{ .reg .u64 t; cvta.to.shared.u64 t, %1; cvt.u32.u64 %0, t; }"
        : "=r"(a) : "l"(p));
    return a;
}

// ---------------------------------------------------------------------------
// Kernel 1 (fp16 MMA streaming): out[M,32] = lrelu(bn( in[M,128] @ w[32,128]^T + b ))
// ---------------------------------------------------------------------------
template <bool FULL, bool HALF>
__global__ __launch_bounds__(256) void embed_f16_kernel(
    const float4* __restrict__ in4, int M,
    const float* __restrict__ w,                      // [32][128] row-major
    const float* __restrict__ b,  const float* __restrict__ g,
    const float* __restrict__ be, const float* __restrict__ mm,
    const float* __restrict__ vv,
    void* __restrict__ outv)
{
    __shared__ unsigned sX[128 * 68];        // fp16 rows, stride 68 uints
    __shared__ unsigned sB0[8][4][32];       // B frags, lane-indexed
    __shared__ unsigned sB1[8][4][32];
    __shared__ float s_scale[32], s_shift[32], s_bias[32];

    const int t    = threadIdx.x;
    const int lane = t & 31;
    const int wid  = t >> 5;
    const int gq   = lane >> 2;
    const int c4   = lane & 3;
    const int r0   = blockIdx.x * 128;
    const int m0   = wid * 16;

    if (t < 32) {
        float sc = g[t] * rsqrtf(vv[t] + EPS);
        s_scale[t] = sc;
        s_shift[t] = be[t] - mm[t] * sc;
        s_bias[t]  = b[t];
    }

    // stage B fragments (fp32 -> fp16)
#pragma unroll
    for (int i = t; i < 1024; i += 256) {
        int kc = i >> 7, nt = (i >> 5) & 3, ln = i & 31;
        int g2 = ln >> 2, c2 = ln & 3;
        const float* wrow = w + (nt * 8 + g2) * 128;
        int k0 = kc * 16 + 2 * c2;
        sB0[kc][nt][ln] = pack_h2(wrow[k0],     wrow[k0 + 1]);
        sB1[kc][nt][ln] = pack_h2(wrow[k0 + 8], wrow[k0 + 9]);
    }
    // stage X (fp32 -> fp16)
#pragma unroll
    for (int j = 0; j < 16; j++) {
        int idx = t + j * 256;
        int r = idx >> 5, q = idx & 31;
        int gr = r0 + r;
        float4 v = (FULL || gr < M) ? in4[(size_t)gr * 32 + q]
                                    : make_float4(0.f, 0.f, 0.f, 0.f);
        *(uint2*)&sX[r * 68 + q * 2] = make_uint2(pack_h2(v.x, v.y), pack_h2(v.z, v.w));
    }
    __syncthreads();

    const int mi     = lane >> 3;
    const int rowoff = ((mi & 1) << 3) + (lane & 7);
    const int ku     = (mi >> 1) << 2;
    unsigned abase = smem_u32(sX) + (unsigned)(((m0 + rowoff) * 68 + ku) * 4);

    float d[4][4];
#pragma unroll
    for (int nt = 0; nt < 4; nt++)
#pragma unroll
        for (int i = 0; i < 4; i++) d[nt][i] = 0.f;

#pragma unroll
    for (int kc = 0; kc < 8; kc++) {
        unsigned a0, a1, a2, a3;
        asm volatile("ldmatrix.sync.aligned.m8n8.x4.shared.b16 {%0,%1,%2,%3}, [%4];"
            : "=r"(a0), "=r"(a1), "=r"(a2), "=r"(a3)
            : "r"(abase + kc * 32));
#pragma unroll
        for (int nt = 0; nt < 4; nt++)
            mma_f16(d[nt], a0, a1, a2, a3, sB0[kc][nt][lane], sB1[kc][nt][lane]);
    }

#pragma unroll
    for (int nt = 0; nt < 4; nt++) {
        int col = nt * 8 + 2 * c4;
        float sc0 = s_scale[col],     sh0 = s_shift[col],     bb0 = s_bias[col];
        float sc1 = s_scale[col + 1], sh1 = s_shift[col + 1], bb1 = s_bias[col + 1];
#pragma unroll
        for (int h = 0; h < 2; h++) {
            int row = r0 + m0 + gq + h * 8;
            if (FULL || row < M) {
                float v0 = (d[nt][2 * h]     + bb0) * sc0 + sh0;
                float v1 = (d[nt][2 * h + 1] + bb1) * sc1 + sh1;
                v0 = v0 > 0.f ? v0 : SLOPE * v0;
                v1 = v1 > 0.f ? v1 : SLOPE * v1;
                if (HALF) {
                    ((unsigned*)outv)[(size_t)row * 16 + (col >> 1)] = pack_h2(v0, v1);
                } else {
                    *(float2*)((float*)outv + (size_t)row * HH + col) = make_float2(v0, v1);
                }
            }
        }
    }
}

// ---------------------------------------------------------------------------
// Kernel 2: node projections.
//   Pd[row*64 + c]      = (h@Wf_dst^T)[c] + bf[c]   (f block)
//   Pd[row*64 + 32 + c] = (h@Ws_dst^T)[c] + bs[c]   (s block)
//   Ps[row*32 + c]      = half2( (h@Wf_src^T)[c], (h@Ws_src^T)[c] )
// ---------------------------------------------------------------------------
__global__ __launch_bounds__(256) void proj4_kernel(
    const float4* __restrict__ in4, int M,
    const float4* __restrict__ wfd, const float4* __restrict__ wfs,
    const float4* __restrict__ wsd, const float4* __restrict__ wss,
    const float* __restrict__ bf, const float* __restrict__ bs,
    float* __restrict__ Pd, unsigned* __restrict__ Ps)
{
    __shared__ float4 wp[4][256];
    __shared__ float4 xs4[32 * 8];

    const int t = threadIdx.x;
    {
        int k4 = t >> 5, c = t & 31;
        wp[0][t] = wfd[c * 24 + k4];
        wp[1][t] = wsd[c * 24 + k4];
        wp[2][t] = wfs[c * 24 + k4];
        wp[3][t] = wss[c * 24 + k4];
    }
    const int r0 = blockIdx.x * 32;
    {
        int r = t >> 3, q = t & 7;
        int gr = r0 + r;
        xs4[t] = (gr < M) ? in4[(size_t)gr * 8 + q]
                          : make_float4(0.f, 0.f, 0.f, 0.f);
    }
    __syncthreads();

    const int c  = t & 31;
    const int rg = t >> 5;

    float acc[4][4];
#pragma unroll
    for (int m = 0; m < 4; m++)
#pragma unroll
        for (int i = 0; i < 4; i++) acc[m][i] = 0.f;

#pragma unroll
    for (int k4 = 0; k4 < 8; k4++) {
        float4 xv[4];
#pragma unroll
        for (int i = 0; i < 4; i++) xv[i] = xs4[(rg * 4 + i) * 8 + k4];
#pragma unroll
        for (int m = 0; m < 4; m++) {
            float4 wv = wp[m][k4 * 32 + c];
#pragma unroll
            for (int i = 0; i < 4; i++) {
                acc[m][i] = fmaf(xv[i].x, wv.x,
                            fmaf(xv[i].y, wv.y,
                            fmaf(xv[i].z, wv.z,
                            fmaf(xv[i].w, wv.w, acc[m][i]))));
            }
        }
    }

    const float bfc = bf[c], bsc = bs[c];
#pragma unroll
    for (int i = 0; i < 4; i++) {
        int row = r0 + rg * 4 + i;
        if (row < M) {
            Pd[(size_t)row * 64 + c]      = acc[0][i] + bfc;
            Pd[(size_t)row * 64 + 32 + c] = acc[1][i] + bsc;
            Ps[(size_t)row * 32 + c] = pack_h2(acc[2][i], acc[3][i]);
        }
    }
}

// ---------------------------------------------------------------------------
// Kernel 3 (fused edge layer, coalesced epilogue + vector reductions):
//   pass 1: D[128,64] = EA_f16 @ [Wf_e|Ws_e]  (MMA, EA tile in union.A)
//   pass 2: 8 lanes/edge, 4 ch/lane: contiguous gathers, gate,
//           red.global.add.v4.f32 into h[dst] (in-place residual).
// ---------------------------------------------------------------------------
__global__ __launch_bounds__(256) void fused_edge_mma_kernel(
    const int* __restrict__ ei,               // [2,E]
    const uint4* __restrict__ ea16,           // [E][4] (fp16 [E,32])
    const float* __restrict__ wfe,            // wf + l*3072 + 64 (row stride 96)
    const float* __restrict__ wse,
    const float* __restrict__ Pd, const unsigned* __restrict__ Ps,
    float* __restrict__ hinout)
{
    __shared__ union {
        unsigned A[128 * 20];                  // fp16 EA tile (phase 1)
        float    D[128 * 68];                  // D tile (phase 2)
    } u;
    __shared__ unsigned sB0[2][8][32];
    __shared__ unsigned sB1[2][8][32];
    __shared__ int s_src[128], s_dst[128];

    const int t  = threadIdx.x;
    const int e0 = blockIdx.x * 128;

#pragma unroll
    for (int j = 0; j < 2; j++) {
        int idx = t + j * 256;
        int r = idx >> 2, q = idx & 3;
        uint4 v = ea16[(size_t)(e0 + r) * 4 + q];
        *(uint4*)&u.A[r * 20 + q * 4] = v;
    }
    if (t < 128)       s_src[t]       = ei[e0 + t];
    else               s_dst[t - 128] = ei[(size_t)EE + e0 + (t - 128)];
#pragma unroll
    for (int i = t; i < 512; i += 256) {
        int kc = i >> 8, nt = (i >> 5) & 7, ln = i & 31;
        int g2 = ln >> 2, c2 = ln & 3;
        int n  = nt * 8 + g2;
        const float* wrow = (n < 32) ? (wfe + n * 96) : (wse + (n - 32) * 96);
        int k0 = kc * 16 + 2 * c2;
        sB0[kc][nt][ln] = pack_h2(wrow[k0],     wrow[k0 + 1]);
        sB1[kc][nt][ln] = pack_h2(wrow[k0 + 8], wrow[k0 + 9]);
    }
    __syncthreads();

    const int lane = t & 31;
    const int wid  = t >> 5;
    const int gq   = lane >> 2;
    const int c4   = lane & 3;
    const int m0   = wid * 16;

    float d[8][4];
#pragma unroll
    for (int nt = 0; nt < 8; nt++)
#pragma unroll
        for (int i = 0; i < 4; i++) d[nt][i] = 0.f;

#pragma unroll
    for (int kc = 0; kc < 2; kc++) {
        int base = (m0 + gq) * 20 + kc * 8 + c4;
        unsigned a0 = u.A[base];
        unsigned a1 = u.A[base + 8 * 20];
        unsigned a2 = u.A[base + 4];
        unsigned a3 = u.A[base + 8 * 20 + 4];
#pragma unroll
        for (int nt = 0; nt < 8; nt++)
            mma_f16(d[nt], a0, a1, a2, a3, sB0[kc][nt][lane], sB1[kc][nt][lane]);
    }

    // all warps done reading u.A before overwriting it as u.D
    __syncthreads();

    // stage D to smem (cols 0-31: f, 32-63: s)
    {
        const int row0 = m0 + gq;
#pragma unroll
        for (int nt = 0; nt < 8; nt++) {
            int col = nt * 8 + 2 * c4;
            *(float2*)&u.D[row0 * 68 + col]       = make_float2(d[nt][0], d[nt][1]);
            *(float2*)&u.D[(row0 + 8) * 68 + col] = make_float2(d[nt][2], d[nt][3]);
        }
    }
    __syncthreads();

    // pass 2: edge-coalesced gather + gate + vector reduction
    const int l  = t & 7;            // lane-in-edge: channels 4l..4l+3
    const int eb = t >> 3;           // 0..31
#pragma unroll
    for (int it = 0; it < 4; it++) {
        int e   = eb + it * 32;
        int dst = s_dst[e];
        int src = s_src[e];
        float4 F = *(float4*)&u.D[e * 68 + 4 * l];
        float4 S = *(float4*)&u.D[e * 68 + 32 + 4 * l];
        float4 pdf = *(const float4*)&Pd[(size_t)dst * 64 + 4 * l];       // f block
        float4 pds = *(const float4*)&Pd[(size_t)dst * 64 + 32 + 4 * l];  // s block
        uint4  pv  = *(const uint4*)&Ps[(size_t)src * 32 + 4 * l];
        float2 q0 = __half22float2(*(__half2*)&pv.x);
        float2 q1 = __half22float2(*(__half2*)&pv.y);
        float2 q2 = __half22float2(*(__half2*)&pv.z);
        float2 q3 = __half22float2(*(__half2*)&pv.w);

        float f0 = F.x + pdf.x + q0.x,  s0 = S.x + pds.x + q0.y;
        float f1 = F.y + pdf.y + q1.x,  s1 = S.y + pds.y + q1.y;
        float f2 = F.z + pdf.z + q2.x,  s2 = S.z + pds.z + q2.y;
        float f3 = F.w + pdf.w + q3.x,  s3 = S.w + pds.w + q3.y;

        float m0_ = __fdividef(1.f, 1.f + __expf(-f0)) *
                    (fmaxf(s0, 0.f) + __logf(1.f + __expf(-fabsf(s0))));
        float m1_ = __fdividef(1.f, 1.f + __expf(-f1)) *
                    (fmaxf(s1, 0.f) + __logf(1.f + __expf(-fabsf(s1))));
        float m2_ = __fdividef(1.f, 1.f + __expf(-f2)) *
                    (fmaxf(s2, 0.f) + __logf(1.f + __expf(-fabsf(s2))));
        float m3_ = __fdividef(1.f, 1.f + __expf(-f3)) *
                    (fmaxf(s3, 0.f) + __logf(1.f + __expf(-fabsf(s3))));

        asm volatile("red.global.add.v4.f32 [%0], {%1,%2,%3,%4};"
            :: "l"(hinout + (size_t)dst * HH + 4 * l),
               "f"(m0_), "f"(m1_), "f"(m2_), "f"(m3_)
            : "memory");
    }
}

// ---------------------------------------------------------------------------
// Kernel 4: out[N,128] = lrelu(bn( h[N,32] @ w_out[128,32]^T + b ))
// ---------------------------------------------------------------------------
__global__ __launch_bounds__(256) void out_kernel(
    const float4* __restrict__ h4,
    const float4* __restrict__ w4,
    const float* __restrict__ b,  const float* __restrict__ g,
    const float* __restrict__ be, const float* __restrict__ mm,
    const float* __restrict__ vv,
    float* __restrict__ out)
{
    __shared__ float4 wp[8 * 128];
    __shared__ float4 xs4[16 * 8];

    const int t = threadIdx.x;
#pragma unroll
    for (int j = 0; j < 4; j++) {
        int i = t + j * 256;
        int k4 = i >> 7, c = i & 127;
        wp[i] = w4[c * 8 + k4];
    }
    const int r0 = blockIdx.x * 16;
    if (t < 128) {
        int r = t >> 3, q = t & 7;
        int gr = r0 + r;
        xs4[t] = (gr < NN) ? h4[(size_t)gr * 8 + q]
                           : make_float4(0.f, 0.f, 0.f, 0.f);
    }
    __syncthreads();

    const int c  = t & 127;
    const int rg = t >> 7;

    float acc[8];
#pragma unroll
    for (int i = 0; i < 8; i++) acc[i] = 0.f;

#pragma unroll
    for (int k4 = 0; k4 < 8; k4++) {
        float4 wv = wp[k4 * 128 + c];
#pragma unroll
        for (int i = 0; i < 8; i++) {
            float4 xv = xs4[(rg * 8 + i) * 8 + k4];
            acc[i] = fmaf(xv.x, wv.x,
                     fmaf(xv.y, wv.y,
                     fmaf(xv.z, wv.z,
                     fmaf(xv.w, wv.w, acc[i]))));
        }
    }

    const float scale = g[c] * rsqrtf(vv[c] + EPS);
    const float shift = be[c] - mm[c] * scale;
    const float bc    = b[c];
#pragma unroll
    for (int i = 0; i < 8; i++) {
        int row = r0 + rg * 8 + i;
        if (row < NN) {
            float val = (acc[i] + bc) * scale + shift;
            out[(size_t)row * DOUT + c] = val > 0.f ? val : SLOPE * val;
        }
    }
}

// ---------------------------------------------------------------------------
// Launch
// ---------------------------------------------------------------------------
extern "C" void kernel_launch(void* const* d_in, const int* in_sizes, int n_in,
                              void* d_out, int out_size)
{
    const float* x     = (const float*)d_in[0];
    const int*   ei    = (const int*)  d_in[1];
    const float* eattr = (const float*)d_in[2];
    const float* w_in  = (const float*)d_in[3];
    const float* b_in  = (const float*)d_in[4];
    const float* g_in  = (const float*)d_in[5];
    const float* be_in = (const float*)d_in[6];
    const float* m_in  = (const float*)d_in[7];
    const float* v_in  = (const float*)d_in[8];
    const float* w_e   = (const float*)d_in[9];
    const float* b_e   = (const float*)d_in[10];
    const float* g_e   = (const float*)d_in[11];
    const float* be_e  = (const float*)d_in[12];
    const float* m_e   = (const float*)d_in[13];
    const float* v_e   = (const float*)d_in[14];
    const float* wf    = (const float*)d_in[15];   // [2,32,96]
    const float* bf    = (const float*)d_in[16];   // [2,32]
    const float* ws    = (const float*)d_in[17];
    const float* bs    = (const float*)d_in[18];
    const float* w_out = (const float*)d_in[19];   // [128,32]
    const float* b_out = (const float*)d_in[20];
    const float* g_out = (const float*)d_in[21];
    const float* be_out= (const float*)d_in[22];
    const float* m_out = (const float*)d_in[23];
    const float* v_out = (const float*)d_in[24];
    float* out = (float*)d_out;

    uint4* eah; float *hA, *Pd; unsigned* Ps;
    cudaGetSymbolAddress((void**)&eah, g_eah);
    cudaGetSymbolAddress((void**)&hA,  g_hA);
    cudaGetSymbolAddress((void**)&Pd,  g_Pd);
    cudaGetSymbolAddress((void**)&Ps,  g_Ps);

    // 1) node embedding (fp16 MMA, fp32 out) — regenerates hA every call
    embed_f16_kernel<false, false><<<(NN + 127) / 128, 256>>>(
        (const float4*)x, NN, w_in,
        b_in, g_in, be_in, m_in, v_in, hA);

    // 2) edge embedding (fp16 MMA, fp16 out; E % 128 == 0)
    embed_f16_kernel<true, true><<<EE / 128, 256>>>(
        (const float4*)eattr, EE, w_e,
        b_e, g_e, be_e, m_e, v_e, eah);

    // ---- layer 0 (in-place residual: messages accumulate into hA) ----
    proj4_kernel<<<(NN + 31) / 32, 256>>>(
        (const float4*)hA, NN,
        (const float4*)(wf),      (const float4*)(wf + 32),
        (const float4*)(ws),      (const float4*)(ws + 32),
        bf, bs, Pd, Ps);
    fused_edge_mma_kernel<<<EE / 128, 256>>>(
        ei, eah, wf + 64, ws + 64, Pd, Ps, hA);

    // ---- layer 1 ----
    proj4_kernel<<<(NN + 31) / 32, 256>>>(
        (const float4*)hA, NN,
        (const float4*)(wf + 3072),      (const float4*)(wf + 3072 + 32),
        (const float4*)(ws + 3072),      (const float4*)(ws + 3072 + 32),
        bf + 32, bs + 32, Pd, Ps);
    fused_edge_mma_kernel<<<EE / 128, 256>>>(
        ei, eah, wf + 3072 + 64, ws + 3072 + 64, Pd, Ps, hA);

    // 4) output
    out_kernel<<<(NN + 15) / 16, 256>>>(
        (const float4*)hA, (const float4*)w_out,
        b_out, g_out, be_out, m_out, v_out, out);
}

// round 12
// speedup vs baseline: 3.6055x; 1.1425x over previous
#include <cuda_runtime.h>
#include <cuda_fp16.h>
#include <stdint.h>
#include <math.h>

#define NN   50000
#define EE   1600000
#define HH   32
#define DOUT 128
#define EPS  1e-5f
#define SLOPE 0.1f

// ---------------------------------------------------------------------------
// Scratch (device globals). ~122 MB total.
// ---------------------------------------------------------------------------
static __device__ uint4    g_eah[(size_t)EE * 4];     // edge embeddings fp16 [E,32]
static __device__ float    g_hA[(size_t)NN * HH];     // node features (in-place residual)
static __device__ float    g_Pd[(size_t)NN * 64];     // [Af+bf | As+bs] fp32, de-interleaved
static __device__ unsigned g_Ps[(size_t)NN * 32];     // (Bf, Bs) half2 per channel

// ---------------------------------------------------------------------------
// helpers
// ---------------------------------------------------------------------------
__device__ __forceinline__ unsigned pack_h2(float lo, float hi) {
    __half2 h = __floats2half2_rn(lo, hi);
    return *(unsigned*)&h;
}
__device__ __forceinline__ float2 unpack_h2(unsigned u) {
    return __half22float2(*(__half2*)&u);
}
__device__ __forceinline__ void mma_f16(
    float* d, unsigned a0, unsigned a1, unsigned a2, unsigned a3,
    unsigned b0, unsigned b1)
{
    asm volatile(
        "mma.sync.aligned.m16n8k16.row.col.f32.f16.f16.f32 "
        "{%0,%1,%2,%3}, {%4,%5,%6,%7}, {%8,%9}, {%0,%1,%2,%3};\n"
        : "+f"(d[0]), "+f"(d[1]), "+f"(d[2]), "+f"(d[3])
        : "r"(a0), "r"(a1), "r"(a2), "r"(a3), "r"(b0), "r"(b1));
}
__device__ __forceinline__ unsigned smem_u32(const void* p) {
    unsigned a;
    asm("{ .reg .u64 t; cvta.to.shared.u64 t, %1; cvt.u32.u64 %0, t; }"
        : "=r"(a) : "l"(p));
    return a;
}

// ---------------------------------------------------------------------------
// Kernel 1 (fp16 MMA, K-halves pipelined):
//   out[M,32] = lrelu(bn( in[M,128] @ w[32,128]^T + b ))
// Half-1 global loads are issued BEFORE the sync+half-0 compute that hides them.
// ---------------------------------------------------------------------------
template <bool FULL, bool HALF>
__global__ __launch_bounds__(256) void embed_f16_kernel(
    const float4* __restrict__ in4, int M,
    const float* __restrict__ w,                      // [32][128] row-major
    const float* __restrict__ b,  const float* __restrict__ g,
    const float* __restrict__ be, const float* __restrict__ mm,
    const float* __restrict__ vv,
    void* __restrict__ outv)
{
    __shared__ unsigned sX[128 * 68];        // fp16 rows, stride 68 uints
    __shared__ unsigned sB0[8][4][32];       // B frags, lane-indexed
    __shared__ unsigned sB1[8][4][32];
    __shared__ float s_scale[32], s_shift[32], s_bias[32];

    const int t    = threadIdx.x;
    const int lane = t & 31;
    const int wid  = t >> 5;
    const int gq   = lane >> 2;
    const int c4   = lane & 3;
    const int r0   = blockIdx.x * 128;
    const int m0   = wid * 16;

    if (t < 32) {
        float sc = g[t] * rsqrtf(vv[t] + EPS);
        s_scale[t] = sc;
        s_shift[t] = be[t] - mm[t] * sc;
        s_bias[t]  = b[t];
    }

    // stage B fragments (fp32 -> fp16)
#pragma unroll
    for (int i = t; i < 1024; i += 256) {
        int kc = i >> 7, nt = (i >> 5) & 3, ln = i & 31;
        int g2 = ln >> 2, c2 = ln & 3;
        const float* wrow = w + (nt * 8 + g2) * 128;
        int k0 = kc * 16 + 2 * c2;
        sB0[kc][nt][ln] = pack_h2(wrow[k0],     wrow[k0 + 1]);
        sB1[kc][nt][ln] = pack_h2(wrow[k0 + 8], wrow[k0 + 9]);
    }
    // stage X half-0 (k floats 0..63): 2 rows x 256B per warp-instr
#pragma unroll
    for (int j = 0; j < 8; j++) {
        int idx = t + j * 256;
        int r = idx >> 4, q = idx & 15;
        int gr = r0 + r;
        float4 v = (FULL || gr < M) ? in4[(size_t)gr * 32 + q]
                                    : make_float4(0.f, 0.f, 0.f, 0.f);
        *(uint2*)&sX[r * 68 + q * 2] = make_uint2(pack_h2(v.x, v.y), pack_h2(v.z, v.w));
    }

    // issue half-1 loads NOW (consumed after half-0 compute -> latency hidden)
    float4 pre[8];
#pragma unroll
    for (int j = 0; j < 8; j++) {
        int idx = t + j * 256;
        int r = idx >> 4, q = 16 + (idx & 15);
        int gr = r0 + r;
        pre[j] = (FULL || gr < M) ? in4[(size_t)gr * 32 + q]
                                  : make_float4(0.f, 0.f, 0.f, 0.f);
    }
    __syncthreads();

    const int mi     = lane >> 3;
    const int rowoff = ((mi & 1) << 3) + (lane & 7);
    const int ku     = (mi >> 1) << 2;
    unsigned abase = smem_u32(sX) + (unsigned)(((m0 + rowoff) * 68 + ku) * 4);

    float d[4][4];
#pragma unroll
    for (int nt = 0; nt < 4; nt++)
#pragma unroll
        for (int i = 0; i < 4; i++) d[nt][i] = 0.f;

    // compute half-0 (kc 0..3)
#pragma unroll
    for (int kc = 0; kc < 4; kc++) {
        unsigned a0, a1, a2, a3;
        asm volatile("ldmatrix.sync.aligned.m8n8.x4.shared.b16 {%0,%1,%2,%3}, [%4];"
            : "=r"(a0), "=r"(a1), "=r"(a2), "=r"(a3)
            : "r"(abase + kc * 32));
#pragma unroll
        for (int nt = 0; nt < 4; nt++)
            mma_f16(d[nt], a0, a1, a2, a3, sB0[kc][nt][lane], sB1[kc][nt][lane]);
    }

    // store half-1 (disjoint smem region: uints 32..63 of each row)
#pragma unroll
    for (int j = 0; j < 8; j++) {
        int idx = t + j * 256;
        int r = idx >> 4, q = 16 + (idx & 15);
        float4 v = pre[j];
        *(uint2*)&sX[r * 68 + q * 2] = make_uint2(pack_h2(v.x, v.y), pack_h2(v.z, v.w));
    }
    __syncthreads();

    // compute half-1 (kc 4..7)
#pragma unroll
    for (int kc = 4; kc < 8; kc++) {
        unsigned a0, a1, a2, a3;
        asm volatile("ldmatrix.sync.aligned.m8n8.x4.shared.b16 {%0,%1,%2,%3}, [%4];"
            : "=r"(a0), "=r"(a1), "=r"(a2), "=r"(a3)
            : "r"(abase + kc * 32));
#pragma unroll
        for (int nt = 0; nt < 4; nt++)
            mma_f16(d[nt], a0, a1, a2, a3, sB0[kc][nt][lane], sB1[kc][nt][lane]);
    }

    // epilogue: bias + BN + lrelu
#pragma unroll
    for (int nt = 0; nt < 4; nt++) {
        int col = nt * 8 + 2 * c4;
        float sc0 = s_scale[col],     sh0 = s_shift[col],     bb0 = s_bias[col];
        float sc1 = s_scale[col + 1], sh1 = s_shift[col + 1], bb1 = s_bias[col + 1];
#pragma unroll
        for (int h = 0; h < 2; h++) {
            int row = r0 + m0 + gq + h * 8;
            if (FULL || row < M) {
                float v0 = (d[nt][2 * h]     + bb0) * sc0 + sh0;
                float v1 = (d[nt][2 * h + 1] + bb1) * sc1 + sh1;
                v0 = v0 > 0.f ? v0 : SLOPE * v0;
                v1 = v1 > 0.f ? v1 : SLOPE * v1;
                if (HALF) {
                    ((unsigned*)outv)[(size_t)row * 16 + (col >> 1)] = pack_h2(v0, v1);
                } else {
                    *(float2*)((float*)outv + (size_t)row * HH + col) = make_float2(v0, v1);
                }
            }
        }
    }
}

// ---------------------------------------------------------------------------
// Kernel 2: node projections (de-interleaved Pd, half2 Ps).
// ---------------------------------------------------------------------------
__global__ __launch_bounds__(256) void proj4_kernel(
    const float4* __restrict__ in4, int M,
    const float4* __restrict__ wfd, const float4* __restrict__ wfs,
    const float4* __restrict__ wsd, const float4* __restrict__ wss,
    const float* __restrict__ bf, const float* __restrict__ bs,
    float* __restrict__ Pd, unsigned* __restrict__ Ps)
{
    __shared__ float4 wp[4][256];
    __shared__ float4 xs4[32 * 8];

    const int t = threadIdx.x;
    {
        int k4 = t >> 5, c = t & 31;
        wp[0][t] = wfd[c * 24 + k4];
        wp[1][t] = wsd[c * 24 + k4];
        wp[2][t] = wfs[c * 24 + k4];
        wp[3][t] = wss[c * 24 + k4];
    }
    const int r0 = blockIdx.x * 32;
    {
        int r = t >> 3, q = t & 7;
        int gr = r0 + r;
        xs4[t] = (gr < M) ? in4[(size_t)gr * 8 + q]
                          : make_float4(0.f, 0.f, 0.f, 0.f);
    }
    __syncthreads();

    const int c  = t & 31;
    const int rg = t >> 5;

    float acc[4][4];
#pragma unroll
    for (int m = 0; m < 4; m++)
#pragma unroll
        for (int i = 0; i < 4; i++) acc[m][i] = 0.f;

#pragma unroll
    for (int k4 = 0; k4 < 8; k4++) {
        float4 xv[4];
#pragma unroll
        for (int i = 0; i < 4; i++) xv[i] = xs4[(rg * 4 + i) * 8 + k4];
#pragma unroll
        for (int m = 0; m < 4; m++) {
            float4 wv = wp[m][k4 * 32 + c];
#pragma unroll
            for (int i = 0; i < 4; i++) {
                acc[m][i] = fmaf(xv[i].x, wv.x,
                            fmaf(xv[i].y, wv.y,
                            fmaf(xv[i].z, wv.z,
                            fmaf(xv[i].w, wv.w, acc[m][i]))));
            }
        }
    }

    const float bfc = bf[c], bsc = bs[c];
#pragma unroll
    for (int i = 0; i < 4; i++) {
        int row = r0 + rg * 4 + i;
        if (row < M) {
            Pd[(size_t)row * 64 + c]      = acc[0][i] + bfc;
            Pd[(size_t)row * 64 + 32 + c] = acc[1][i] + bsc;
            Ps[(size_t)row * 32 + c] = pack_h2(acc[2][i], acc[3][i]);
        }
    }
}

// ---------------------------------------------------------------------------
// Kernel 3 (fused edge layer): MMA -> fp16 D in smem -> coalesced epilogue.
// Smem: union 18432 + sB 4096 + idx 1024 = 23.5 KB.
// ---------------------------------------------------------------------------
__global__ __launch_bounds__(256) void fused_edge_mma_kernel(
    const int* __restrict__ ei,               // [2,E]
    const uint4* __restrict__ ea16,           // [E][4] (fp16 [E,32])
    const float* __restrict__ wfe,            // wf + l*3072 + 64 (row stride 96)
    const float* __restrict__ wse,
    const float* __restrict__ Pd, const unsigned* __restrict__ Ps,
    float* __restrict__ hinout)
{
    __shared__ union {
        unsigned A[128 * 20];                  // fp16 EA tile (phase 1)
        unsigned Dh[128 * 36];                 // fp16 D tile (phase 2), stride 36 uints
    } u;
    __shared__ unsigned sB0[2][8][32];
    __shared__ unsigned sB1[2][8][32];
    __shared__ int s_src[128], s_dst[128];

    const int t  = threadIdx.x;
    const int e0 = blockIdx.x * 128;

#pragma unroll
    for (int j = 0; j < 2; j++) {
        int idx = t + j * 256;
        int r = idx >> 2, q = idx & 3;
        uint4 v = ea16[(size_t)(e0 + r) * 4 + q];
        *(uint4*)&u.A[r * 20 + q * 4] = v;
    }
    if (t < 128)       s_src[t]       = ei[e0 + t];
    else               s_dst[t - 128] = ei[(size_t)EE + e0 + (t - 128)];
#pragma unroll
    for (int i = t; i < 512; i += 256) {
        int kc = i >> 8, nt = (i >> 5) & 7, ln = i & 31;
        int g2 = ln >> 2, c2 = ln & 3;
        int n  = nt * 8 + g2;
        const float* wrow = (n < 32) ? (wfe + n * 96) : (wse + (n - 32) * 96);
        int k0 = kc * 16 + 2 * c2;
        sB0[kc][nt][ln] = pack_h2(wrow[k0],     wrow[k0 + 1]);
        sB1[kc][nt][ln] = pack_h2(wrow[k0 + 8], wrow[k0 + 9]);
    }
    __syncthreads();

    const int lane = t & 31;
    const int wid  = t >> 5;
    const int gq   = lane >> 2;
    const int c4   = lane & 3;
    const int m0   = wid * 16;

    float d[8][4];
#pragma unroll
    for (int nt = 0; nt < 8; nt++)
#pragma unroll
        for (int i = 0; i < 4; i++) d[nt][i] = 0.f;

#pragma unroll
    for (int kc = 0; kc < 2; kc++) {
        // preload B frags for this kc into registers
        unsigned rb0[8], rb1[8];
#pragma unroll
        for (int nt = 0; nt < 8; nt++) {
            rb0[nt] = sB0[kc][nt][lane];
            rb1[nt] = sB1[kc][nt][lane];
        }
        int base = (m0 + gq) * 20 + kc * 8 + c4;
        unsigned a0 = u.A[base];
        unsigned a1 = u.A[base + 8 * 20];
        unsigned a2 = u.A[base + 4];
        unsigned a3 = u.A[base + 8 * 20 + 4];
#pragma unroll
        for (int nt = 0; nt < 8; nt++)
            mma_f16(d[nt], a0, a1, a2, a3, rb0[nt], rb1[nt]);
    }

    // all warps done reading u.A before overwriting it as u.Dh
    __syncthreads();

    // stage D as fp16 (halves: cols 0-31 = f -> uints 0-15, cols 32-63 = s -> uints 16-31)
    {
        const int row0 = m0 + gq;
#pragma unroll
        for (int nt = 0; nt < 8; nt++) {
            int cu = nt * 4 + c4;
            u.Dh[row0 * 36 + cu]       = pack_h2(d[nt][0], d[nt][1]);
            u.Dh[(row0 + 8) * 36 + cu] = pack_h2(d[nt][2], d[nt][3]);
        }
    }
    __syncthreads();

    // pass 2: edge-coalesced gather + gate + vector reduction
    const int l  = t & 7;            // lane-in-edge: channels 4l..4l+3
    const int eb = t >> 3;           // 0..31
#pragma unroll
    for (int it = 0; it < 4; it++) {
        int e   = eb + it * 32;
        int dst = s_dst[e];
        int src = s_src[e];
        uint2 Fu = *(uint2*)&u.Dh[e * 36 + 2 * l];
        uint2 Su = *(uint2*)&u.Dh[e * 36 + 16 + 2 * l];
        float2 Fa = unpack_h2(Fu.x), Fb = unpack_h2(Fu.y);
        float2 Sa = unpack_h2(Su.x), Sb = unpack_h2(Su.y);
        float4 pdf = *(const float4*)&Pd[(size_t)dst * 64 + 4 * l];       // f block
        float4 pds = *(const float4*)&Pd[(size_t)dst * 64 + 32 + 4 * l];  // s block
        uint4  pv  = *(const uint4*)&Ps[(size_t)src * 32 + 4 * l];
        float2 q0 = unpack_h2(pv.x);
        float2 q1 = unpack_h2(pv.y);
        float2 q2 = unpack_h2(pv.z);
        float2 q3 = unpack_h2(pv.w);

        float f0 = Fa.x + pdf.x + q0.x,  s0 = Sa.x + pds.x + q0.y;
        float f1 = Fa.y + pdf.y + q1.x,  s1 = Sa.y + pds.y + q1.y;
        float f2 = Fb.x + pdf.z + q2.x,  s2 = Sb.x + pds.z + q2.y;
        float f3 = Fb.y + pdf.w + q3.x,  s3 = Sb.y + pds.w + q3.y;

        float m0_ = __fdividef(1.f, 1.f + __expf(-f0)) *
                    (fmaxf(s0, 0.f) + __logf(1.f + __expf(-fabsf(s0))));
        float m1_ = __fdividef(1.f, 1.f + __expf(-f1)) *
                    (fmaxf(s1, 0.f) + __logf(1.f + __expf(-fabsf(s1))));
        float m2_ = __fdividef(1.f, 1.f + __expf(-f2)) *
                    (fmaxf(s2, 0.f) + __logf(1.f + __expf(-fabsf(s2))));
        float m3_ = __fdividef(1.f, 1.f + __expf(-f3)) *
                    (fmaxf(s3, 0.f) + __logf(1.f + __expf(-fabsf(s3))));

        asm volatile("red.global.add.v4.f32 [%0], {%1,%2,%3,%4};"
            :: "l"(hinout + (size_t)dst * HH + 4 * l),
               "f"(m0_), "f"(m1_), "f"(m2_), "f"(m3_)
            : "memory");
    }
}

// ---------------------------------------------------------------------------
// Kernel 4: out[N,128] = lrelu(bn( h[N,32] @ w_out[128,32]^T + b ))
// ---------------------------------------------------------------------------
__global__ __launch_bounds__(256) void out_kernel(
    const float4* __restrict__ h4,
    const float4* __restrict__ w4,
    const float* __restrict__ b,  const float* __restrict__ g,
    const float* __restrict__ be, const float* __restrict__ mm,
    const float* __restrict__ vv,
    float* __restrict__ out)
{
    __shared__ float4 wp[8 * 128];
    __shared__ float4 xs4[16 * 8];

    const int t = threadIdx.x;
#pragma unroll
    for (int j = 0; j < 4; j++) {
        int i = t + j * 256;
        int k4 = i >> 7, c = i & 127;
        wp[i] = w4[c * 8 + k4];
    }
    const int r0 = blockIdx.x * 16;
    if (t < 128) {
        int r = t >> 3, q = t & 7;
        int gr = r0 + r;
        xs4[t] = (gr < NN) ? h4[(size_t)gr * 8 + q]
                           : make_float4(0.f, 0.f, 0.f, 0.f);
    }
    __syncthreads();

    const int c  = t & 127;
    const int rg = t >> 7;

    float acc[8];
#pragma unroll
    for (int i = 0; i < 8; i++) acc[i] = 0.f;

#pragma unroll
    for (int k4 = 0; k4 < 8; k4++) {
        float4 wv = wp[k4 * 128 + c];
#pragma unroll
        for (int i = 0; i < 8; i++) {
            float4 xv = xs4[(rg * 8 + i) * 8 + k4];
            acc[i] = fmaf(xv.x, wv.x,
                     fmaf(xv.y, wv.y,
                     fmaf(xv.z, wv.z,
                     fmaf(xv.w, wv.w, acc[i]))));
        }
    }

    const float scale = g[c] * rsqrtf(vv[c] + EPS);
    const float shift = be[c] - mm[c] * scale;
    const float bc    = b[c];
#pragma unroll
    for (int i = 0; i < 8; i++) {
        int row = r0 + rg * 8 + i;
        if (row < NN) {
            float val = (acc[i] + bc) * scale + shift;
            out[(size_t)row * DOUT + c] = val > 0.f ? val : SLOPE * val;
        }
    }
}

// ---------------------------------------------------------------------------
// Launch. Node embed split into 4 sub-launches so that launch index 5
// (ncu -s 5 -c 1) lands on the EDGE EMBED kernel for profiling.
// Order: node_a(0) node_b(1) node_c(2) node_d(3) proj4_0(4) edge(5) fused0(6)
//        proj4_1(7) fused1(8) out(9)
// ---------------------------------------------------------------------------
extern "C" void kernel_launch(void* const* d_in, const int* in_sizes, int n_in,
                              void* d_out, int out_size)
{
    const float* x     = (const float*)d_in[0];
    const int*   ei    = (const int*)  d_in[1];
    const float* eattr = (const float*)d_in[2];
    const float* w_in  = (const float*)d_in[3];
    const float* b_in  = (const float*)d_in[4];
    const float* g_in  = (const float*)d_in[5];
    const float* be_in = (const float*)d_in[6];
    const float* m_in  = (const float*)d_in[7];
    const float* v_in  = (const float*)d_in[8];
    const float* w_e   = (const float*)d_in[9];
    const float* b_e   = (const float*)d_in[10];
    const float* g_e   = (const float*)d_in[11];
    const float* be_e  = (const float*)d_in[12];
    const float* m_e   = (const float*)d_in[13];
    const float* v_e   = (const float*)d_in[14];
    const float* wf    = (const float*)d_in[15];   // [2,32,96]
    const float* bf    = (const float*)d_in[16];   // [2,32]
    const float* ws    = (const float*)d_in[17];
    const float* bs    = (const float*)d_in[18];
    const float* w_out = (const float*)d_in[19];   // [128,32]
    const float* b_out = (const float*)d_in[20];
    const float* g_out = (const float*)d_in[21];
    const float* be_out= (const float*)d_in[22];
    const float* m_out = (const float*)d_in[23];
    const float* v_out = (const float*)d_in[24];
    float* out = (float*)d_out;

    uint4* eah; float *hA, *Pd; unsigned* Ps;
    cudaGetSymbolAddress((void**)&eah, g_eah);
    cudaGetSymbolAddress((void**)&hA,  g_hA);
    cudaGetSymbolAddress((void**)&Pd,  g_Pd);
    cudaGetSymbolAddress((void**)&Ps,  g_Ps);

    // 1) node embedding, split into 4 row-range sub-launches (profiling index shim)
    {
        const int offs[5] = {0, 12544, 25088, 37632, NN};  // multiples of 128
        for (int p = 0; p < 4; p++) {
            int off = offs[p], cnt = offs[p + 1] - off;
            embed_f16_kernel<false, false><<<(cnt + 127) / 128, 256>>>(
                (const float4*)(x + (size_t)off * 128), cnt, w_in,
                b_in, g_in, be_in, m_in, v_in, hA + (size_t)off * HH);
        }
    }

    // layer-0 node projections (launch 4)
    proj4_kernel<<<(NN + 31) / 32, 256>>>(
        (const float4*)hA, NN,
        (const float4*)(wf),      (const float4*)(wf + 32),
        (const float4*)(ws),      (const float4*)(ws + 32),
        bf, bs, Pd, Ps);

    // 2) edge embedding (launch 5 — profiled by ncu -s 5 -c 1)
    embed_f16_kernel<true, true><<<EE / 128, 256>>>(
        (const float4*)eattr, EE, w_e,
        b_e, g_e, be_e, m_e, v_e, eah);

    // ---- layer 0 (in-place residual) ----
    fused_edge_mma_kernel<<<EE / 128, 256>>>(
        ei, eah, wf + 64, ws + 64, Pd, Ps, hA);

    // ---- layer 1 ----
    proj4_kernel<<<(NN + 31) / 32, 256>>>(
        (const float4*)hA, NN,
        (const float4*)(wf + 3072),      (const float4*)(wf + 3072 + 32),
        (const float4*)(ws + 3072),      (const float4*)(ws + 3072 + 32),
        bf + 32, bs + 32, Pd, Ps);
    fused_edge_mma_kernel<<<EE / 128, 256>>>(
        ei, eah, wf + 3072 + 64, ws + 3072 + 64, Pd, Ps, hA);

    // 4) output
    out_kernel<<<(NN + 15) / 16, 256>>>(
        (const float4*)hA, (const float4*)w_out,
        b_out, g_out, be_out, m_out, v_out, out);
}

// round 13
// speedup vs baseline: 3.7745x; 1.0469x over previous
#include <cuda_runtime.h>
#include <cuda_fp16.h>
#include <stdint.h>
#include <math.h>

#define NN   50000
#define EE   1600000
#define HH   32
#define DOUT 128
#define EPS  1e-5f
#define SLOPE 0.1f

// ---------------------------------------------------------------------------
// Scratch (device globals). ~122 MB total.
// ---------------------------------------------------------------------------
static __device__ uint4    g_eah[(size_t)EE * 4];     // edge embeddings fp16 [E,32]
static __device__ float    g_hA[(size_t)NN * HH];     // node features (in-place residual)
static __device__ float    g_Pd[(size_t)NN * 64];     // [Af+bf | As+bs] fp32, de-interleaved
static __device__ unsigned g_Ps[(size_t)NN * 32];     // (Bf, Bs) half2 per channel

// ---------------------------------------------------------------------------
// helpers
// ---------------------------------------------------------------------------
__device__ __forceinline__ unsigned pack_h2(float lo, float hi) {
    __half2 h = __floats2half2_rn(lo, hi);
    return *(unsigned*)&h;
}
__device__ __forceinline__ float2 unpack_h2(unsigned u) {
    return __half22float2(*(__half2*)&u);
}
__device__ __forceinline__ void mma_f16(
    float* d, unsigned a0, unsigned a1, unsigned a2, unsigned a3,
    unsigned b0, unsigned b1)
{
    asm volatile(
        "mma.sync.aligned.m16n8k16.row.col.f32.f16.f16.f32 "
        "{%0,%1,%2,%3}, {%4,%5,%6,%7}, {%8,%9}, {%0,%1,%2,%3};\n"
        : "+f"(d[0]), "+f"(d[1]), "+f"(d[2]), "+f"(d[3])
        : "r"(a0), "r"(a1), "r"(a2), "r"(a3), "r"(b0), "r"(b1));
}
__device__ __forceinline__ unsigned smem_u32(const void* p) {
    unsigned a;
    asm("{ .reg .u64 t; cvta.to.shared.u64 t, %1; cvt.u32.u64 %0, t; }"
        : "=r"(a) : "l"(p));
    return a;
}

// ---------------------------------------------------------------------------
// Kernel 1 (fp16 MMA, K-halves pipelined):
//   out[M,32] = lrelu(bn( in[M,128] @ w[32,128]^T + b ))
// ---------------------------------------------------------------------------
template <bool FULL, bool HALF>
__global__ __launch_bounds__(256) void embed_f16_kernel(
    const float4* __restrict__ in4, int M,
    const float* __restrict__ w,                      // [32][128] row-major
    const float* __restrict__ b,  const float* __restrict__ g,
    const float* __restrict__ be, const float* __restrict__ mm,
    const float* __restrict__ vv,
    void* __restrict__ outv)
{
    __shared__ unsigned sX[128 * 68];        // fp16 rows, stride 68 uints
    __shared__ unsigned sB0[8][4][32];       // B frags, lane-indexed
    __shared__ unsigned sB1[8][4][32];
    __shared__ float s_scale[32], s_shift[32], s_bias[32];

    const int t    = threadIdx.x;
    const int lane = t & 31;
    const int wid  = t >> 5;
    const int gq   = lane >> 2;
    const int c4   = lane & 3;
    const int r0   = blockIdx.x * 128;
    const int m0   = wid * 16;

    if (t < 32) {
        float sc = g[t] * rsqrtf(vv[t] + EPS);
        s_scale[t] = sc;
        s_shift[t] = be[t] - mm[t] * sc;
        s_bias[t]  = b[t];
    }

#pragma unroll
    for (int i = t; i < 1024; i += 256) {
        int kc = i >> 7, nt = (i >> 5) & 3, ln = i & 31;
        int g2 = ln >> 2, c2 = ln & 3;
        const float* wrow = w + (nt * 8 + g2) * 128;
        int k0 = kc * 16 + 2 * c2;
        sB0[kc][nt][ln] = pack_h2(wrow[k0],     wrow[k0 + 1]);
        sB1[kc][nt][ln] = pack_h2(wrow[k0 + 8], wrow[k0 + 9]);
    }
#pragma unroll
    for (int j = 0; j < 8; j++) {
        int idx = t + j * 256;
        int r = idx >> 4, q = idx & 15;
        int gr = r0 + r;
        float4 v = (FULL || gr < M) ? in4[(size_t)gr * 32 + q]
                                    : make_float4(0.f, 0.f, 0.f, 0.f);
        *(uint2*)&sX[r * 68 + q * 2] = make_uint2(pack_h2(v.x, v.y), pack_h2(v.z, v.w));
    }

    float4 pre[8];
#pragma unroll
    for (int j = 0; j < 8; j++) {
        int idx = t + j * 256;
        int r = idx >> 4, q = 16 + (idx & 15);
        int gr = r0 + r;
        pre[j] = (FULL || gr < M) ? in4[(size_t)gr * 32 + q]
                                  : make_float4(0.f, 0.f, 0.f, 0.f);
    }
    __syncthreads();

    const int mi     = lane >> 3;
    const int rowoff = ((mi & 1) << 3) + (lane & 7);
    const int ku     = (mi >> 1) << 2;
    unsigned abase = smem_u32(sX) + (unsigned)(((m0 + rowoff) * 68 + ku) * 4);

    float d[4][4];
#pragma unroll
    for (int nt = 0; nt < 4; nt++)
#pragma unroll
        for (int i = 0; i < 4; i++) d[nt][i] = 0.f;

#pragma unroll
    for (int kc = 0; kc < 4; kc++) {
        unsigned a0, a1, a2, a3;
        asm volatile("ldmatrix.sync.aligned.m8n8.x4.shared.b16 {%0,%1,%2,%3}, [%4];"
            : "=r"(a0), "=r"(a1), "=r"(a2), "=r"(a3)
            : "r"(abase + kc * 32));
#pragma unroll
        for (int nt = 0; nt < 4; nt++)
            mma_f16(d[nt], a0, a1, a2, a3, sB0[kc][nt][lane], sB1[kc][nt][lane]);
    }

#pragma unroll
    for (int j = 0; j < 8; j++) {
        int idx = t + j * 256;
        int r = idx >> 4, q = 16 + (idx & 15);
        float4 v = pre[j];
        *(uint2*)&sX[r * 68 + q * 2] = make_uint2(pack_h2(v.x, v.y), pack_h2(v.z, v.w));
    }
    __syncthreads();

#pragma unroll
    for (int kc = 4; kc < 8; kc++) {
        unsigned a0, a1, a2, a3;
        asm volatile("ldmatrix.sync.aligned.m8n8.x4.shared.b16 {%0,%1,%2,%3}, [%4];"
            : "=r"(a0), "=r"(a1), "=r"(a2), "=r"(a3)
            : "r"(abase + kc * 32));
#pragma unroll
        for (int nt = 0; nt < 4; nt++)
            mma_f16(d[nt], a0, a1, a2, a3, sB0[kc][nt][lane], sB1[kc][nt][lane]);
    }

#pragma unroll
    for (int nt = 0; nt < 4; nt++) {
        int col = nt * 8 + 2 * c4;
        float sc0 = s_scale[col],     sh0 = s_shift[col],     bb0 = s_bias[col];
        float sc1 = s_scale[col + 1], sh1 = s_shift[col + 1], bb1 = s_bias[col + 1];
#pragma unroll
        for (int h = 0; h < 2; h++) {
            int row = r0 + m0 + gq + h * 8;
            if (FULL || row < M) {
                float v0 = (d[nt][2 * h]     + bb0) * sc0 + sh0;
                float v1 = (d[nt][2 * h + 1] + bb1) * sc1 + sh1;
                v0 = v0 > 0.f ? v0 : SLOPE * v0;
                v1 = v1 > 0.f ? v1 : SLOPE * v1;
                if (HALF) {
                    ((unsigned*)outv)[(size_t)row * 16 + (col >> 1)] = pack_h2(v0, v1);
                } else {
                    *(float2*)((float*)outv + (size_t)row * HH + col) = make_float2(v0, v1);
                }
            }
        }
    }
}

// ---------------------------------------------------------------------------
// Kernel 2: node projections (de-interleaved Pd, half2 Ps).
// ---------------------------------------------------------------------------
__global__ __launch_bounds__(256) void proj4_kernel(
    const float4* __restrict__ in4, int M,
    const float4* __restrict__ wfd, const float4* __restrict__ wfs,
    const float4* __restrict__ wsd, const float4* __restrict__ wss,
    const float* __restrict__ bf, const float* __restrict__ bs,
    float* __restrict__ Pd, unsigned* __restrict__ Ps)
{
    __shared__ float4 wp[4][256];
    __shared__ float4 xs4[32 * 8];

    const int t = threadIdx.x;
    {
        int k4 = t >> 5, c = t & 31;
        wp[0][t] = wfd[c * 24 + k4];
        wp[1][t] = wsd[c * 24 + k4];
        wp[2][t] = wfs[c * 24 + k4];
        wp[3][t] = wss[c * 24 + k4];
    }
    const int r0 = blockIdx.x * 32;
    {
        int r = t >> 3, q = t & 7;
        int gr = r0 + r;
        xs4[t] = (gr < M) ? in4[(size_t)gr * 8 + q]
                          : make_float4(0.f, 0.f, 0.f, 0.f);
    }
    __syncthreads();

    const int c  = t & 31;
    const int rg = t >> 5;

    float acc[4][4];
#pragma unroll
    for (int m = 0; m < 4; m++)
#pragma unroll
        for (int i = 0; i < 4; i++) acc[m][i] = 0.f;

#pragma unroll
    for (int k4 = 0; k4 < 8; k4++) {
        float4 xv[4];
#pragma unroll
        for (int i = 0; i < 4; i++) xv[i] = xs4[(rg * 4 + i) * 8 + k4];
#pragma unroll
        for (int m = 0; m < 4; m++) {
            float4 wv = wp[m][k4 * 32 + c];
#pragma unroll
            for (int i = 0; i < 4; i++) {
                acc[m][i] = fmaf(xv[i].x, wv.x,
                            fmaf(xv[i].y, wv.y,
                            fmaf(xv[i].z, wv.z,
                            fmaf(xv[i].w, wv.w, acc[m][i]))));
            }
        }
    }

    const float bfc = bf[c], bsc = bs[c];
#pragma unroll
    for (int i = 0; i < 4; i++) {
        int row = r0 + rg * 4 + i;
        if (row < M) {
            Pd[(size_t)row * 64 + c]      = acc[0][i] + bfc;
            Pd[(size_t)row * 64 + 32 + c] = acc[1][i] + bsc;
            Ps[(size_t)row * 32 + c] = pack_h2(acc[2][i], acc[3][i]);
        }
    }
}

// ---------------------------------------------------------------------------
// Kernel 3a (MERGED layer 0): edge embed + edge layer in one pass.
//   EA = lrelu(bn(edge_attr @ We^T + b))  [MMA1, fp16 out -> eah + registers]
//   D  = EA @ [Wf_e|Ws_e]                 [MMA2, A-frags reused from MMA1 D!]
//   pass 2: gate + red.add into h[dst]
// Fragment identity: MMA1 D (rows gq/gq+8, cols nt*8+2c4..+1) packed as half2
// == MMA2 A-frag a0..a3 for k-chunk kc with nt = 2kc, 2kc+1.
// Smem: union 34816 + sBe 8192 + sB 4096 + idx 1024 + bn 384 = 48512 <= 48K.
// ---------------------------------------------------------------------------
__global__ __launch_bounds__(256) void fused_embed_edge_kernel(
    const int* __restrict__ ei,
    const float4* __restrict__ eattr4,        // [E][32] fp32
    const float* __restrict__ we,             // [32][128]
    const float* __restrict__ b,  const float* __restrict__ g,
    const float* __restrict__ be, const float* __restrict__ mm,
    const float* __restrict__ vv,
    const float* __restrict__ wfe, const float* __restrict__ wse,
    const float* __restrict__ Pd, const unsigned* __restrict__ Ps,
    unsigned* __restrict__ eah_out,
    float* __restrict__ hinout)
{
    __shared__ union {
        unsigned X[128 * 68];                  // fp16 edge_attr tile (phase 1)
        unsigned Dh[128 * 36];                 // fp16 D tile (phase 3)
    } u;
    __shared__ unsigned sBe0[8][4][32];        // embed W frags
    __shared__ unsigned sBe1[8][4][32];
    __shared__ unsigned sB0[2][8][32];         // edge W frags
    __shared__ unsigned sB1[2][8][32];
    __shared__ int s_src[128], s_dst[128];
    __shared__ float s_scale[32], s_shift[32], s_bias[32];

    const int t    = threadIdx.x;
    const int lane = t & 31;
    const int wid  = t >> 5;
    const int gq   = lane >> 2;
    const int c4   = lane & 3;
    const int e0   = blockIdx.x * 128;
    const int m0   = wid * 16;

    if (t < 32) {
        float sc = g[t] * rsqrtf(vv[t] + EPS);
        s_scale[t] = sc;
        s_shift[t] = be[t] - mm[t] * sc;
        s_bias[t]  = b[t];
    }
    // embed W frags
#pragma unroll
    for (int i = t; i < 1024; i += 256) {
        int kc = i >> 7, nt = (i >> 5) & 3, ln = i & 31;
        int g2 = ln >> 2, c2 = ln & 3;
        const float* wrow = we + (nt * 8 + g2) * 128;
        int k0 = kc * 16 + 2 * c2;
        sBe0[kc][nt][ln] = pack_h2(wrow[k0],     wrow[k0 + 1]);
        sBe1[kc][nt][ln] = pack_h2(wrow[k0 + 8], wrow[k0 + 9]);
    }
    // edge W frags
#pragma unroll
    for (int i = t; i < 512; i += 256) {
        int kc = i >> 8, nt = (i >> 5) & 7, ln = i & 31;
        int g2 = ln >> 2, c2 = ln & 3;
        int n  = nt * 8 + g2;
        const float* wrow = (n < 32) ? (wfe + n * 96) : (wse + (n - 32) * 96);
        int k0 = kc * 16 + 2 * c2;
        sB0[kc][nt][ln] = pack_h2(wrow[k0],     wrow[k0 + 1]);
        sB1[kc][nt][ln] = pack_h2(wrow[k0 + 8], wrow[k0 + 9]);
    }
    if (t < 128)       s_src[t]       = ei[e0 + t];
    else               s_dst[t - 128] = ei[(size_t)EE + e0 + (t - 128)];

    // X half-0 (k floats 0..63)
#pragma unroll
    for (int j = 0; j < 8; j++) {
        int idx = t + j * 256;
        int r = idx >> 4, q = idx & 15;
        float4 v = eattr4[(size_t)(e0 + r) * 32 + q];
        *(uint2*)&u.X[r * 68 + q * 2] = make_uint2(pack_h2(v.x, v.y), pack_h2(v.z, v.w));
    }
    // prefetch half-1
    float4 pre[8];
#pragma unroll
    for (int j = 0; j < 8; j++) {
        int idx = t + j * 256;
        int r = idx >> 4, q = 16 + (idx & 15);
        pre[j] = eattr4[(size_t)(e0 + r) * 32 + q];
    }
    __syncthreads();

    const int mi     = lane >> 3;
    const int rowoff = ((mi & 1) << 3) + (lane & 7);
    const int ku     = (mi >> 1) << 2;
    unsigned abase = smem_u32(u.X) + (unsigned)(((m0 + rowoff) * 68 + ku) * 4);

    // ---- MMA1: EA = edge_attr @ We^T ----
    float d[4][4];
#pragma unroll
    for (int nt = 0; nt < 4; nt++)
#pragma unroll
        for (int i = 0; i < 4; i++) d[nt][i] = 0.f;

#pragma unroll
    for (int kc = 0; kc < 4; kc++) {
        unsigned a0, a1, a2, a3;
        asm volatile("ldmatrix.sync.aligned.m8n8.x4.shared.b16 {%0,%1,%2,%3}, [%4];"
            : "=r"(a0), "=r"(a1), "=r"(a2), "=r"(a3)
            : "r"(abase + kc * 32));
#pragma unroll
        for (int nt = 0; nt < 4; nt++)
            mma_f16(d[nt], a0, a1, a2, a3, sBe0[kc][nt][lane], sBe1[kc][nt][lane]);
    }
#pragma unroll
    for (int j = 0; j < 8; j++) {
        int idx = t + j * 256;
        int r = idx >> 4, q = 16 + (idx & 15);
        float4 v = pre[j];
        *(uint2*)&u.X[r * 68 + q * 2] = make_uint2(pack_h2(v.x, v.y), pack_h2(v.z, v.w));
    }
    __syncthreads();
#pragma unroll
    for (int kc = 4; kc < 8; kc++) {
        unsigned a0, a1, a2, a3;
        asm volatile("ldmatrix.sync.aligned.m8n8.x4.shared.b16 {%0,%1,%2,%3}, [%4];"
            : "=r"(a0), "=r"(a1), "=r"(a2), "=r"(a3)
            : "r"(abase + kc * 32));
#pragma unroll
        for (int nt = 0; nt < 4; nt++)
            mma_f16(d[nt], a0, a1, a2, a3, sBe0[kc][nt][lane], sBe1[kc][nt][lane]);
    }

    // ---- epilogue: BN + lrelu -> packed half2 (= MMA2 A-frags) + eah store ----
    unsigned pa[4], pb[4];
#pragma unroll
    for (int nt = 0; nt < 4; nt++) {
        int col = nt * 8 + 2 * c4;
        float sc0 = s_scale[col],     sh0 = s_shift[col],     bb0 = s_bias[col];
        float sc1 = s_scale[col + 1], sh1 = s_shift[col + 1], bb1 = s_bias[col + 1];
        float v0 = (d[nt][0] + bb0) * sc0 + sh0;  v0 = v0 > 0.f ? v0 : SLOPE * v0;
        float v1 = (d[nt][1] + bb1) * sc1 + sh1;  v1 = v1 > 0.f ? v1 : SLOPE * v1;
        float v2 = (d[nt][2] + bb0) * sc0 + sh0;  v2 = v2 > 0.f ? v2 : SLOPE * v2;
        float v3 = (d[nt][3] + bb1) * sc1 + sh1;  v3 = v3 > 0.f ? v3 : SLOPE * v3;
        pa[nt] = pack_h2(v0, v1);
        pb[nt] = pack_h2(v2, v3);
        size_t row_lo = (size_t)(e0 + m0 + gq);
        eah_out[row_lo * 16 + (col >> 1)]       = pa[nt];
        eah_out[(row_lo + 8) * 16 + (col >> 1)] = pb[nt];
    }

    // ---- MMA2: D = EA @ [Wf_e|Ws_e] (A-frags = pa/pb, no smem) ----
    float d2[8][4];
#pragma unroll
    for (int nt = 0; nt < 8; nt++)
#pragma unroll
        for (int i = 0; i < 4; i++) d2[nt][i] = 0.f;

#pragma unroll
    for (int kc = 0; kc < 2; kc++) {
        unsigned rb0[8], rb1[8];
#pragma unroll
        for (int nt = 0; nt < 8; nt++) {
            rb0[nt] = sB0[kc][nt][lane];
            rb1[nt] = sB1[kc][nt][lane];
        }
        unsigned a0 = pa[2 * kc], a1 = pb[2 * kc];
        unsigned a2 = pa[2 * kc + 1], a3 = pb[2 * kc + 1];
#pragma unroll
        for (int nt = 0; nt < 8; nt++)
            mma_f16(d2[nt], a0, a1, a2, a3, rb0[nt], rb1[nt]);
    }

    // all warps done with u.X ldmatrix reads before overlay as u.Dh
    __syncthreads();
    {
        const int row0 = m0 + gq;
#pragma unroll
        for (int nt = 0; nt < 8; nt++) {
            int cu = nt * 4 + c4;
            u.Dh[row0 * 36 + cu]       = pack_h2(d2[nt][0], d2[nt][1]);
            u.Dh[(row0 + 8) * 36 + cu] = pack_h2(d2[nt][2], d2[nt][3]);
        }
    }
    __syncthreads();

    // pass 2: edge-coalesced gather + gate + vector reduction
    const int l  = t & 7;
    const int eb = t >> 3;
#pragma unroll
    for (int it = 0; it < 4; it++) {
        int e   = eb + it * 32;
        int dst = s_dst[e];
        int src = s_src[e];
        uint2 Fu = *(uint2*)&u.Dh[e * 36 + 2 * l];
        uint2 Su = *(uint2*)&u.Dh[e * 36 + 16 + 2 * l];
        float2 Fa = unpack_h2(Fu.x), Fb = unpack_h2(Fu.y);
        float2 Sa = unpack_h2(Su.x), Sb = unpack_h2(Su.y);
        float4 pdf = *(const float4*)&Pd[(size_t)dst * 64 + 4 * l];
        float4 pds = *(const float4*)&Pd[(size_t)dst * 64 + 32 + 4 * l];
        uint4  pv  = *(const uint4*)&Ps[(size_t)src * 32 + 4 * l];
        float2 q0 = unpack_h2(pv.x), q1 = unpack_h2(pv.y);
        float2 q2 = unpack_h2(pv.z), q3 = unpack_h2(pv.w);

        float f0 = Fa.x + pdf.x + q0.x,  s0 = Sa.x + pds.x + q0.y;
        float f1 = Fa.y + pdf.y + q1.x,  s1 = Sa.y + pds.y + q1.y;
        float f2 = Fb.x + pdf.z + q2.x,  s2 = Sb.x + pds.z + q2.y;
        float f3 = Fb.y + pdf.w + q3.x,  s3 = Sb.y + pds.w + q3.y;

        float m0_ = __fdividef(1.f, 1.f + __expf(-f0)) *
                    (fmaxf(s0, 0.f) + __logf(1.f + __expf(-fabsf(s0))));
        float m1_ = __fdividef(1.f, 1.f + __expf(-f1)) *
                    (fmaxf(s1, 0.f) + __logf(1.f + __expf(-fabsf(s1))));
        float m2_ = __fdividef(1.f, 1.f + __expf(-f2)) *
                    (fmaxf(s2, 0.f) + __logf(1.f + __expf(-fabsf(s2))));
        float m3_ = __fdividef(1.f, 1.f + __expf(-f3)) *
                    (fmaxf(s3, 0.f) + __logf(1.f + __expf(-fabsf(s3))));

        asm volatile("red.global.add.v4.f32 [%0], {%1,%2,%3,%4};"
            :: "l"(hinout + (size_t)dst * HH + 4 * l),
               "f"(m0_), "f"(m1_), "f"(m2_), "f"(m3_)
            : "memory");
    }
}

// ---------------------------------------------------------------------------
// Kernel 3b (fused edge layer 1, reads eah): unchanged from round 12.
// ---------------------------------------------------------------------------
__global__ __launch_bounds__(256) void fused_edge_mma_kernel(
    const int* __restrict__ ei,
    const uint4* __restrict__ ea16,
    const float* __restrict__ wfe,
    const float* __restrict__ wse,
    const float* __restrict__ Pd, const unsigned* __restrict__ Ps,
    float* __restrict__ hinout)
{
    __shared__ union {
        unsigned A[128 * 20];
        unsigned Dh[128 * 36];
    } u;
    __shared__ unsigned sB0[2][8][32];
    __shared__ unsigned sB1[2][8][32];
    __shared__ int s_src[128], s_dst[128];

    const int t  = threadIdx.x;
    const int e0 = blockIdx.x * 128;

#pragma unroll
    for (int j = 0; j < 2; j++) {
        int idx = t + j * 256;
        int r = idx >> 2, q = idx & 3;
        uint4 v = ea16[(size_t)(e0 + r) * 4 + q];
        *(uint4*)&u.A[r * 20 + q * 4] = v;
    }
    if (t < 128)       s_src[t]       = ei[e0 + t];
    else               s_dst[t - 128] = ei[(size_t)EE + e0 + (t - 128)];
#pragma unroll
    for (int i = t; i < 512; i += 256) {
        int kc = i >> 8, nt = (i >> 5) & 7, ln = i & 31;
        int g2 = ln >> 2, c2 = ln & 3;
        int n  = nt * 8 + g2;
        const float* wrow = (n < 32) ? (wfe + n * 96) : (wse + (n - 32) * 96);
        int k0 = kc * 16 + 2 * c2;
        sB0[kc][nt][ln] = pack_h2(wrow[k0],     wrow[k0 + 1]);
        sB1[kc][nt][ln] = pack_h2(wrow[k0 + 8], wrow[k0 + 9]);
    }
    __syncthreads();

    const int lane = t & 31;
    const int wid  = t >> 5;
    const int gq   = lane >> 2;
    const int c4   = lane & 3;
    const int m0   = wid * 16;

    float d[8][4];
#pragma unroll
    for (int nt = 0; nt < 8; nt++)
#pragma unroll
        for (int i = 0; i < 4; i++) d[nt][i] = 0.f;

#pragma unroll
    for (int kc = 0; kc < 2; kc++) {
        unsigned rb0[8], rb1[8];
#pragma unroll
        for (int nt = 0; nt < 8; nt++) {
            rb0[nt] = sB0[kc][nt][lane];
            rb1[nt] = sB1[kc][nt][lane];
        }
        int base = (m0 + gq) * 20 + kc * 8 + c4;
        unsigned a0 = u.A[base];
        unsigned a1 = u.A[base + 8 * 20];
        unsigned a2 = u.A[base + 4];
        unsigned a3 = u.A[base + 8 * 20 + 4];
#pragma unroll
        for (int nt = 0; nt < 8; nt++)
            mma_f16(d[nt], a0, a1, a2, a3, rb0[nt], rb1[nt]);
    }

    __syncthreads();
    {
        const int row0 = m0 + gq;
#pragma unroll
        for (int nt = 0; nt < 8; nt++) {
            int cu = nt * 4 + c4;
            u.Dh[row0 * 36 + cu]       = pack_h2(d[nt][0], d[nt][1]);
            u.Dh[(row0 + 8) * 36 + cu] = pack_h2(d[nt][2], d[nt][3]);
        }
    }
    __syncthreads();

    const int l  = t & 7;
    const int eb = t >> 3;
#pragma unroll
    for (int it = 0; it < 4; it++) {
        int e   = eb + it * 32;
        int dst = s_dst[e];
        int src = s_src[e];
        uint2 Fu = *(uint2*)&u.Dh[e * 36 + 2 * l];
        uint2 Su = *(uint2*)&u.Dh[e * 36 + 16 + 2 * l];
        float2 Fa = unpack_h2(Fu.x), Fb = unpack_h2(Fu.y);
        float2 Sa = unpack_h2(Su.x), Sb = unpack_h2(Su.y);
        float4 pdf = *(const float4*)&Pd[(size_t)dst * 64 + 4 * l];
        float4 pds = *(const float4*)&Pd[(size_t)dst * 64 + 32 + 4 * l];
        uint4  pv  = *(const uint4*)&Ps[(size_t)src * 32 + 4 * l];
        float2 q0 = unpack_h2(pv.x), q1 = unpack_h2(pv.y);
        float2 q2 = unpack_h2(pv.z), q3 = unpack_h2(pv.w);

        float f0 = Fa.x + pdf.x + q0.x,  s0 = Sa.x + pds.x + q0.y;
        float f1 = Fa.y + pdf.y + q1.x,  s1 = Sa.y + pds.y + q1.y;
        float f2 = Fb.x + pdf.z + q2.x,  s2 = Sb.x + pds.z + q2.y;
        float f3 = Fb.y + pdf.w + q3.x,  s3 = Sb.y + pds.w + q3.y;

        float m0_ = __fdividef(1.f, 1.f + __expf(-f0)) *
                    (fmaxf(s0, 0.f) + __logf(1.f + __expf(-fabsf(s0))));
        float m1_ = __fdividef(1.f, 1.f + __expf(-f1)) *
                    (fmaxf(s1, 0.f) + __logf(1.f + __expf(-fabsf(s1))));
        float m2_ = __fdividef(1.f, 1.f + __expf(-f2)) *
                    (fmaxf(s2, 0.f) + __logf(1.f + __expf(-fabsf(s2))));
        float m3_ = __fdividef(1.f, 1.f + __expf(-f3)) *
                    (fmaxf(s3, 0.f) + __logf(1.f + __expf(-fabsf(s3))));

        asm volatile("red.global.add.v4.f32 [%0], {%1,%2,%3,%4};"
            :: "l"(hinout + (size_t)dst * HH + 4 * l),
               "f"(m0_), "f"(m1_), "f"(m2_), "f"(m3_)
            : "memory");
    }
}

// ---------------------------------------------------------------------------
// Kernel 4: out[N,128] = lrelu(bn( h[N,32] @ w_out[128,32]^T + b ))
// ---------------------------------------------------------------------------
__global__ __launch_bounds__(256) void out_kernel(
    const float4* __restrict__ h4,
    const float4* __restrict__ w4,
    const float* __restrict__ b,  const float* __restrict__ g,
    const float* __restrict__ be, const float* __restrict__ mm,
    const float* __restrict__ vv,
    float* __restrict__ out)
{
    __shared__ float4 wp[8 * 128];
    __shared__ float4 xs4[16 * 8];

    const int t = threadIdx.x;
#pragma unroll
    for (int j = 0; j < 4; j++) {
        int i = t + j * 256;
        int k4 = i >> 7, c = i & 127;
        wp[i] = w4[c * 8 + k4];
    }
    const int r0 = blockIdx.x * 16;
    if (t < 128) {
        int r = t >> 3, q = t & 7;
        int gr = r0 + r;
        xs4[t] = (gr < NN) ? h4[(size_t)gr * 8 + q]
                           : make_float4(0.f, 0.f, 0.f, 0.f);
    }
    __syncthreads();

    const int c  = t & 127;
    const int rg = t >> 7;

    float acc[8];
#pragma unroll
    for (int i = 0; i < 8; i++) acc[i] = 0.f;

#pragma unroll
    for (int k4 = 0; k4 < 8; k4++) {
        float4 wv = wp[k4 * 128 + c];
#pragma unroll
        for (int i = 0; i < 8; i++) {
            float4 xv = xs4[(rg * 8 + i) * 8 + k4];
            acc[i] = fmaf(xv.x, wv.x,
                     fmaf(xv.y, wv.y,
                     fmaf(xv.z, wv.z,
                     fmaf(xv.w, wv.w, acc[i]))));
        }
    }

    const float scale = g[c] * rsqrtf(vv[c] + EPS);
    const float shift = be[c] - mm[c] * scale;
    const float bc    = b[c];
#pragma unroll
    for (int i = 0; i < 8; i++) {
        int row = r0 + rg * 8 + i;
        if (row < NN) {
            float val = (acc[i] + bc) * scale + shift;
            out[(size_t)row * DOUT + c] = val > 0.f ? val : SLOPE * val;
        }
    }
}

// ---------------------------------------------------------------------------
// Launch
// ---------------------------------------------------------------------------
extern "C" void kernel_launch(void* const* d_in, const int* in_sizes, int n_in,
                              void* d_out, int out_size)
{
    const float* x     = (const float*)d_in[0];
    const int*   ei    = (const int*)  d_in[1];
    const float* eattr = (const float*)d_in[2];
    const float* w_in  = (const float*)d_in[3];
    const float* b_in  = (const float*)d_in[4];
    const float* g_in  = (const float*)d_in[5];
    const float* be_in = (const float*)d_in[6];
    const float* m_in  = (const float*)d_in[7];
    const float* v_in  = (const float*)d_in[8];
    const float* w_e   = (const float*)d_in[9];
    const float* b_e   = (const float*)d_in[10];
    const float* g_e   = (const float*)d_in[11];
    const float* be_e  = (const float*)d_in[12];
    const float* m_e   = (const float*)d_in[13];
    const float* v_e   = (const float*)d_in[14];
    const float* wf    = (const float*)d_in[15];   // [2,32,96]
    const float* bf    = (const float*)d_in[16];   // [2,32]
    const float* ws    = (const float*)d_in[17];
    const float* bs    = (const float*)d_in[18];
    const float* w_out = (const float*)d_in[19];   // [128,32]
    const float* b_out = (const float*)d_in[20];
    const float* g_out = (const float*)d_in[21];
    const float* be_out= (const float*)d_in[22];
    const float* m_out = (const float*)d_in[23];
    const float* v_out = (const float*)d_in[24];
    float* out = (float*)d_out;

    uint4* eah; float *hA, *Pd; unsigned* Ps;
    cudaGetSymbolAddress((void**)&eah, g_eah);
    cudaGetSymbolAddress((void**)&hA,  g_hA);
    cudaGetSymbolAddress((void**)&Pd,  g_Pd);
    cudaGetSymbolAddress((void**)&Ps,  g_Ps);

    // 1) node embedding
    embed_f16_kernel<false, false><<<(NN + 127) / 128, 256>>>(
        (const float4*)x, NN, w_in,
        b_in, g_in, be_in, m_in, v_in, hA);

    // 2) layer-0 node projections
    proj4_kernel<<<(NN + 31) / 32, 256>>>(
        (const float4*)hA, NN,
        (const float4*)(wf),      (const float4*)(wf + 32),
        (const float4*)(ws),      (const float4*)(ws + 32),
        bf, bs, Pd, Ps);

    // 3) MERGED: edge embed + layer-0 message pass (writes eah for layer 1)
    fused_embed_edge_kernel<<<EE / 128, 256>>>(
        ei, (const float4*)eattr,
        w_e, b_e, g_e, be_e, m_e, v_e,
        wf + 64, ws + 64,
        Pd, Ps, (unsigned*)eah, hA);

    // 4) layer 1
    proj4_kernel<<<(NN + 31) / 32, 256>>>(
        (const float4*)hA, NN,
        (const float4*)(wf + 3072),      (const float4*)(wf + 3072 + 32),
        (const float4*)(ws + 3072),      (const float4*)(ws + 3072 + 32),
        bf + 32, bs + 32, Pd, Ps);
    fused_edge_mma_kernel<<<EE / 128, 256>>>(
        ei, eah, wf + 3072 + 64, ws + 3072 + 64, Pd, Ps, hA);

    // 5) output
    out_kernel<<<(NN + 15) / 16, 256>>>(
        (const float4*)hA, (const float4*)w_out,
        b_out, g_out, be_out, m_out, v_out, out);
}

// round 14
// speedup vs baseline: 3.7906x; 1.0043x over previous
#include <cuda_runtime.h>
#include <cuda_fp16.h>
#include <stdint.h>
#include <math.h>

#define NN   50000
#define EE   1600000
#define HH   32
#define DOUT 128
#define EPS  1e-5f
#define SLOPE 0.1f

// ---------------------------------------------------------------------------
// Scratch (device globals). ~122 MB total.
// ---------------------------------------------------------------------------
static __device__ uint4    g_eah[(size_t)EE * 4];     // edge embeddings fp16 [E,32]
static __device__ float    g_hA[(size_t)NN * HH];     // node features (in-place residual)
static __device__ float    g_Pd[(size_t)NN * 64];     // [Af+bf | As+bs] fp32, de-interleaved
static __device__ unsigned g_Ps[(size_t)NN * 32];     // (Bf, Bs) half2 per channel

// ---------------------------------------------------------------------------
// helpers
// ---------------------------------------------------------------------------
__device__ __forceinline__ unsigned pack_h2(float lo, float hi) {
    __half2 h = __floats2half2_rn(lo, hi);
    return *(unsigned*)&h;
}
__device__ __forceinline__ float2 unpack_h2(unsigned u) {
    return __half22float2(*(__half2*)&u);
}
__device__ __forceinline__ void mma_f16(
    float* d, unsigned a0, unsigned a1, unsigned a2, unsigned a3,
    unsigned b0, unsigned b1)
{
    asm volatile(
        "mma.sync.aligned.m16n8k16.row.col.f32.f16.f16.f32 "
        "{%0,%1,%2,%3}, {%4,%5,%6,%7}, {%8,%9}, {%0,%1,%2,%3};\n"
        : "+f"(d[0]), "+f"(d[1]), "+f"(d[2]), "+f"(d[3])
        : "r"(a0), "r"(a1), "r"(a2), "r"(a3), "r"(b0), "r"(b1));
}
__device__ __forceinline__ unsigned smem_u32(const void* p) {
    unsigned a;
    asm("{ .reg .u64 t; cvta.to.shared.u64 t, %1; cvt.u32.u64 %0, t; }"
        : "=r"(a) : "l"(p));
    return a;
}

// ---------------------------------------------------------------------------
// Kernel 1 (fp16 MMA, K-halves pipelined):
//   out[M,32] = lrelu(bn( in[M,128] @ w[32,128]^T + b ))
// ---------------------------------------------------------------------------
template <bool FULL, bool HALF>
__global__ __launch_bounds__(256) void embed_f16_kernel(
    const float4* __restrict__ in4, int M,
    const float* __restrict__ w,                      // [32][128] row-major
    const float* __restrict__ b,  const float* __restrict__ g,
    const float* __restrict__ be, const float* __restrict__ mm,
    const float* __restrict__ vv,
    void* __restrict__ outv)
{
    __shared__ unsigned sX[128 * 68];        // fp16 rows, stride 68 uints
    __shared__ unsigned sB0[8][4][32];       // B frags, lane-indexed
    __shared__ unsigned sB1[8][4][32];
    __shared__ float s_scale[32], s_shift[32], s_bias[32];

    const int t    = threadIdx.x;
    const int lane = t & 31;
    const int wid  = t >> 5;
    const int gq   = lane >> 2;
    const int c4   = lane & 3;
    const int r0   = blockIdx.x * 128;
    const int m0   = wid * 16;

    if (t < 32) {
        float sc = g[t] * rsqrtf(vv[t] + EPS);
        s_scale[t] = sc;
        s_shift[t] = be[t] - mm[t] * sc;
        s_bias[t]  = b[t];
    }

#pragma unroll
    for (int i = t; i < 1024; i += 256) {
        int kc = i >> 7, nt = (i >> 5) & 3, ln = i & 31;
        int g2 = ln >> 2, c2 = ln & 3;
        const float* wrow = w + (nt * 8 + g2) * 128;
        int k0 = kc * 16 + 2 * c2;
        sB0[kc][nt][ln] = pack_h2(wrow[k0],     wrow[k0 + 1]);
        sB1[kc][nt][ln] = pack_h2(wrow[k0 + 8], wrow[k0 + 9]);
    }
#pragma unroll
    for (int j = 0; j < 8; j++) {
        int idx = t + j * 256;
        int r = idx >> 4, q = idx & 15;
        int gr = r0 + r;
        float4 v = (FULL || gr < M) ? in4[(size_t)gr * 32 + q]
                                    : make_float4(0.f, 0.f, 0.f, 0.f);
        *(uint2*)&sX[r * 68 + q * 2] = make_uint2(pack_h2(v.x, v.y), pack_h2(v.z, v.w));
    }

    float4 pre[8];
#pragma unroll
    for (int j = 0; j < 8; j++) {
        int idx = t + j * 256;
        int r = idx >> 4, q = 16 + (idx & 15);
        int gr = r0 + r;
        pre[j] = (FULL || gr < M) ? in4[(size_t)gr * 32 + q]
                                  : make_float4(0.f, 0.f, 0.f, 0.f);
    }
    __syncthreads();

    const int mi     = lane >> 3;
    const int rowoff = ((mi & 1) << 3) + (lane & 7);
    const int ku     = (mi >> 1) << 2;
    unsigned abase = smem_u32(sX) + (unsigned)(((m0 + rowoff) * 68 + ku) * 4);

    float d[4][4];
#pragma unroll
    for (int nt = 0; nt < 4; nt++)
#pragma unroll
        for (int i = 0; i < 4; i++) d[nt][i] = 0.f;

#pragma unroll
    for (int kc = 0; kc < 4; kc++) {
        unsigned a0, a1, a2, a3;
        asm volatile("ldmatrix.sync.aligned.m8n8.x4.shared.b16 {%0,%1,%2,%3}, [%4];"
            : "=r"(a0), "=r"(a1), "=r"(a2), "=r"(a3)
            : "r"(abase + kc * 32));
#pragma unroll
        for (int nt = 0; nt < 4; nt++)
            mma_f16(d[nt], a0, a1, a2, a3, sB0[kc][nt][lane], sB1[kc][nt][lane]);
    }

#pragma unroll
    for (int j = 0; j < 8; j++) {
        int idx = t + j * 256;
        int r = idx >> 4, q = 16 + (idx & 15);
        float4 v = pre[j];
        *(uint2*)&sX[r * 68 + q * 2] = make_uint2(pack_h2(v.x, v.y), pack_h2(v.z, v.w));
    }
    __syncthreads();

#pragma unroll
    for (int kc = 4; kc < 8; kc++) {
        unsigned a0, a1, a2, a3;
        asm volatile("ldmatrix.sync.aligned.m8n8.x4.shared.b16 {%0,%1,%2,%3}, [%4];"
            : "=r"(a0), "=r"(a1), "=r"(a2), "=r"(a3)
            : "r"(abase + kc * 32));
#pragma unroll
        for (int nt = 0; nt < 4; nt++)
            mma_f16(d[nt], a0, a1, a2, a3, sB0[kc][nt][lane], sB1[kc][nt][lane]);
    }

#pragma unroll
    for (int nt = 0; nt < 4; nt++) {
        int col = nt * 8 + 2 * c4;
        float sc0 = s_scale[col],     sh0 = s_shift[col],     bb0 = s_bias[col];
        float sc1 = s_scale[col + 1], sh1 = s_shift[col + 1], bb1 = s_bias[col + 1];
#pragma unroll
        for (int h = 0; h < 2; h++) {
            int row = r0 + m0 + gq + h * 8;
            if (FULL || row < M) {
                float v0 = (d[nt][2 * h]     + bb0) * sc0 + sh0;
                float v1 = (d[nt][2 * h + 1] + bb1) * sc1 + sh1;
                v0 = v0 > 0.f ? v0 : SLOPE * v0;
                v1 = v1 > 0.f ? v1 : SLOPE * v1;
                if (HALF) {
                    ((unsigned*)outv)[(size_t)row * 16 + (col >> 1)] = pack_h2(v0, v1);
                } else {
                    *(float2*)((float*)outv + (size_t)row * HH + col) = make_float2(v0, v1);
                }
            }
        }
    }
}

// ---------------------------------------------------------------------------
// Kernel 2: node projections (de-interleaved Pd, half2 Ps).
// ---------------------------------------------------------------------------
__global__ __launch_bounds__(256) void proj4_kernel(
    const float4* __restrict__ in4, int M,
    const float4* __restrict__ wfd, const float4* __restrict__ wfs,
    const float4* __restrict__ wsd, const float4* __restrict__ wss,
    const float* __restrict__ bf, const float* __restrict__ bs,
    float* __restrict__ Pd, unsigned* __restrict__ Ps)
{
    __shared__ float4 wp[4][256];
    __shared__ float4 xs4[32 * 8];

    const int t = threadIdx.x;
    {
        int k4 = t >> 5, c = t & 31;
        wp[0][t] = wfd[c * 24 + k4];
        wp[1][t] = wsd[c * 24 + k4];
        wp[2][t] = wfs[c * 24 + k4];
        wp[3][t] = wss[c * 24 + k4];
    }
    const int r0 = blockIdx.x * 32;
    {
        int r = t >> 3, q = t & 7;
        int gr = r0 + r;
        xs4[t] = (gr < M) ? in4[(size_t)gr * 8 + q]
                          : make_float4(0.f, 0.f, 0.f, 0.f);
    }
    __syncthreads();

    const int c  = t & 31;
    const int rg = t >> 5;

    float acc[4][4];
#pragma unroll
    for (int m = 0; m < 4; m++)
#pragma unroll
        for (int i = 0; i < 4; i++) acc[m][i] = 0.f;

#pragma unroll
    for (int k4 = 0; k4 < 8; k4++) {
        float4 xv[4];
#pragma unroll
        for (int i = 0; i < 4; i++) xv[i] = xs4[(rg * 4 + i) * 8 + k4];
#pragma unroll
        for (int m = 0; m < 4; m++) {
            float4 wv = wp[m][k4 * 32 + c];
#pragma unroll
            for (int i = 0; i < 4; i++) {
                acc[m][i] = fmaf(xv[i].x, wv.x,
                            fmaf(xv[i].y, wv.y,
                            fmaf(xv[i].z, wv.z,
                            fmaf(xv[i].w, wv.w, acc[m][i]))));
            }
        }
    }

    const float bfc = bf[c], bsc = bs[c];
#pragma unroll
    for (int i = 0; i < 4; i++) {
        int row = r0 + rg * 4 + i;
        if (row < M) {
            Pd[(size_t)row * 64 + c]      = acc[0][i] + bfc;
            Pd[(size_t)row * 64 + 32 + c] = acc[1][i] + bsc;
            Ps[(size_t)row * 32 + c] = pack_h2(acc[2][i], acc[3][i]);
        }
    }
}

// ---------------------------------------------------------------------------
// Kernel 3a (MERGED layer 0): edge embed + edge layer in one pass.
// Single-pass X staging (no register pipeline) + minBlocks=3 for occupancy:
// cross-block concurrency hides the eattr stream latency.
// ---------------------------------------------------------------------------
__global__ __launch_bounds__(256, 3) void fused_embed_edge_kernel(
    const int* __restrict__ ei,
    const float4* __restrict__ eattr4,        // [E][32] fp32
    const float* __restrict__ we,             // [32][128]
    const float* __restrict__ b,  const float* __restrict__ g,
    const float* __restrict__ be, const float* __restrict__ mm,
    const float* __restrict__ vv,
    const float* __restrict__ wfe, const float* __restrict__ wse,
    const float* __restrict__ Pd, const unsigned* __restrict__ Ps,
    unsigned* __restrict__ eah_out,
    float* __restrict__ hinout)
{
    __shared__ union {
        unsigned X[128 * 68];                  // fp16 edge_attr tile (phase 1)
        unsigned Dh[128 * 36];                 // fp16 D tile (phase 3)
    } u;
    __shared__ unsigned sBe0[8][4][32];        // embed W frags
    __shared__ unsigned sBe1[8][4][32];
    __shared__ unsigned sB0[2][8][32];         // edge W frags
    __shared__ unsigned sB1[2][8][32];
    __shared__ int s_src[128], s_dst[128];
    __shared__ float s_scale[32], s_shift[32], s_bias[32];

    const int t    = threadIdx.x;
    const int lane = t & 31;
    const int wid  = t >> 5;
    const int gq   = lane >> 2;
    const int c4   = lane & 3;
    const int e0   = blockIdx.x * 128;
    const int m0   = wid * 16;

    if (t < 32) {
        float sc = g[t] * rsqrtf(vv[t] + EPS);
        s_scale[t] = sc;
        s_shift[t] = be[t] - mm[t] * sc;
        s_bias[t]  = b[t];
    }
    // embed W frags
#pragma unroll
    for (int i = t; i < 1024; i += 256) {
        int kc = i >> 7, nt = (i >> 5) & 3, ln = i & 31;
        int g2 = ln >> 2, c2 = ln & 3;
        const float* wrow = we + (nt * 8 + g2) * 128;
        int k0 = kc * 16 + 2 * c2;
        sBe0[kc][nt][ln] = pack_h2(wrow[k0],     wrow[k0 + 1]);
        sBe1[kc][nt][ln] = pack_h2(wrow[k0 + 8], wrow[k0 + 9]);
    }
    // edge W frags
#pragma unroll
    for (int i = t; i < 512; i += 256) {
        int kc = i >> 8, nt = (i >> 5) & 7, ln = i & 31;
        int g2 = ln >> 2, c2 = ln & 3;
        int n  = nt * 8 + g2;
        const float* wrow = (n < 32) ? (wfe + n * 96) : (wse + (n - 32) * 96);
        int k0 = kc * 16 + 2 * c2;
        sB0[kc][nt][ln] = pack_h2(wrow[k0],     wrow[k0 + 1]);
        sB1[kc][nt][ln] = pack_h2(wrow[k0 + 8], wrow[k0 + 9]);
    }
    if (t < 128)       s_src[t]       = ei[e0 + t];
    else               s_dst[t - 128] = ei[(size_t)EE + e0 + (t - 128)];

    // X: full tile, single pass (no register pipeline — occupancy hides latency)
#pragma unroll
    for (int j = 0; j < 16; j++) {
        int idx = t + j * 256;
        int r = idx >> 5, q = idx & 31;
        float4 v = eattr4[(size_t)(e0 + r) * 32 + q];
        *(uint2*)&u.X[r * 68 + q * 2] = make_uint2(pack_h2(v.x, v.y), pack_h2(v.z, v.w));
    }
    __syncthreads();

    const int mi     = lane >> 3;
    const int rowoff = ((mi & 1) << 3) + (lane & 7);
    const int ku     = (mi >> 1) << 2;
    unsigned abase = smem_u32(u.X) + (unsigned)(((m0 + rowoff) * 68 + ku) * 4);

    // ---- MMA1: EA = edge_attr @ We^T ----
    float d[4][4];
#pragma unroll
    for (int nt = 0; nt < 4; nt++)
#pragma unroll
        for (int i = 0; i < 4; i++) d[nt][i] = 0.f;

#pragma unroll
    for (int kc = 0; kc < 8; kc++) {
        unsigned a0, a1, a2, a3;
        asm volatile("ldmatrix.sync.aligned.m8n8.x4.shared.b16 {%0,%1,%2,%3}, [%4];"
            : "=r"(a0), "=r"(a1), "=r"(a2), "=r"(a3)
            : "r"(abase + kc * 32));
#pragma unroll
        for (int nt = 0; nt < 4; nt++)
            mma_f16(d[nt], a0, a1, a2, a3, sBe0[kc][nt][lane], sBe1[kc][nt][lane]);
    }

    // ---- epilogue: BN + lrelu -> packed half2 (= MMA2 A-frags) + eah store ----
    unsigned pa[4], pb[4];
#pragma unroll
    for (int nt = 0; nt < 4; nt++) {
        int col = nt * 8 + 2 * c4;
        float sc0 = s_scale[col],     sh0 = s_shift[col],     bb0 = s_bias[col];
        float sc1 = s_scale[col + 1], sh1 = s_shift[col + 1], bb1 = s_bias[col + 1];
        float v0 = (d[nt][0] + bb0) * sc0 + sh0;  v0 = v0 > 0.f ? v0 : SLOPE * v0;
        float v1 = (d[nt][1] + bb1) * sc1 + sh1;  v1 = v1 > 0.f ? v1 : SLOPE * v1;
        float v2 = (d[nt][2] + bb0) * sc0 + sh0;  v2 = v2 > 0.f ? v2 : SLOPE * v2;
        float v3 = (d[nt][3] + bb1) * sc1 + sh1;  v3 = v3 > 0.f ? v3 : SLOPE * v3;
        pa[nt] = pack_h2(v0, v1);
        pb[nt] = pack_h2(v2, v3);
        size_t row_lo = (size_t)(e0 + m0 + gq);
        eah_out[row_lo * 16 + (col >> 1)]       = pa[nt];
        eah_out[(row_lo + 8) * 16 + (col >> 1)] = pb[nt];
    }

    // ---- MMA2: D = EA @ [Wf_e|Ws_e] (A-frags = pa/pb, no smem) ----
    float d2[8][4];
#pragma unroll
    for (int nt = 0; nt < 8; nt++)
#pragma unroll
        for (int i = 0; i < 4; i++) d2[nt][i] = 0.f;

#pragma unroll
    for (int kc = 0; kc < 2; kc++) {
        unsigned a0 = pa[2 * kc], a1 = pb[2 * kc];
        unsigned a2 = pa[2 * kc + 1], a3 = pb[2 * kc + 1];
#pragma unroll
        for (int nt = 0; nt < 8; nt++)
            mma_f16(d2[nt], a0, a1, a2, a3, sB0[kc][nt][lane], sB1[kc][nt][lane]);
    }

    // all warps done with u.X ldmatrix reads before overlay as u.Dh
    __syncthreads();
    {
        const int row0 = m0 + gq;
#pragma unroll
        for (int nt = 0; nt < 8; nt++) {
            int cu = nt * 4 + c4;
            u.Dh[row0 * 36 + cu]       = pack_h2(d2[nt][0], d2[nt][1]);
            u.Dh[(row0 + 8) * 36 + cu] = pack_h2(d2[nt][2], d2[nt][3]);
        }
    }
    __syncthreads();

    // pass 2: edge-coalesced gather + gate + vector reduction
    const int l  = t & 7;
    const int eb = t >> 3;
#pragma unroll
    for (int it = 0; it < 4; it++) {
        int e   = eb + it * 32;
        int dst = s_dst[e];
        int src = s_src[e];
        uint2 Fu = *(uint2*)&u.Dh[e * 36 + 2 * l];
        uint2 Su = *(uint2*)&u.Dh[e * 36 + 16 + 2 * l];
        float2 Fa = unpack_h2(Fu.x), Fb = unpack_h2(Fu.y);
        float2 Sa = unpack_h2(Su.x), Sb = unpack_h2(Su.y);
        float4 pdf = *(const float4*)&Pd[(size_t)dst * 64 + 4 * l];
        float4 pds = *(const float4*)&Pd[(size_t)dst * 64 + 32 + 4 * l];
        uint4  pv  = *(const uint4*)&Ps[(size_t)src * 32 + 4 * l];
        float2 q0 = unpack_h2(pv.x), q1 = unpack_h2(pv.y);
        float2 q2 = unpack_h2(pv.z), q3 = unpack_h2(pv.w);

        float f0 = Fa.x + pdf.x + q0.x,  s0 = Sa.x + pds.x + q0.y;
        float f1 = Fa.y + pdf.y + q1.x,  s1 = Sa.y + pds.y + q1.y;
        float f2 = Fb.x + pdf.z + q2.x,  s2 = Sb.x + pds.z + q2.y;
        float f3 = Fb.y + pdf.w + q3.x,  s3 = Sb.y + pds.w + q3.y;

        float m0_ = __fdividef(1.f, 1.f + __expf(-f0)) *
                    (fmaxf(s0, 0.f) + __logf(1.f + __expf(-fabsf(s0))));
        float m1_ = __fdividef(1.f, 1.f + __expf(-f1)) *
                    (fmaxf(s1, 0.f) + __logf(1.f + __expf(-fabsf(s1))));
        float m2_ = __fdividef(1.f, 1.f + __expf(-f2)) *
                    (fmaxf(s2, 0.f) + __logf(1.f + __expf(-fabsf(s2))));
        float m3_ = __fdividef(1.f, 1.f + __expf(-f3)) *
                    (fmaxf(s3, 0.f) + __logf(1.f + __expf(-fabsf(s3))));

        asm volatile("red.global.add.v4.f32 [%0], {%1,%2,%3,%4};"
            :: "l"(hinout + (size_t)dst * HH + 4 * l),
               "f"(m0_), "f"(m1_), "f"(m2_), "f"(m3_)
            : "memory");
    }
}

// ---------------------------------------------------------------------------
// Kernel 3b (fused edge layer 1): cp.async A-tile, minBlocks=4.
// ---------------------------------------------------------------------------
__global__ __launch_bounds__(256, 4) void fused_edge_mma_kernel(
    const int* __restrict__ ei,
    const uint4* __restrict__ ea16,
    const float* __restrict__ wfe,
    const float* __restrict__ wse,
    const float* __restrict__ Pd, const unsigned* __restrict__ Ps,
    float* __restrict__ hinout)
{
    __shared__ union {
        unsigned A[128 * 20];
        unsigned Dh[128 * 36];
    } u;
    __shared__ unsigned sB0[2][8][32];
    __shared__ unsigned sB1[2][8][32];
    __shared__ int s_src[128], s_dst[128];

    const int t  = threadIdx.x;
    const int e0 = blockIdx.x * 128;

    // A tile via cp.async (fp16 in global — raw 16B copies)
    {
        unsigned sa = smem_u32(u.A);
#pragma unroll
        for (int j = 0; j < 2; j++) {
            int idx = t + j * 256;
            int r = idx >> 2, q = idx & 3;
            unsigned dstp = sa + (unsigned)((r * 20 + q * 4) * 4);
            const uint4* gp = &ea16[(size_t)(e0 + r) * 4 + q];
            asm volatile("cp.async.ca.shared.global [%0], [%1], 16;"
                :: "r"(dstp), "l"(gp));
        }
        asm volatile("cp.async.commit_group;");
    }
    if (t < 128)       s_src[t]       = ei[e0 + t];
    else               s_dst[t - 128] = ei[(size_t)EE + e0 + (t - 128)];
#pragma unroll
    for (int i = t; i < 512; i += 256) {
        int kc = i >> 8, nt = (i >> 5) & 7, ln = i & 31;
        int g2 = ln >> 2, c2 = ln & 3;
        int n  = nt * 8 + g2;
        const float* wrow = (n < 32) ? (wfe + n * 96) : (wse + (n - 32) * 96);
        int k0 = kc * 16 + 2 * c2;
        sB0[kc][nt][ln] = pack_h2(wrow[k0],     wrow[k0 + 1]);
        sB1[kc][nt][ln] = pack_h2(wrow[k0 + 8], wrow[k0 + 9]);
    }
    asm volatile("cp.async.wait_group 0;" ::: "memory");
    __syncthreads();

    const int lane = t & 31;
    const int wid  = t >> 5;
    const int gq   = lane >> 2;
    const int c4   = lane & 3;
    const int m0   = wid * 16;

    float d[8][4];
#pragma unroll
    for (int nt = 0; nt < 8; nt++)
#pragma unroll
        for (int i = 0; i < 4; i++) d[nt][i] = 0.f;

#pragma unroll
    for (int kc = 0; kc < 2; kc++) {
        int base = (m0 + gq) * 20 + kc * 8 + c4;
        unsigned a0 = u.A[base];
        unsigned a1 = u.A[base + 8 * 20];
        unsigned a2 = u.A[base + 4];
        unsigned a3 = u.A[base + 8 * 20 + 4];
#pragma unroll
        for (int nt = 0; nt < 8; nt++)
            mma_f16(d[nt], a0, a1, a2, a3, sB0[kc][nt][lane], sB1[kc][nt][lane]);
    }

    __syncthreads();
    {
        const int row0 = m0 + gq;
#pragma unroll
        for (int nt = 0; nt < 8; nt++) {
            int cu = nt * 4 + c4;
            u.Dh[row0 * 36 + cu]       = pack_h2(d[nt][0], d[nt][1]);
            u.Dh[(row0 + 8) * 36 + cu] = pack_h2(d[nt][2], d[nt][3]);
        }
    }
    __syncthreads();

    const int l  = t & 7;
    const int eb = t >> 3;
#pragma unroll
    for (int it = 0; it < 4; it++) {
        int e   = eb + it * 32;
        int dst = s_dst[e];
        int src = s_src[e];
        uint2 Fu = *(uint2*)&u.Dh[e * 36 + 2 * l];
        uint2 Su = *(uint2*)&u.Dh[e * 36 + 16 + 2 * l];
        float2 Fa = unpack_h2(Fu.x), Fb = unpack_h2(Fu.y);
        float2 Sa = unpack_h2(Su.x), Sb = unpack_h2(Su.y);
        float4 pdf = *(const float4*)&Pd[(size_t)dst * 64 + 4 * l];
        float4 pds = *(const float4*)&Pd[(size_t)dst * 64 + 32 + 4 * l];
        uint4  pv  = *(const uint4*)&Ps[(size_t)src * 32 + 4 * l];
        float2 q0 = unpack_h2(pv.x), q1 = unpack_h2(pv.y);
        float2 q2 = unpack_h2(pv.z), q3 = unpack_h2(pv.w);

        float f0 = Fa.x + pdf.x + q0.x,  s0 = Sa.x + pds.x + q0.y;
        float f1 = Fa.y + pdf.y + q1.x,  s1 = Sa.y + pds.y + q1.y;
        float f2 = Fb.x + pdf.z + q2.x,  s2 = Sb.x + pds.z + q2.y;
        float f3 = Fb.y + pdf.w + q3.x,  s3 = Sb.y + pds.w + q3.y;

        float m0_ = __fdividef(1.f, 1.f + __expf(-f0)) *
                    (fmaxf(s0, 0.f) + __logf(1.f + __expf(-fabsf(s0))));
        float m1_ = __fdividef(1.f, 1.f + __expf(-f1)) *
                    (fmaxf(s1, 0.f) + __logf(1.f + __expf(-fabsf(s1))));
        float m2_ = __fdividef(1.f, 1.f + __expf(-f2)) *
                    (fmaxf(s2, 0.f) + __logf(1.f + __expf(-fabsf(s2))));
        float m3_ = __fdividef(1.f, 1.f + __expf(-f3)) *
                    (fmaxf(s3, 0.f) + __logf(1.f + __expf(-fabsf(s3))));

        asm volatile("red.global.add.v4.f32 [%0], {%1,%2,%3,%4};"
            :: "l"(hinout + (size_t)dst * HH + 4 * l),
               "f"(m0_), "f"(m1_), "f"(m2_), "f"(m3_)
            : "memory");
    }
}

// ---------------------------------------------------------------------------
// Kernel 4: out[N,128] = lrelu(bn( h[N,32] @ w_out[128,32]^T + b ))
// ---------------------------------------------------------------------------
__global__ __launch_bounds__(256) void out_kernel(
    const float4* __restrict__ h4,
    const float4* __restrict__ w4,
    const float* __restrict__ b,  const float* __restrict__ g,
    const float* __restrict__ be, const float* __restrict__ mm,
    const float* __restrict__ vv,
    float* __restrict__ out)
{
    __shared__ float4 wp[8 * 128];
    __shared__ float4 xs4[16 * 8];

    const int t = threadIdx.x;
#pragma unroll
    for (int j = 0; j < 4; j++) {
        int i = t + j * 256;
        int k4 = i >> 7, c = i & 127;
        wp[i] = w4[c * 8 + k4];
    }
    const int r0 = blockIdx.x * 16;
    if (t < 128) {
        int r = t >> 3, q = t & 7;
        int gr = r0 + r;
        xs4[t] = (gr < NN) ? h4[(size_t)gr * 8 + q]
                           : make_float4(0.f, 0.f, 0.f, 0.f);
    }
    __syncthreads();

    const int c  = t & 127;
    const int rg = t >> 7;

    float acc[8];
#pragma unroll
    for (int i = 0; i < 8; i++) acc[i] = 0.f;

#pragma unroll
    for (int k4 = 0; k4 < 8; k4++) {
        float4 wv = wp[k4 * 128 + c];
#pragma unroll
        for (int i = 0; i < 8; i++) {
            float4 xv = xs4[(rg * 8 + i) * 8 + k4];
            acc[i] = fmaf(xv.x, wv.x,
                     fmaf(xv.y, wv.y,
                     fmaf(xv.z, wv.z,
                     fmaf(xv.w, wv.w, acc[i]))));
        }
    }

    const float scale = g[c] * rsqrtf(vv[c] + EPS);
    const float shift = be[c] - mm[c] * scale;
    const float bc    = b[c];
#pragma unroll
    for (int i = 0; i < 8; i++) {
        int row = r0 + rg * 8 + i;
        if (row < NN) {
            float val = (acc[i] + bc) * scale + shift;
            out[(size_t)row * DOUT + c] = val > 0.f ? val : SLOPE * val;
        }
    }
}

// ---------------------------------------------------------------------------
// Launch
// ---------------------------------------------------------------------------
extern "C" void kernel_launch(void* const* d_in, const int* in_sizes, int n_in,
                              void* d_out, int out_size)
{
    const float* x     = (const float*)d_in[0];
    const int*   ei    = (const int*)  d_in[1];
    const float* eattr = (const float*)d_in[2];
    const float* w_in  = (const float*)d_in[3];
    const float* b_in  = (const float*)d_in[4];
    const float* g_in  = (const float*)d_in[5];
    const float* be_in = (const float*)d_in[6];
    const float* m_in  = (const float*)d_in[7];
    const float* v_in  = (const float*)d_in[8];
    const float* w_e   = (const float*)d_in[9];
    const float* b_e   = (const float*)d_in[10];
    const float* g_e   = (const float*)d_in[11];
    const float* be_e  = (const float*)d_in[12];
    const float* m_e   = (const float*)d_in[13];
    const float* v_e   = (const float*)d_in[14];
    const float* wf    = (const float*)d_in[15];   // [2,32,96]
    const float* bf    = (const float*)d_in[16];   // [2,32]
    const float* ws    = (const float*)d_in[17];
    const float* bs    = (const float*)d_in[18];
    const float* w_out = (const float*)d_in[19];   // [128,32]
    const float* b_out = (const float*)d_in[20];
    const float* g_out = (const float*)d_in[21];
    const float* be_out= (const float*)d_in[22];
    const float* m_out = (const float*)d_in[23];
    const float* v_out = (const float*)d_in[24];
    float* out = (float*)d_out;

    uint4* eah; float *hA, *Pd; unsigned* Ps;
    cudaGetSymbolAddress((void**)&eah, g_eah);
    cudaGetSymbolAddress((void**)&hA,  g_hA);
    cudaGetSymbolAddress((void**)&Pd,  g_Pd);
    cudaGetSymbolAddress((void**)&Ps,  g_Ps);

    // 1) node embedding
    embed_f16_kernel<false, false><<<(NN + 127) / 128, 256>>>(
        (const float4*)x, NN, w_in,
        b_in, g_in, be_in, m_in, v_in, hA);

    // 2) layer-0 node projections
    proj4_kernel<<<(NN + 31) / 32, 256>>>(
        (const float4*)hA, NN,
        (const float4*)(wf),      (const float4*)(wf + 32),
        (const float4*)(ws),      (const float4*)(ws + 32),
        bf, bs, Pd, Ps);

    // 3) MERGED: edge embed + layer-0 message pass (writes eah for layer 1)
    fused_embed_edge_kernel<<<EE / 128, 256>>>(
        ei, (const float4*)eattr,
        w_e, b_e, g_e, be_e, m_e, v_e,
        wf + 64, ws + 64,
        Pd, Ps, (unsigned*)eah, hA);

    // 4) layer 1
    proj4_kernel<<<(NN + 31) / 32, 256>>>(
        (const float4*)hA, NN,
        (const float4*)(wf + 3072),      (const float4*)(wf + 3072 + 32),
        (const float4*)(ws + 3072),      (const float4*)(ws + 3072 + 32),
        bf + 32, bs + 32, Pd, Ps);
    fused_edge_mma_kernel<<<EE / 128, 256>>>(
        ei, eah, wf + 3072 + 64, ws + 3072 + 64, Pd, Ps, hA);

    // 5) output
    out_kernel<<<(NN + 15) / 16, 256>>>(
        (const float4*)hA, (const float4*)w_out,
        b_out, g_out, be_out, m_out, v_out, out);
}

// round 15
// speedup vs baseline: 3.9245x; 1.0353x over previous
#include <cuda_runtime.h>
#include <cuda_fp16.h>
#include <stdint.h>
#include <math.h>

#define NN   50000
#define EE   1600000
#define HH   32
#define DOUT 128
#define EPS  1e-5f
#define SLOPE 0.1f

// ---------------------------------------------------------------------------
// Scratch (device globals). ~116 MB total.
// ---------------------------------------------------------------------------
static __device__ uint4    g_eah[(size_t)EE * 4];     // edge embeddings fp16 [E,32]
static __device__ float    g_hA[(size_t)NN * HH];     // node features (in-place residual)
static __device__ unsigned g_Pd[(size_t)NN * 32];     // (Af+bf, As+bs) half2 per channel
static __device__ unsigned g_Ps[(size_t)NN * 32];     // (Bf, Bs) half2 per channel

// ---------------------------------------------------------------------------
// helpers
// ---------------------------------------------------------------------------
__device__ __forceinline__ unsigned pack_h2(float lo, float hi) {
    __half2 h = __floats2half2_rn(lo, hi);
    return *(unsigned*)&h;
}
__device__ __forceinline__ float2 unpack_h2(unsigned u) {
    return __half22float2(*(__half2*)&u);
}
__device__ __forceinline__ void mma_f16(
    float* d, unsigned a0, unsigned a1, unsigned a2, unsigned a3,
    unsigned b0, unsigned b1)
{
    asm volatile(
        "mma.sync.aligned.m16n8k16.row.col.f32.f16.f16.f32 "
        "{%0,%1,%2,%3}, {%4,%5,%6,%7}, {%8,%9}, {%0,%1,%2,%3};\n"
        : "+f"(d[0]), "+f"(d[1]), "+f"(d[2]), "+f"(d[3])
        : "r"(a0), "r"(a1), "r"(a2), "r"(a3), "r"(b0), "r"(b1));
}
__device__ __forceinline__ unsigned smem_u32(const void* p) {
    unsigned a;
    asm("{ .reg .u64 t; cvta.to.shared.u64 t, %1; cvt.u32.u64 %0, t; }"
        : "=r"(a) : "l"(p));
    return a;
}
// gated message: sigmoid(f) * softplus(s); sigmoid via tanh (1 MUFU vs 2)
__device__ __forceinline__ float gate_msg(float f, float s) {
    float t;
    asm("tanh.approx.f32 %0, %1;" : "=f"(t) : "f"(f * 0.5f));
    float sig = fmaf(t, 0.5f, 0.5f);
    float sp  = fmaxf(s, 0.f) + __logf(1.f + __expf(-fabsf(s)));
    return sig * sp;
}

// ---------------------------------------------------------------------------
// Kernel 1 (fp16 MMA, K-halves pipelined):
//   out[M,32] = lrelu(bn( in[M,128] @ w[32,128]^T + b ))
// ---------------------------------------------------------------------------
template <bool FULL, bool HALF>
__global__ __launch_bounds__(256) void embed_f16_kernel(
    const float4* __restrict__ in4, int M,
    const float* __restrict__ w,                      // [32][128] row-major
    const float* __restrict__ b,  const float* __restrict__ g,
    const float* __restrict__ be, const float* __restrict__ mm,
    const float* __restrict__ vv,
    void* __restrict__ outv)
{
    __shared__ unsigned sX[128 * 68];        // fp16 rows, stride 68 uints
    __shared__ uint2 sB[8][4][32];           // B frags (b0,b1), lane-indexed
    __shared__ float s_scale[32], s_shift[32], s_bias[32];

    const int t    = threadIdx.x;
    const int lane = t & 31;
    const int wid  = t >> 5;
    const int gq   = lane >> 2;
    const int c4   = lane & 3;
    const int r0   = blockIdx.x * 128;
    const int m0   = wid * 16;

    if (t < 32) {
        float sc = g[t] * rsqrtf(vv[t] + EPS);
        s_scale[t] = sc;
        s_shift[t] = be[t] - mm[t] * sc;
        s_bias[t]  = b[t];
    }

#pragma unroll
    for (int i = t; i < 1024; i += 256) {
        int kc = i >> 7, nt = (i >> 5) & 3, ln = i & 31;
        int g2 = ln >> 2, c2 = ln & 3;
        const float* wrow = w + (nt * 8 + g2) * 128;
        int k0 = kc * 16 + 2 * c2;
        sB[kc][nt][ln] = make_uint2(pack_h2(wrow[k0],     wrow[k0 + 1]),
                                    pack_h2(wrow[k0 + 8], wrow[k0 + 9]));
    }
#pragma unroll
    for (int j = 0; j < 8; j++) {
        int idx = t + j * 256;
        int r = idx >> 4, q = idx & 15;
        int gr = r0 + r;
        float4 v = (FULL || gr < M) ? in4[(size_t)gr * 32 + q]
                                    : make_float4(0.f, 0.f, 0.f, 0.f);
        *(uint2*)&sX[r * 68 + q * 2] = make_uint2(pack_h2(v.x, v.y), pack_h2(v.z, v.w));
    }

    float4 pre[8];
#pragma unroll
    for (int j = 0; j < 8; j++) {
        int idx = t + j * 256;
        int r = idx >> 4, q = 16 + (idx & 15);
        int gr = r0 + r;
        pre[j] = (FULL || gr < M) ? in4[(size_t)gr * 32 + q]
                                  : make_float4(0.f, 0.f, 0.f, 0.f);
    }
    __syncthreads();

    const int mi     = lane >> 3;
    const int rowoff = ((mi & 1) << 3) + (lane & 7);
    const int ku     = (mi >> 1) << 2;
    unsigned abase = smem_u32(sX) + (unsigned)(((m0 + rowoff) * 68 + ku) * 4);

    float d[4][4];
#pragma unroll
    for (int nt = 0; nt < 4; nt++)
#pragma unroll
        for (int i = 0; i < 4; i++) d[nt][i] = 0.f;

#pragma unroll
    for (int kc = 0; kc < 4; kc++) {
        unsigned a0, a1, a2, a3;
        asm volatile("ldmatrix.sync.aligned.m8n8.x4.shared.b16 {%0,%1,%2,%3}, [%4];"
            : "=r"(a0), "=r"(a1), "=r"(a2), "=r"(a3)
            : "r"(abase + kc * 32));
#pragma unroll
        for (int nt = 0; nt < 4; nt++) {
            uint2 bb = sB[kc][nt][lane];
            mma_f16(d[nt], a0, a1, a2, a3, bb.x, bb.y);
        }
    }

#pragma unroll
    for (int j = 0; j < 8; j++) {
        int idx = t + j * 256;
        int r = idx >> 4, q = 16 + (idx & 15);
        float4 v = pre[j];
        *(uint2*)&sX[r * 68 + q * 2] = make_uint2(pack_h2(v.x, v.y), pack_h2(v.z, v.w));
    }
    __syncthreads();

#pragma unroll
    for (int kc = 4; kc < 8; kc++) {
        unsigned a0, a1, a2, a3;
        asm volatile("ldmatrix.sync.aligned.m8n8.x4.shared.b16 {%0,%1,%2,%3}, [%4];"
            : "=r"(a0), "=r"(a1), "=r"(a2), "=r"(a3)
            : "r"(abase + kc * 32));
#pragma unroll
        for (int nt = 0; nt < 4; nt++) {
            uint2 bb = sB[kc][nt][lane];
            mma_f16(d[nt], a0, a1, a2, a3, bb.x, bb.y);
        }
    }

#pragma unroll
    for (int nt = 0; nt < 4; nt++) {
        int col = nt * 8 + 2 * c4;
        float sc0 = s_scale[col],     sh0 = s_shift[col],     bb0 = s_bias[col];
        float sc1 = s_scale[col + 1], sh1 = s_shift[col + 1], bb1 = s_bias[col + 1];
#pragma unroll
        for (int h = 0; h < 2; h++) {
            int row = r0 + m0 + gq + h * 8;
            if (FULL || row < M) {
                float v0 = (d[nt][2 * h]     + bb0) * sc0 + sh0;
                float v1 = (d[nt][2 * h + 1] + bb1) * sc1 + sh1;
                v0 = v0 > 0.f ? v0 : SLOPE * v0;
                v1 = v1 > 0.f ? v1 : SLOPE * v1;
                if (HALF) {
                    ((unsigned*)outv)[(size_t)row * 16 + (col >> 1)] = pack_h2(v0, v1);
                } else {
                    *(float2*)((float*)outv + (size_t)row * HH + col) = make_float2(v0, v1);
                }
            }
        }
    }
}

// ---------------------------------------------------------------------------
// Kernel 2: node projections. Both outputs packed fp16:
//   Pd[row*32+c] = half2( (h@Wf_dst^T)[c]+bf[c], (h@Ws_dst^T)[c]+bs[c] )
//   Ps[row*32+c] = half2( (h@Wf_src^T)[c],       (h@Ws_src^T)[c] )
// ---------------------------------------------------------------------------
__global__ __launch_bounds__(256) void proj4_kernel(
    const float4* __restrict__ in4, int M,
    const float4* __restrict__ wfd, const float4* __restrict__ wfs,
    const float4* __restrict__ wsd, const float4* __restrict__ wss,
    const float* __restrict__ bf, const float* __restrict__ bs,
    unsigned* __restrict__ Pd, unsigned* __restrict__ Ps)
{
    __shared__ float4 wp[4][256];
    __shared__ float4 xs4[32 * 8];

    const int t = threadIdx.x;
    {
        int k4 = t >> 5, c = t & 31;
        wp[0][t] = wfd[c * 24 + k4];
        wp[1][t] = wsd[c * 24 + k4];
        wp[2][t] = wfs[c * 24 + k4];
        wp[3][t] = wss[c * 24 + k4];
    }
    const int r0 = blockIdx.x * 32;
    {
        int r = t >> 3, q = t & 7;
        int gr = r0 + r;
        xs4[t] = (gr < M) ? in4[(size_t)gr * 8 + q]
                          : make_float4(0.f, 0.f, 0.f, 0.f);
    }
    __syncthreads();

    const int c  = t & 31;
    const int rg = t >> 5;

    float acc[4][4];
#pragma unroll
    for (int m = 0; m < 4; m++)
#pragma unroll
        for (int i = 0; i < 4; i++) acc[m][i] = 0.f;

#pragma unroll
    for (int k4 = 0; k4 < 8; k4++) {
        float4 xv[4];
#pragma unroll
        for (int i = 0; i < 4; i++) xv[i] = xs4[(rg * 4 + i) * 8 + k4];
#pragma unroll
        for (int m = 0; m < 4; m++) {
            float4 wv = wp[m][k4 * 32 + c];
#pragma unroll
            for (int i = 0; i < 4; i++) {
                acc[m][i] = fmaf(xv[i].x, wv.x,
                            fmaf(xv[i].y, wv.y,
                            fmaf(xv[i].z, wv.z,
                            fmaf(xv[i].w, wv.w, acc[m][i]))));
            }
        }
    }

    const float bfc = bf[c], bsc = bs[c];
#pragma unroll
    for (int i = 0; i < 4; i++) {
        int row = r0 + rg * 4 + i;
        if (row < M) {
            Pd[(size_t)row * 32 + c] = pack_h2(acc[0][i] + bfc, acc[1][i] + bsc);
            Ps[(size_t)row * 32 + c] = pack_h2(acc[2][i], acc[3][i]);
        }
    }
}

// ---------------------------------------------------------------------------
// Kernel 3a (MERGED layer 0): edge embed + edge layer in one pass.
// ---------------------------------------------------------------------------
__global__ __launch_bounds__(256, 3) void fused_embed_edge_kernel(
    const int* __restrict__ ei,
    const float4* __restrict__ eattr4,        // [E][32] fp32
    const float* __restrict__ we,             // [32][128]
    const float* __restrict__ b,  const float* __restrict__ g,
    const float* __restrict__ be, const float* __restrict__ mm,
    const float* __restrict__ vv,
    const float* __restrict__ wfe, const float* __restrict__ wse,
    const unsigned* __restrict__ Pd, const unsigned* __restrict__ Ps,
    unsigned* __restrict__ eah_out,
    float* __restrict__ hinout)
{
    __shared__ union {
        unsigned X[128 * 68];                  // fp16 edge_attr tile (phase 1)
        unsigned Dh[128 * 36];                 // fp16 D tile (phase 3)
    } u;
    __shared__ uint2 sBe[8][4][32];            // embed W frags
    __shared__ uint2 sB[2][8][32];             // edge W frags
    __shared__ int s_src[128], s_dst[128];
    __shared__ float s_scale[32], s_shift[32], s_bias[32];

    const int t    = threadIdx.x;
    const int lane = t & 31;
    const int wid  = t >> 5;
    const int gq   = lane >> 2;
    const int c4   = lane & 3;
    const int e0   = blockIdx.x * 128;
    const int m0   = wid * 16;

    if (t < 32) {
        float sc = g[t] * rsqrtf(vv[t] + EPS);
        s_scale[t] = sc;
        s_shift[t] = be[t] - mm[t] * sc;
        s_bias[t]  = b[t];
    }
#pragma unroll
    for (int i = t; i < 1024; i += 256) {
        int kc = i >> 7, nt = (i >> 5) & 3, ln = i & 31;
        int g2 = ln >> 2, c2 = ln & 3;
        const float* wrow = we + (nt * 8 + g2) * 128;
        int k0 = kc * 16 + 2 * c2;
        sBe[kc][nt][ln] = make_uint2(pack_h2(wrow[k0],     wrow[k0 + 1]),
                                     pack_h2(wrow[k0 + 8], wrow[k0 + 9]));
    }
#pragma unroll
    for (int i = t; i < 512; i += 256) {
        int kc = i >> 8, nt = (i >> 5) & 7, ln = i & 31;
        int g2 = ln >> 2, c2 = ln & 3;
        int n  = nt * 8 + g2;
        const float* wrow = (n < 32) ? (wfe + n * 96) : (wse + (n - 32) * 96);
        int k0 = kc * 16 + 2 * c2;
        sB[kc][nt][ln] = make_uint2(pack_h2(wrow[k0],     wrow[k0 + 1]),
                                    pack_h2(wrow[k0 + 8], wrow[k0 + 9]));
    }
    if (t < 128)       s_src[t]       = ei[e0 + t];
    else               s_dst[t - 128] = ei[(size_t)EE + e0 + (t - 128)];

#pragma unroll
    for (int j = 0; j < 16; j++) {
        int idx = t + j * 256;
        int r = idx >> 5, q = idx & 31;
        float4 v = eattr4[(size_t)(e0 + r) * 32 + q];
        *(uint2*)&u.X[r * 68 + q * 2] = make_uint2(pack_h2(v.x, v.y), pack_h2(v.z, v.w));
    }
    __syncthreads();

    const int mi     = lane >> 3;
    const int rowoff = ((mi & 1) << 3) + (lane & 7);
    const int ku     = (mi >> 1) << 2;
    unsigned abase = smem_u32(u.X) + (unsigned)(((m0 + rowoff) * 68 + ku) * 4);

    // ---- MMA1: EA = edge_attr @ We^T ----
    float d[4][4];
#pragma unroll
    for (int nt = 0; nt < 4; nt++)
#pragma unroll
        for (int i = 0; i < 4; i++) d[nt][i] = 0.f;

#pragma unroll
    for (int kc = 0; kc < 8; kc++) {
        unsigned a0, a1, a2, a3;
        asm volatile("ldmatrix.sync.aligned.m8n8.x4.shared.b16 {%0,%1,%2,%3}, [%4];"
            : "=r"(a0), "=r"(a1), "=r"(a2), "=r"(a3)
            : "r"(abase + kc * 32));
#pragma unroll
        for (int nt = 0; nt < 4; nt++) {
            uint2 bb = sBe[kc][nt][lane];
            mma_f16(d[nt], a0, a1, a2, a3, bb.x, bb.y);
        }
    }

    // ---- epilogue: BN + lrelu -> packed half2 (= MMA2 A-frags) + eah store ----
    unsigned pa[4], pb[4];
#pragma unroll
    for (int nt = 0; nt < 4; nt++) {
        int col = nt * 8 + 2 * c4;
        float sc0 = s_scale[col],     sh0 = s_shift[col],     bb0 = s_bias[col];
        float sc1 = s_scale[col + 1], sh1 = s_shift[col + 1], bb1 = s_bias[col + 1];
        float v0 = (d[nt][0] + bb0) * sc0 + sh0;  v0 = v0 > 0.f ? v0 : SLOPE * v0;
        float v1 = (d[nt][1] + bb1) * sc1 + sh1;  v1 = v1 > 0.f ? v1 : SLOPE * v1;
        float v2 = (d[nt][2] + bb0) * sc0 + sh0;  v2 = v2 > 0.f ? v2 : SLOPE * v2;
        float v3 = (d[nt][3] + bb1) * sc1 + sh1;  v3 = v3 > 0.f ? v3 : SLOPE * v3;
        pa[nt] = pack_h2(v0, v1);
        pb[nt] = pack_h2(v2, v3);
        size_t row_lo = (size_t)(e0 + m0 + gq);
        eah_out[row_lo * 16 + (col >> 1)]       = pa[nt];
        eah_out[(row_lo + 8) * 16 + (col >> 1)] = pb[nt];
    }

    // ---- MMA2: D = EA @ [Wf_e|Ws_e] (A-frags = pa/pb, no smem) ----
    float d2[8][4];
#pragma unroll
    for (int nt = 0; nt < 8; nt++)
#pragma unroll
        for (int i = 0; i < 4; i++) d2[nt][i] = 0.f;

#pragma unroll
    for (int kc = 0; kc < 2; kc++) {
        unsigned a0 = pa[2 * kc], a1 = pb[2 * kc];
        unsigned a2 = pa[2 * kc + 1], a3 = pb[2 * kc + 1];
#pragma unroll
        for (int nt = 0; nt < 8; nt++) {
            uint2 bb = sB[kc][nt][lane];
            mma_f16(d2[nt], a0, a1, a2, a3, bb.x, bb.y);
        }
    }

    __syncthreads();
    {
        const int row0 = m0 + gq;
#pragma unroll
        for (int nt = 0; nt < 8; nt++) {
            int cu = nt * 4 + c4;
            u.Dh[row0 * 36 + cu]       = pack_h2(d2[nt][0], d2[nt][1]);
            u.Dh[(row0 + 8) * 36 + cu] = pack_h2(d2[nt][2], d2[nt][3]);
        }
    }
    __syncthreads();

    // pass 2: edge-coalesced gather + gate + vector reduction
    const int l  = t & 7;
    const int eb = t >> 3;
#pragma unroll
    for (int it = 0; it < 4; it++) {
        int e   = eb + it * 32;
        int dst = s_dst[e];
        int src = s_src[e];
        uint2 Fu = *(uint2*)&u.Dh[e * 36 + 2 * l];
        uint2 Su = *(uint2*)&u.Dh[e * 36 + 16 + 2 * l];
        float2 Fa = unpack_h2(Fu.x), Fb = unpack_h2(Fu.y);
        float2 Sa = unpack_h2(Su.x), Sb = unpack_h2(Su.y);
        uint4 pdv = *(const uint4*)&Pd[(size_t)dst * 32 + 4 * l];
        uint4 pv  = *(const uint4*)&Ps[(size_t)src * 32 + 4 * l];
        float2 p0 = unpack_h2(pdv.x), p1 = unpack_h2(pdv.y);
        float2 p2 = unpack_h2(pdv.z), p3 = unpack_h2(pdv.w);
        float2 q0 = unpack_h2(pv.x),  q1 = unpack_h2(pv.y);
        float2 q2 = unpack_h2(pv.z),  q3 = unpack_h2(pv.w);

        float m0_ = gate_msg(Fa.x + p0.x + q0.x, Sa.x + p0.y + q0.y);
        float m1_ = gate_msg(Fa.y + p1.x + q1.x, Sa.y + p1.y + q1.y);
        float m2_ = gate_msg(Fb.x + p2.x + q2.x, Sb.x + p2.y + q2.y);
        float m3_ = gate_msg(Fb.y + p3.x + q3.x, Sb.y + p3.y + q3.y);

        asm volatile("red.global.add.v4.f32 [%0], {%1,%2,%3,%4};"
            :: "l"(hinout + (size_t)dst * HH + 4 * l),
               "f"(m0_), "f"(m1_), "f"(m2_), "f"(m3_)
            : "memory");
    }
}

// ---------------------------------------------------------------------------
// Kernel 3b (fused edge layer 1): cp.async A-tile, minBlocks=4.
// ---------------------------------------------------------------------------
__global__ __launch_bounds__(256, 4) void fused_edge_mma_kernel(
    const int* __restrict__ ei,
    const uint4* __restrict__ ea16,
    const float* __restrict__ wfe,
    const float* __restrict__ wse,
    const unsigned* __restrict__ Pd, const unsigned* __restrict__ Ps,
    float* __restrict__ hinout)
{
    __shared__ union {
        unsigned A[128 * 20];
        unsigned Dh[128 * 36];
    } u;
    __shared__ uint2 sB[2][8][32];
    __shared__ int s_src[128], s_dst[128];

    const int t  = threadIdx.x;
    const int e0 = blockIdx.x * 128;

    {
        unsigned sa = smem_u32(u.A);
#pragma unroll
        for (int j = 0; j < 2; j++) {
            int idx = t + j * 256;
            int r = idx >> 2, q = idx & 3;
            unsigned dstp = sa + (unsigned)((r * 20 + q * 4) * 4);
            const uint4* gp = &ea16[(size_t)(e0 + r) * 4 + q];
            asm volatile("cp.async.ca.shared.global [%0], [%1], 16;"
                :: "r"(dstp), "l"(gp));
        }
        asm volatile("cp.async.commit_group;");
    }
    if (t < 128)       s_src[t]       = ei[e0 + t];
    else               s_dst[t - 128] = ei[(size_t)EE + e0 + (t - 128)];
#pragma unroll
    for (int i = t; i < 512; i += 256) {
        int kc = i >> 8, nt = (i >> 5) & 7, ln = i & 31;
        int g2 = ln >> 2, c2 = ln & 3;
        int n  = nt * 8 + g2;
        const float* wrow = (n < 32) ? (wfe + n * 96) : (wse + (n - 32) * 96);
        int k0 = kc * 16 + 2 * c2;
        sB[kc][nt][ln] = make_uint2(pack_h2(wrow[k0],     wrow[k0 + 1]),
                                    pack_h2(wrow[k0 + 8], wrow[k0 + 9]));
    }
    asm volatile("cp.async.wait_group 0;" ::: "memory");
    __syncthreads();

    const int lane = t & 31;
    const int wid  = t >> 5;
    const int gq   = lane >> 2;
    const int c4   = lane & 3;
    const int m0   = wid * 16;

    float d[8][4];
#pragma unroll
    for (int nt = 0; nt < 8; nt++)
#pragma unroll
        for (int i = 0; i < 4; i++) d[nt][i] = 0.f;

#pragma unroll
    for (int kc = 0; kc < 2; kc++) {
        int base = (m0 + gq) * 20 + kc * 8 + c4;
        unsigned a0 = u.A[base];
        unsigned a1 = u.A[base + 8 * 20];
        unsigned a2 = u.A[base + 4];
        unsigned a3 = u.A[base + 8 * 20 + 4];
#pragma unroll
        for (int nt = 0; nt < 8; nt++) {
            uint2 bb = sB[kc][nt][lane];
            mma_f16(d[nt], a0, a1, a2, a3, bb.x, bb.y);
        }
    }

    __syncthreads();
    {
        const int row0 = m0 + gq;
#pragma unroll
        for (int nt = 0; nt < 8; nt++) {
            int cu = nt * 4 + c4;
            u.Dh[row0 * 36 + cu]       = pack_h2(d[nt][0], d[nt][1]);
            u.Dh[(row0 + 8) * 36 + cu] = pack_h2(d[nt][2], d[nt][3]);
        }
    }
    __syncthreads();

    const int l  = t & 7;
    const int eb = t >> 3;
#pragma unroll
    for (int it = 0; it < 4; it++) {
        int e   = eb + it * 32;
        int dst = s_dst[e];
        int src = s_src[e];
        uint2 Fu = *(uint2*)&u.Dh[e * 36 + 2 * l];
        uint2 Su = *(uint2*)&u.Dh[e * 36 + 16 + 2 * l];
        float2 Fa = unpack_h2(Fu.x), Fb = unpack_h2(Fu.y);
        float2 Sa = unpack_h2(Su.x), Sb = unpack_h2(Su.y);
        uint4 pdv = *(const uint4*)&Pd[(size_t)dst * 32 + 4 * l];
        uint4 pv  = *(const uint4*)&Ps[(size_t)src * 32 + 4 * l];
        float2 p0 = unpack_h2(pdv.x), p1 = unpack_h2(pdv.y);
        float2 p2 = unpack_h2(pdv.z), p3 = unpack_h2(pdv.w);
        float2 q0 = unpack_h2(pv.x),  q1 = unpack_h2(pv.y);
        float2 q2 = unpack_h2(pv.z),  q3 = unpack_h2(pv.w);

        float m0_ = gate_msg(Fa.x + p0.x + q0.x, Sa.x + p0.y + q0.y);
        float m1_ = gate_msg(Fa.y + p1.x + q1.x, Sa.y + p1.y + q1.y);
        float m2_ = gate_msg(Fb.x + p2.x + q2.x, Sb.x + p2.y + q2.y);
        float m3_ = gate_msg(Fb.y + p3.x + q3.x, Sb.y + p3.y + q3.y);

        asm volatile("red.global.add.v4.f32 [%0], {%1,%2,%3,%4};"
            :: "l"(hinout + (size_t)dst * HH + 4 * l),
               "f"(m0_), "f"(m1_), "f"(m2_), "f"(m3_)
            : "memory");
    }
}

// ---------------------------------------------------------------------------
// Kernel 4: out[N,128] = lrelu(bn( h[N,32] @ w_out[128,32]^T + b ))
// ---------------------------------------------------------------------------
__global__ __launch_bounds__(256) void out_kernel(
    const float4* __restrict__ h4,
    const float4* __restrict__ w4,
    const float* __restrict__ b,  const float* __restrict__ g,
    const float* __restrict__ be, const float* __restrict__ mm,
    const float* __restrict__ vv,
    float* __restrict__ out)
{
    __shared__ float4 wp[8 * 128];
    __shared__ float4 xs4[16 * 8];

    const int t = threadIdx.x;
#pragma unroll
    for (int j = 0; j < 4; j++) {
        int i = t + j * 256;
        int k4 = i >> 7, c = i & 127;
        wp[i] = w4[c * 8 + k4];
    }
    const int r0 = blockIdx.x * 16;
    if (t < 128) {
        int r = t >> 3, q = t & 7;
        int gr = r0 + r;
        xs4[t] = (gr < NN) ? h4[(size_t)gr * 8 + q]
                           : make_float4(0.f, 0.f, 0.f, 0.f);
    }
    __syncthreads();

    const int c  = t & 127;
    const int rg = t >> 7;

    float acc[8];
#pragma unroll
    for (int i = 0; i < 8; i++) acc[i] = 0.f;

#pragma unroll
    for (int k4 = 0; k4 < 8; k4++) {
        float4 wv = wp[k4 * 128 + c];
#pragma unroll
        for (int i = 0; i < 8; i++) {
            float4 xv = xs4[(rg * 8 + i) * 8 + k4];
            acc[i] = fmaf(xv.x, wv.x,
                     fmaf(xv.y, wv.y,
                     fmaf(xv.z, wv.z,
                     fmaf(xv.w, wv.w, acc[i]))));
        }
    }

    const float scale = g[c] * rsqrtf(vv[c] + EPS);
    const float shift = be[c] - mm[c] * scale;
    const float bc    = b[c];
#pragma unroll
    for (int i = 0; i < 8; i++) {
        int row = r0 + rg * 8 + i;
        if (row < NN) {
            float val = (acc[i] + bc) * scale + shift;
            out[(size_t)row * DOUT + c] = val > 0.f ? val : SLOPE * val;
        }
    }
}

// ---------------------------------------------------------------------------
// Launch
// ---------------------------------------------------------------------------
extern "C" void kernel_launch(void* const* d_in, const int* in_sizes, int n_in,
                              void* d_out, int out_size)
{
    const float* x     = (const float*)d_in[0];
    const int*   ei    = (const int*)  d_in[1];
    const float* eattr = (const float*)d_in[2];
    const float* w_in  = (const float*)d_in[3];
    const float* b_in  = (const float*)d_in[4];
    const float* g_in  = (const float*)d_in[5];
    const float* be_in = (const float*)d_in[6];
    const float* m_in  = (const float*)d_in[7];
    const float* v_in  = (const float*)d_in[8];
    const float* w_e   = (const float*)d_in[9];
    const float* b_e   = (const float*)d_in[10];
    const float* g_e   = (const float*)d_in[11];
    const float* be_e  = (const float*)d_in[12];
    const float* m_e   = (const float*)d_in[13];
    const float* v_e   = (const float*)d_in[14];
    const float* wf    = (const float*)d_in[15];   // [2,32,96]
    const float* bf    = (const float*)d_in[16];   // [2,32]
    const float* ws    = (const float*)d_in[17];
    const float* bs    = (const float*)d_in[18];
    const float* w_out = (const float*)d_in[19];   // [128,32]
    const float* b_out = (const float*)d_in[20];
    const float* g_out = (const float*)d_in[21];
    const float* be_out= (const float*)d_in[22];
    const float* m_out = (const float*)d_in[23];
    const float* v_out = (const float*)d_in[24];
    float* out = (float*)d_out;

    uint4* eah; float* hA; unsigned *Pd, *Ps;
    cudaGetSymbolAddress((void**)&eah, g_eah);
    cudaGetSymbolAddress((void**)&hA,  g_hA);
    cudaGetSymbolAddress((void**)&Pd,  g_Pd);
    cudaGetSymbolAddress((void**)&Ps,  g_Ps);

    // 1) node embedding
    embed_f16_kernel<false, false><<<(NN + 127) / 128, 256>>>(
        (const float4*)x, NN, w_in,
        b_in, g_in, be_in, m_in, v_in, hA);

    // 2) layer-0 node projections
    proj4_kernel<<<(NN + 31) / 32, 256>>>(
        (const float4*)hA, NN,
        (const float4*)(wf),      (const float4*)(wf + 32),
        (const float4*)(ws),      (const float4*)(ws + 32),
        bf, bs, Pd, Ps);

    // 3) MERGED: edge embed + layer-0 message pass (writes eah for layer 1)
    fused_embed_edge_kernel<<<EE / 128, 256>>>(
        ei, (const float4*)eattr,
        w_e, b_e, g_e, be_e, m_e, v_e,
        wf + 64, ws + 64,
        Pd, Ps, (unsigned*)eah, hA);

    // 4) layer 1
    proj4_kernel<<<(NN + 31) / 32, 256>>>(
        (const float4*)hA, NN,
        (const float4*)(wf + 3072),      (const float4*)(wf + 3072 + 32),
        (const float4*)(ws + 3072),      (const float4*)(ws + 3072 + 32),
        bf + 32, bs + 32, Pd, Ps);
    fused_edge_mma_kernel<<<EE / 128, 256>>>(
        ei, eah, wf + 3072 + 64, ws + 3072 + 64, Pd, Ps, hA);

    // 5) output
    out_kernel<<<(NN + 15) / 16, 256>>>(
        (const float4*)hA, (const float4*)w_out,
        b_out, g_out, be_out, m_out, v_out, out);
}

// round 16
// speedup vs baseline: 4.4675x; 1.1383x over previous
#include <cuda_runtime.h>
#include <cuda_fp16.h>
#include <stdint.h>
#include <math.h>

#define NN   50000
#define EE   1600000
#define HH   32
#define DOUT 128
#define EPS  1e-5f
#define SLOPE 0.1f

// ---------------------------------------------------------------------------
// Scratch (device globals). ~116 MB total.
// ---------------------------------------------------------------------------
static __device__ uint4    g_eah[(size_t)EE * 4];     // edge embeddings fp16 [E,32]
static __device__ float    g_hA[(size_t)NN * HH];     // node features (in-place residual)
static __device__ unsigned g_Pd[(size_t)NN * 32];     // (Af+bf, As+bs) half2 per channel
static __device__ unsigned g_Ps[(size_t)NN * 32];     // (Bf, Bs) half2 per channel
static __device__ uint2    g_wfrag[2048];             // packed fp16 W frags:
                                                      // [0,1024)   embed We
                                                      // [1024,1536) layer-0 edge W
                                                      // [1536,2048) layer-1 edge W

// ---------------------------------------------------------------------------
// helpers
// ---------------------------------------------------------------------------
__device__ __forceinline__ unsigned pack_h2(float lo, float hi) {
    __half2 h = __floats2half2_rn(lo, hi);
    return *(unsigned*)&h;
}
__device__ __forceinline__ float2 unpack_h2(unsigned u) {
    return __half22float2(*(__half2*)&u);
}
__device__ __forceinline__ void mma_f16(
    float* d, unsigned a0, unsigned a1, unsigned a2, unsigned a3,
    unsigned b0, unsigned b1)
{
    asm volatile(
        "mma.sync.aligned.m16n8k16.row.col.f32.f16.f16.f32 "
        "{%0,%1,%2,%3}, {%4,%5,%6,%7}, {%8,%9}, {%0,%1,%2,%3};\n"
        : "+f"(d[0]), "+f"(d[1]), "+f"(d[2]), "+f"(d[3])
        : "r"(a0), "r"(a1), "r"(a2), "r"(a3), "r"(b0), "r"(b1));
}
__device__ __forceinline__ unsigned smem_u32(const void* p) {
    unsigned a;
    asm("{ .reg .u64 t; cvta.to.shared.u64 t, %1; cvt.u32.u64 %0, t; }"
        : "=r"(a) : "l"(p));
    return a;
}
// gated message: sigmoid(f) * softplus(s); sigmoid via tanh (1 MUFU vs 2)
__device__ __forceinline__ float gate_msg(float f, float s) {
    float t;
    asm("tanh.approx.f32 %0, %1;" : "=f"(t) : "f"(f * 0.5f));
    float sig = fmaf(t, 0.5f, 0.5f);
    float sp  = fmaxf(s, 0.f) + __logf(1.f + __expf(-fabsf(s)));
    return sig * sp;
}

// ---------------------------------------------------------------------------
// Kernel 0: pack weight fragments (one block; runs once per call).
//   [0,1024):    embed We frags   flat = kc*128 + nt*32 + ln   (kc<8, nt<4)
//   [1024+l*512): edge W frags    flat = kc*256 + nt*32 + ln   (kc<2, nt<8)
// ---------------------------------------------------------------------------
__global__ void pack_wfrags_kernel(
    const float* __restrict__ we,              // [32][128]
    const float* __restrict__ wf,              // [2][32][96]
    const float* __restrict__ ws)
{
    const int t = threadIdx.x;    // 256
    for (int i = t; i < 1024; i += 256) {
        int kc = i >> 7, nt = (i >> 5) & 3, ln = i & 31;
        int g2 = ln >> 2, c2 = ln & 3;
        const float* wrow = we + (nt * 8 + g2) * 128;
        int k0 = kc * 16 + 2 * c2;
        g_wfrag[i] = make_uint2(pack_h2(wrow[k0],     wrow[k0 + 1]),
                                pack_h2(wrow[k0 + 8], wrow[k0 + 9]));
    }
    for (int l = 0; l < 2; l++) {
        const float* wfe = wf + l * 3072 + 64;
        const float* wse = ws + l * 3072 + 64;
        for (int i = t; i < 512; i += 256) {
            int kc = i >> 8, nt = (i >> 5) & 7, ln = i & 31;
            int g2 = ln >> 2, c2 = ln & 3;
            int n  = nt * 8 + g2;
            const float* wrow = (n < 32) ? (wfe + n * 96) : (wse + (n - 32) * 96);
            int k0 = kc * 16 + 2 * c2;
            g_wfrag[1024 + l * 512 + i] =
                make_uint2(pack_h2(wrow[k0],     wrow[k0 + 1]),
                           pack_h2(wrow[k0 + 8], wrow[k0 + 9]));
        }
    }
}

// ---------------------------------------------------------------------------
// Kernel 1 (fp16 MMA, K-halves pipelined):
//   out[M,32] = lrelu(bn( in[M,128] @ w[32,128]^T + b ))
// ---------------------------------------------------------------------------
template <bool FULL, bool HALF>
__global__ __launch_bounds__(256) void embed_f16_kernel(
    const float4* __restrict__ in4, int M,
    const float* __restrict__ w,                      // [32][128] row-major
    const float* __restrict__ b,  const float* __restrict__ g,
    const float* __restrict__ be, const float* __restrict__ mm,
    const float* __restrict__ vv,
    void* __restrict__ outv)
{
    __shared__ unsigned sX[128 * 68];        // fp16 rows, stride 68 uints
    __shared__ uint2 sB[8][4][32];           // B frags (b0,b1), lane-indexed
    __shared__ float s_scale[32], s_shift[32], s_bias[32];

    const int t    = threadIdx.x;
    const int lane = t & 31;
    const int wid  = t >> 5;
    const int gq   = lane >> 2;
    const int c4   = lane & 3;
    const int r0   = blockIdx.x * 128;
    const int m0   = wid * 16;

    if (t < 32) {
        float sc = g[t] * rsqrtf(vv[t] + EPS);
        s_scale[t] = sc;
        s_shift[t] = be[t] - mm[t] * sc;
        s_bias[t]  = b[t];
    }

#pragma unroll
    for (int i = t; i < 1024; i += 256) {
        int kc = i >> 7, nt = (i >> 5) & 3, ln = i & 31;
        int g2 = ln >> 2, c2 = ln & 3;
        const float* wrow = w + (nt * 8 + g2) * 128;
        int k0 = kc * 16 + 2 * c2;
        sB[kc][nt][ln] = make_uint2(pack_h2(wrow[k0],     wrow[k0 + 1]),
                                    pack_h2(wrow[k0 + 8], wrow[k0 + 9]));
    }
#pragma unroll
    for (int j = 0; j < 8; j++) {
        int idx = t + j * 256;
        int r = idx >> 4, q = idx & 15;
        int gr = r0 + r;
        float4 v = (FULL || gr < M) ? in4[(size_t)gr * 32 + q]
                                    : make_float4(0.f, 0.f, 0.f, 0.f);
        *(uint2*)&sX[r * 68 + q * 2] = make_uint2(pack_h2(v.x, v.y), pack_h2(v.z, v.w));
    }

    float4 pre[8];
#pragma unroll
    for (int j = 0; j < 8; j++) {
        int idx = t + j * 256;
        int r = idx >> 4, q = 16 + (idx & 15);
        int gr = r0 + r;
        pre[j] = (FULL || gr < M) ? in4[(size_t)gr * 32 + q]
                                  : make_float4(0.f, 0.f, 0.f, 0.f);
    }
    __syncthreads();

    const int mi     = lane >> 3;
    const int rowoff = ((mi & 1) << 3) + (lane & 7);
    const int ku     = (mi >> 1) << 2;
    unsigned abase = smem_u32(sX) + (unsigned)(((m0 + rowoff) * 68 + ku) * 4);

    float d[4][4];
#pragma unroll
    for (int nt = 0; nt < 4; nt++)
#pragma unroll
        for (int i = 0; i < 4; i++) d[nt][i] = 0.f;

#pragma unroll
    for (int kc = 0; kc < 4; kc++) {
        unsigned a0, a1, a2, a3;
        asm volatile("ldmatrix.sync.aligned.m8n8.x4.shared.b16 {%0,%1,%2,%3}, [%4];"
            : "=r"(a0), "=r"(a1), "=r"(a2), "=r"(a3)
            : "r"(abase + kc * 32));
#pragma unroll
        for (int nt = 0; nt < 4; nt++) {
            uint2 bb = sB[kc][nt][lane];
            mma_f16(d[nt], a0, a1, a2, a3, bb.x, bb.y);
        }
    }

#pragma unroll
    for (int j = 0; j < 8; j++) {
        int idx = t + j * 256;
        int r = idx >> 4, q = 16 + (idx & 15);
        float4 v = pre[j];
        *(uint2*)&sX[r * 68 + q * 2] = make_uint2(pack_h2(v.x, v.y), pack_h2(v.z, v.w));
    }
    __syncthreads();

#pragma unroll
    for (int kc = 4; kc < 8; kc++) {
        unsigned a0, a1, a2, a3;
        asm volatile("ldmatrix.sync.aligned.m8n8.x4.shared.b16 {%0,%1,%2,%3}, [%4];"
            : "=r"(a0), "=r"(a1), "=r"(a2), "=r"(a3)
            : "r"(abase + kc * 32));
#pragma unroll
        for (int nt = 0; nt < 4; nt++) {
            uint2 bb = sB[kc][nt][lane];
            mma_f16(d[nt], a0, a1, a2, a3, bb.x, bb.y);
        }
    }

#pragma unroll
    for (int nt = 0; nt < 4; nt++) {
        int col = nt * 8 + 2 * c4;
        float sc0 = s_scale[col],     sh0 = s_shift[col],     bb0 = s_bias[col];
        float sc1 = s_scale[col + 1], sh1 = s_shift[col + 1], bb1 = s_bias[col + 1];
#pragma unroll
        for (int h = 0; h < 2; h++) {
            int row = r0 + m0 + gq + h * 8;
            if (FULL || row < M) {
                float v0 = (d[nt][2 * h]     + bb0) * sc0 + sh0;
                float v1 = (d[nt][2 * h + 1] + bb1) * sc1 + sh1;
                v0 = v0 > 0.f ? v0 : SLOPE * v0;
                v1 = v1 > 0.f ? v1 : SLOPE * v1;
                if (HALF) {
                    ((unsigned*)outv)[(size_t)row * 16 + (col >> 1)] = pack_h2(v0, v1);
                } else {
                    *(float2*)((float*)outv + (size_t)row * HH + col) = make_float2(v0, v1);
                }
            }
        }
    }
}

// ---------------------------------------------------------------------------
// Kernel 2: node projections. Both outputs packed fp16.
// ---------------------------------------------------------------------------
__global__ __launch_bounds__(256) void proj4_kernel(
    const float4* __restrict__ in4, int M,
    const float4* __restrict__ wfd, const float4* __restrict__ wfs,
    const float4* __restrict__ wsd, const float4* __restrict__ wss,
    const float* __restrict__ bf, const float* __restrict__ bs,
    unsigned* __restrict__ Pd, unsigned* __restrict__ Ps)
{
    __shared__ float4 wp[4][256];
    __shared__ float4 xs4[32 * 8];

    const int t = threadIdx.x;
    {
        int k4 = t >> 5, c = t & 31;
        wp[0][t] = wfd[c * 24 + k4];
        wp[1][t] = wsd[c * 24 + k4];
        wp[2][t] = wfs[c * 24 + k4];
        wp[3][t] = wss[c * 24 + k4];
    }
    const int r0 = blockIdx.x * 32;
    {
        int r = t >> 3, q = t & 7;
        int gr = r0 + r;
        xs4[t] = (gr < M) ? in4[(size_t)gr * 8 + q]
                          : make_float4(0.f, 0.f, 0.f, 0.f);
    }
    __syncthreads();

    const int c  = t & 31;
    const int rg = t >> 5;

    float acc[4][4];
#pragma unroll
    for (int m = 0; m < 4; m++)
#pragma unroll
        for (int i = 0; i < 4; i++) acc[m][i] = 0.f;

#pragma unroll
    for (int k4 = 0; k4 < 8; k4++) {
        float4 xv[4];
#pragma unroll
        for (int i = 0; i < 4; i++) xv[i] = xs4[(rg * 4 + i) * 8 + k4];
#pragma unroll
        for (int m = 0; m < 4; m++) {
            float4 wv = wp[m][k4 * 32 + c];
#pragma unroll
            for (int i = 0; i < 4; i++) {
                acc[m][i] = fmaf(xv[i].x, wv.x,
                            fmaf(xv[i].y, wv.y,
                            fmaf(xv[i].z, wv.z,
                            fmaf(xv[i].w, wv.w, acc[m][i]))));
            }
        }
    }

    const float bfc = bf[c], bsc = bs[c];
#pragma unroll
    for (int i = 0; i < 4; i++) {
        int row = r0 + rg * 4 + i;
        if (row < M) {
            Pd[(size_t)row * 32 + c] = pack_h2(acc[0][i] + bfc, acc[1][i] + bsc);
            Ps[(size_t)row * 32 + c] = pack_h2(acc[2][i], acc[3][i]);
        }
    }
}

// ---------------------------------------------------------------------------
// Kernel 3a (MERGED layer 0): edge embed + edge layer. W frags from g_wfrag.
// ---------------------------------------------------------------------------
__global__ __launch_bounds__(256, 3) void fused_embed_edge_kernel(
    const int* __restrict__ ei,
    const float4* __restrict__ eattr4,        // [E][32] fp32
    const float* __restrict__ b,  const float* __restrict__ g,
    const float* __restrict__ be, const float* __restrict__ mm,
    const float* __restrict__ vv,
    const uint2* __restrict__ wfragE,          // 1024 entries (embed)
    const uint2* __restrict__ wfragL,          // 512 entries (edge, this layer)
    const unsigned* __restrict__ Pd, const unsigned* __restrict__ Ps,
    unsigned* __restrict__ eah_out,
    float* __restrict__ hinout)
{
    __shared__ union {
        unsigned X[128 * 68];                  // fp16 edge_attr tile (phase 1)
        unsigned Dh[128 * 36];                 // fp16 D tile (phase 3)
    } u;
    __shared__ uint2 sBe[8][4][32];            // embed W frags
    __shared__ uint2 sB[2][8][32];             // edge W frags
    __shared__ int s_src[128], s_dst[128];
    __shared__ float s_scale[32], s_shift[32], s_bias[32];

    const int t    = threadIdx.x;
    const int lane = t & 31;
    const int wid  = t >> 5;
    const int gq   = lane >> 2;
    const int c4   = lane & 3;
    const int e0   = blockIdx.x * 128;
    const int m0   = wid * 16;

    if (t < 32) {
        float sc = g[t] * rsqrtf(vv[t] + EPS);
        s_scale[t] = sc;
        s_shift[t] = be[t] - mm[t] * sc;
        s_bias[t]  = b[t];
    }
    // stage W frags: coalesced copies from the packed table
    {
        uint2* be_f = &sBe[0][0][0];
#pragma unroll
        for (int i = t; i < 1024; i += 256) be_f[i] = wfragE[i];
        uint2* b_f = &sB[0][0][0];
#pragma unroll
        for (int i = t; i < 512; i += 256) b_f[i] = wfragL[i];
    }
    if (t < 128)       s_src[t]       = ei[e0 + t];
    else               s_dst[t - 128] = ei[(size_t)EE + e0 + (t - 128)];

#pragma unroll
    for (int j = 0; j < 16; j++) {
        int idx = t + j * 256;
        int r = idx >> 5, q = idx & 31;
        float4 v = eattr4[(size_t)(e0 + r) * 32 + q];
        *(uint2*)&u.X[r * 68 + q * 2] = make_uint2(pack_h2(v.x, v.y), pack_h2(v.z, v.w));
    }
    __syncthreads();

    const int mi     = lane >> 3;
    const int rowoff = ((mi & 1) << 3) + (lane & 7);
    const int ku     = (mi >> 1) << 2;
    unsigned abase = smem_u32(u.X) + (unsigned)(((m0 + rowoff) * 68 + ku) * 4);

    // ---- MMA1: EA = edge_attr @ We^T ----
    float d[4][4];
#pragma unroll
    for (int nt = 0; nt < 4; nt++)
#pragma unroll
        for (int i = 0; i < 4; i++) d[nt][i] = 0.f;

#pragma unroll
    for (int kc = 0; kc < 8; kc++) {
        unsigned a0, a1, a2, a3;
        asm volatile("ldmatrix.sync.aligned.m8n8.x4.shared.b16 {%0,%1,%2,%3}, [%4];"
            : "=r"(a0), "=r"(a1), "=r"(a2), "=r"(a3)
            : "r"(abase + kc * 32));
#pragma unroll
        for (int nt = 0; nt < 4; nt++) {
            uint2 bb = sBe[kc][nt][lane];
            mma_f16(d[nt], a0, a1, a2, a3, bb.x, bb.y);
        }
    }

    // ---- epilogue: BN + lrelu -> packed half2 (= MMA2 A-frags) + eah store ----
    unsigned pa[4], pb[4];
#pragma unroll
    for (int nt = 0; nt < 4; nt++) {
        int col = nt * 8 + 2 * c4;
        float sc0 = s_scale[col],     sh0 = s_shift[col],     bb0 = s_bias[col];
        float sc1 = s_scale[col + 1], sh1 = s_shift[col + 1], bb1 = s_bias[col + 1];
        float v0 = (d[nt][0] + bb0) * sc0 + sh0;  v0 = v0 > 0.f ? v0 : SLOPE * v0;
        float v1 = (d[nt][1] + bb1) * sc1 + sh1;  v1 = v1 > 0.f ? v1 : SLOPE * v1;
        float v2 = (d[nt][2] + bb0) * sc0 + sh0;  v2 = v2 > 0.f ? v2 : SLOPE * v2;
        float v3 = (d[nt][3] + bb1) * sc1 + sh1;  v3 = v3 > 0.f ? v3 : SLOPE * v3;
        pa[nt] = pack_h2(v0, v1);
        pb[nt] = pack_h2(v2, v3);
        size_t row_lo = (size_t)(e0 + m0 + gq);
        eah_out[row_lo * 16 + (col >> 1)]       = pa[nt];
        eah_out[(row_lo + 8) * 16 + (col >> 1)] = pb[nt];
    }

    // ---- MMA2: D = EA @ [Wf_e|Ws_e] (A-frags = pa/pb, no smem) ----
    float d2[8][4];
#pragma unroll
    for (int nt = 0; nt < 8; nt++)
#pragma unroll
        for (int i = 0; i < 4; i++) d2[nt][i] = 0.f;

#pragma unroll
    for (int kc = 0; kc < 2; kc++) {
        unsigned a0 = pa[2 * kc], a1 = pb[2 * kc];
        unsigned a2 = pa[2 * kc + 1], a3 = pb[2 * kc + 1];
#pragma unroll
        for (int nt = 0; nt < 8; nt++) {
            uint2 bb = sB[kc][nt][lane];
            mma_f16(d2[nt], a0, a1, a2, a3, bb.x, bb.y);
        }
    }

    __syncthreads();
    {
        const int row0 = m0 + gq;
#pragma unroll
        for (int nt = 0; nt < 8; nt++) {
            int cu = nt * 4 + c4;
            u.Dh[row0 * 36 + cu]       = pack_h2(d2[nt][0], d2[nt][1]);
            u.Dh[(row0 + 8) * 36 + cu] = pack_h2(d2[nt][2], d2[nt][3]);
        }
    }
    __syncthreads();

    // pass 2: edge-coalesced gather + gate + vector reduction
    const int l  = t & 7;
    const int eb = t >> 3;
#pragma unroll
    for (int it = 0; it < 4; it++) {
        int e   = eb + it * 32;
        int dst = s_dst[e];
        int src = s_src[e];
        uint2 Fu = *(uint2*)&u.Dh[e * 36 + 2 * l];
        uint2 Su = *(uint2*)&u.Dh[e * 36 + 16 + 2 * l];
        float2 Fa = unpack_h2(Fu.x), Fb = unpack_h2(Fu.y);
        float2 Sa = unpack_h2(Su.x), Sb = unpack_h2(Su.y);
        uint4 pdv = *(const uint4*)&Pd[(size_t)dst * 32 + 4 * l];
        uint4 pv  = *(const uint4*)&Ps[(size_t)src * 32 + 4 * l];
        float2 p0 = unpack_h2(pdv.x), p1 = unpack_h2(pdv.y);
        float2 p2 = unpack_h2(pdv.z), p3 = unpack_h2(pdv.w);
        float2 q0 = unpack_h2(pv.x),  q1 = unpack_h2(pv.y);
        float2 q2 = unpack_h2(pv.z),  q3 = unpack_h2(pv.w);

        float m0_ = gate_msg(Fa.x + p0.x + q0.x, Sa.x + p0.y + q0.y);
        float m1_ = gate_msg(Fa.y + p1.x + q1.x, Sa.y + p1.y + q1.y);
        float m2_ = gate_msg(Fb.x + p2.x + q2.x, Sb.x + p2.y + q2.y);
        float m3_ = gate_msg(Fb.y + p3.x + q3.x, Sb.y + p3.y + q3.y);

        asm volatile("red.global.add.v4.f32 [%0], {%1,%2,%3,%4};"
            :: "l"(hinout + (size_t)dst * HH + 4 * l),
               "f"(m0_), "f"(m1_), "f"(m2_), "f"(m3_)
            : "memory");
    }
}

// ---------------------------------------------------------------------------
// Kernel 3b (fused edge layer 1): cp.async A-tile; W frags from g_wfrag.
// ---------------------------------------------------------------------------
__global__ __launch_bounds__(256, 4) void fused_edge_mma_kernel(
    const int* __restrict__ ei,
    const uint4* __restrict__ ea16,
    const uint2* __restrict__ wfragL,          // 512 entries
    const unsigned* __restrict__ Pd, const unsigned* __restrict__ Ps,
    float* __restrict__ hinout)
{
    __shared__ union {
        unsigned A[128 * 20];
        unsigned Dh[128 * 36];
    } u;
    __shared__ uint2 sB[2][8][32];
    __shared__ int s_src[128], s_dst[128];

    const int t  = threadIdx.x;
    const int e0 = blockIdx.x * 128;

    {
        unsigned sa = smem_u32(u.A);
#pragma unroll
        for (int j = 0; j < 2; j++) {
            int idx = t + j * 256;
            int r = idx >> 2, q = idx & 3;
            unsigned dstp = sa + (unsigned)((r * 20 + q * 4) * 4);
            const uint4* gp = &ea16[(size_t)(e0 + r) * 4 + q];
            asm volatile("cp.async.ca.shared.global [%0], [%1], 16;"
                :: "r"(dstp), "l"(gp));
        }
        asm volatile("cp.async.commit_group;");
    }
    if (t < 128)       s_src[t]       = ei[e0 + t];
    else               s_dst[t - 128] = ei[(size_t)EE + e0 + (t - 128)];
    {
        uint2* b_f = &sB[0][0][0];
#pragma unroll
        for (int i = t; i < 512; i += 256) b_f[i] = wfragL[i];
    }
    asm volatile("cp.async.wait_group 0;" ::: "memory");
    __syncthreads();

    const int lane = t & 31;
    const int wid  = t >> 5;
    const int gq   = lane >> 2;
    const int c4   = lane & 3;
    const int m0   = wid * 16;

    float d[8][4];
#pragma unroll
    for (int nt = 0; nt < 8; nt++)
#pragma unroll
        for (int i = 0; i < 4; i++) d[nt][i] = 0.f;

#pragma unroll
    for (int kc = 0; kc < 2; kc++) {
        int base = (m0 + gq) * 20 + kc * 8 + c4;
        unsigned a0 = u.A[base];
        unsigned a1 = u.A[base + 8 * 20];
        unsigned a2 = u.A[base + 4];
        unsigned a3 = u.A[base + 8 * 20 + 4];
#pragma unroll
        for (int nt = 0; nt < 8; nt++) {
            uint2 bb = sB[kc][nt][lane];
            mma_f16(d[nt], a0, a1, a2, a3, bb.x, bb.y);
        }
    }

    __syncthreads();
    {
        const int row0 = m0 + gq;
#pragma unroll
        for (int nt = 0; nt < 8; nt++) {
            int cu = nt * 4 + c4;
            u.Dh[row0 * 36 + cu]       = pack_h2(d[nt][0], d[nt][1]);
            u.Dh[(row0 + 8) * 36 + cu] = pack_h2(d[nt][2], d[nt][3]);
        }
    }
    __syncthreads();

    const int l  = t & 7;
    const int eb = t >> 3;
#pragma unroll
    for (int it = 0; it < 4; it++) {
        int e   = eb + it * 32;
        int dst = s_dst[e];
        int src = s_src[e];
        uint2 Fu = *(uint2*)&u.Dh[e * 36 + 2 * l];
        uint2 Su = *(uint2*)&u.Dh[e * 36 + 16 + 2 * l];
        float2 Fa = unpack_h2(Fu.x), Fb = unpack_h2(Fu.y);
        float2 Sa = unpack_h2(Su.x), Sb = unpack_h2(Su.y);
        uint4 pdv = *(const uint4*)&Pd[(size_t)dst * 32 + 4 * l];
        uint4 pv  = *(const uint4*)&Ps[(size_t)src * 32 + 4 * l];
        float2 p0 = unpack_h2(pdv.x), p1 = unpack_h2(pdv.y);
        float2 p2 = unpack_h2(pdv.z), p3 = unpack_h2(pdv.w);
        float2 q0 = unpack_h2(pv.x),  q1 = unpack_h2(pv.y);
        float2 q2 = unpack_h2(pv.z),  q3 = unpack_h2(pv.w);

        float m0_ = gate_msg(Fa.x + p0.x + q0.x, Sa.x + p0.y + q0.y);
        float m1_ = gate_msg(Fa.y + p1.x + q1.x, Sa.y + p1.y + q1.y);
        float m2_ = gate_msg(Fb.x + p2.x + q2.x, Sb.x + p2.y + q2.y);
        float m3_ = gate_msg(Fb.y + p3.x + q3.x, Sb.y + p3.y + q3.y);

        asm volatile("red.global.add.v4.f32 [%0], {%1,%2,%3,%4};"
            :: "l"(hinout + (size_t)dst * HH + 4 * l),
               "f"(m0_), "f"(m1_), "f"(m2_), "f"(m3_)
            : "memory");
    }
}

// ---------------------------------------------------------------------------
// Kernel 4: out[N,128] = lrelu(bn( h[N,32] @ w_out[128,32]^T + b ))
// ---------------------------------------------------------------------------
__global__ __launch_bounds__(256) void out_kernel(
    const float4* __restrict__ h4,
    const float4* __restrict__ w4,
    const float* __restrict__ b,  const float* __restrict__ g,
    const float* __restrict__ be, const float* __restrict__ mm,
    const float* __restrict__ vv,
    float* __restrict__ out)
{
    __shared__ float4 wp[8 * 128];
    __shared__ float4 xs4[16 * 8];

    const int t = threadIdx.x;
#pragma unroll
    for (int j = 0; j < 4; j++) {
        int i = t + j * 256;
        int k4 = i >> 7, c = i & 127;
        wp[i] = w4[c * 8 + k4];
    }
    const int r0 = blockIdx.x * 16;
    if (t < 128) {
        int r = t >> 3, q = t & 7;
        int gr = r0 + r;
        xs4[t] = (gr < NN) ? h4[(size_t)gr * 8 + q]
                           : make_float4(0.f, 0.f, 0.f, 0.f);
    }
    __syncthreads();

    const int c  = t & 127;
    const int rg = t >> 7;

    float acc[8];
#pragma unroll
    for (int i = 0; i < 8; i++) acc[i] = 0.f;

#pragma unroll
    for (int k4 = 0; k4 < 8; k4++) {
        float4 wv = wp[k4 * 128 + c];
#pragma unroll
        for (int i = 0; i < 8; i++) {
            float4 xv = xs4[(rg * 8 + i) * 8 + k4];
            acc[i] = fmaf(xv.x, wv.x,
                     fmaf(xv.y, wv.y,
                     fmaf(xv.z, wv.z,
                     fmaf(xv.w, wv.w, acc[i]))));
        }
    }

    const float scale = g[c] * rsqrtf(vv[c] + EPS);
    const float shift = be[c] - mm[c] * scale;
    const float bc    = b[c];
#pragma unroll
    for (int i = 0; i < 8; i++) {
        int row = r0 + rg * 8 + i;
        if (row < NN) {
            float val = (acc[i] + bc) * scale + shift;
            out[(size_t)row * DOUT + c] = val > 0.f ? val : SLOPE * val;
        }
    }
}

// ---------------------------------------------------------------------------
// Launch. Order: pack(0) node(1) proj4(2) MERGED(3) proj4(4) fused1(5) out(6)
// — ncu samples launch index 3, so next round profiles the merged kernel.
// ---------------------------------------------------------------------------
extern "C" void kernel_launch(void* const* d_in, const int* in_sizes, int n_in,
                              void* d_out, int out_size)
{
    const float* x     = (const float*)d_in[0];
    const int*   ei    = (const int*)  d_in[1];
    const float* eattr = (const float*)d_in[2];
    const float* w_in  = (const float*)d_in[3];
    const float* b_in  = (const float*)d_in[4];
    const float* g_in  = (const float*)d_in[5];
    const float* be_in = (const float*)d_in[6];
    const float* m_in  = (const float*)d_in[7];
    const float* v_in  = (const float*)d_in[8];
    const float* w_e   = (const float*)d_in[9];
    const float* b_e   = (const float*)d_in[10];
    const float* g_e   = (const float*)d_in[11];
    const float* be_e  = (const float*)d_in[12];
    const float* m_e   = (const float*)d_in[13];
    const float* v_e   = (const float*)d_in[14];
    const float* wf    = (const float*)d_in[15];   // [2,32,96]
    const float* bf    = (const float*)d_in[16];   // [2,32]
    const float* ws    = (const float*)d_in[17];
    const float* bs    = (const float*)d_in[18];
    const float* w_out = (const float*)d_in[19];   // [128,32]
    const float* b_out = (const float*)d_in[20];
    const float* g_out = (const float*)d_in[21];
    const float* be_out= (const float*)d_in[22];
    const float* m_out = (const float*)d_in[23];
    const float* v_out = (const float*)d_in[24];
    float* out = (float*)d_out;

    uint4* eah; float* hA; unsigned *Pd, *Ps; uint2* wfrag;
    cudaGetSymbolAddress((void**)&eah,   g_eah);
    cudaGetSymbolAddress((void**)&hA,    g_hA);
    cudaGetSymbolAddress((void**)&Pd,    g_Pd);
    cudaGetSymbolAddress((void**)&Ps,    g_Ps);
    cudaGetSymbolAddress((void**)&wfrag, g_wfrag);

    // 0) pack weight fragments (tiny)
    pack_wfrags_kernel<<<1, 256>>>(w_e, wf, ws);

    // 1) node embedding
    embed_f16_kernel<false, false><<<(NN + 127) / 128, 256>>>(
        (const float4*)x, NN, w_in,
        b_in, g_in, be_in, m_in, v_in, hA);

    // 2) layer-0 node projections
    proj4_kernel<<<(NN + 31) / 32, 256>>>(
        (const float4*)hA, NN,
        (const float4*)(wf),      (const float4*)(wf + 32),
        (const float4*)(ws),      (const float4*)(ws + 32),
        bf, bs, Pd, Ps);

    // 3) MERGED: edge embed + layer-0 message pass (profiled slot)
    fused_embed_edge_kernel<<<EE / 128, 256>>>(
        ei, (const float4*)eattr,
        b_e, g_e, be_e, m_e, v_e,
        wfrag, wfrag + 1024,
        Pd, Ps, (unsigned*)eah, hA);

    // 4) layer 1
    proj4_kernel<<<(NN + 31) / 32, 256>>>(
        (const float4*)hA, NN,
        (const float4*)(wf + 3072),      (const float4*)(wf + 3072 + 32),
        (const float4*)(ws + 3072),      (const float4*)(ws + 3072 + 32),
        bf + 32, bs + 32, Pd, Ps);
    fused_edge_mma_kernel<<<EE / 128, 256>>>(
        ei, eah, wfrag + 1536, Pd, Ps, hA);

    // 5) output
    out_kernel<<<(NN + 15) / 16, 256>>>(
        (const float4*)hA, (const float4*)w_out,
        b_out, g_out, be_out, m_out, v_out, out);
}

// round 17
// speedup vs baseline: 4.6444x; 1.0396x over previous
#include <cuda_runtime.h>
#include <cuda_fp16.h>
#include <stdint.h>
#include <math.h>

#define NN   50000
#define EE   1600000
#define HH   32
#define DOUT 128
#define EPS  1e-5f
#define SLOPE 0.1f

// ---------------------------------------------------------------------------
// Scratch (device globals). ~116 MB total.
// ---------------------------------------------------------------------------
static __device__ uint4    g_eah[(size_t)EE * 4];     // edge embeddings fp16 [E,32]
static __device__ float    g_hA[(size_t)NN * HH];     // node features (in-place residual)
static __device__ unsigned g_Pd[(size_t)NN * 32];     // (Af+bf, As+bs) half2 per channel
static __device__ unsigned g_Ps[(size_t)NN * 32];     // (Bf, Bs) half2 per channel
static __device__ uint2    g_wfrag[3072];             // packed fp16 W frags:
                                                      // [0,1024)    embed We
                                                      // [1024,1536) layer-0 edge W
                                                      // [1536,2048) layer-1 edge W
                                                      // [2048,3072) layer-0 proj W (16 nt)

// ---------------------------------------------------------------------------
// helpers
// ---------------------------------------------------------------------------
__device__ __forceinline__ unsigned pack_h2(float lo, float hi) {
    __half2 h = __floats2half2_rn(lo, hi);
    return *(unsigned*)&h;
}
__device__ __forceinline__ float2 unpack_h2(unsigned u) {
    return __half22float2(*(__half2*)&u);
}
__device__ __forceinline__ void mma_f16(
    float* d, unsigned a0, unsigned a1, unsigned a2, unsigned a3,
    unsigned b0, unsigned b1)
{
    asm volatile(
        "mma.sync.aligned.m16n8k16.row.col.f32.f16.f16.f32 "
        "{%0,%1,%2,%3}, {%4,%5,%6,%7}, {%8,%9}, {%0,%1,%2,%3};\n"
        : "+f"(d[0]), "+f"(d[1]), "+f"(d[2]), "+f"(d[3])
        : "r"(a0), "r"(a1), "r"(a2), "r"(a3), "r"(b0), "r"(b1));
}
__device__ __forceinline__ unsigned smem_u32(const void* p) {
    unsigned a;
    asm("{ .reg .u64 t; cvta.to.shared.u64 t, %1; cvt.u32.u64 %0, t; }"
        : "=r"(a) : "l"(p));
    return a;
}
// gated message: sigmoid(f) * softplus(s); sigmoid via tanh (1 MUFU vs 2)
__device__ __forceinline__ float gate_msg(float f, float s) {
    float t;
    asm("tanh.approx.f32 %0, %1;" : "=f"(t) : "f"(f * 0.5f));
    float sig = fmaf(t, 0.5f, 0.5f);
    float sp  = fmaxf(s, 0.f) + __logf(1.f + __expf(-fabsf(s)));
    return sig * sp;
}

// ---------------------------------------------------------------------------
// Kernel 0: pack weight fragments (one block; runs once per call).
// ---------------------------------------------------------------------------
__global__ void pack_wfrags_kernel(
    const float* __restrict__ we,              // [32][128]
    const float* __restrict__ wf,              // [2][32][96]
    const float* __restrict__ ws)
{
    const int t = threadIdx.x;    // 256
    // embed We frags: flat = kc*128 + nt*32 + ln (kc<8, nt<4)
    for (int i = t; i < 1024; i += 256) {
        int kc = i >> 7, nt = (i >> 5) & 3, ln = i & 31;
        int g2 = ln >> 2, c2 = ln & 3;
        const float* wrow = we + (nt * 8 + g2) * 128;
        int k0 = kc * 16 + 2 * c2;
        g_wfrag[i] = make_uint2(pack_h2(wrow[k0],     wrow[k0 + 1]),
                                pack_h2(wrow[k0 + 8], wrow[k0 + 9]));
    }
    // edge W frags per layer: flat = kc*256 + nt*32 + ln (kc<2, nt<8)
    for (int l = 0; l < 2; l++) {
        const float* wfe = wf + l * 3072 + 64;
        const float* wse = ws + l * 3072 + 64;
        for (int i = t; i < 512; i += 256) {
            int kc = i >> 8, nt = (i >> 5) & 7, ln = i & 31;
            int g2 = ln >> 2, c2 = ln & 3;
            int n  = nt * 8 + g2;
            const float* wrow = (n < 32) ? (wfe + n * 96) : (wse + (n - 32) * 96);
            int k0 = kc * 16 + 2 * c2;
            g_wfrag[1024 + l * 512 + i] =
                make_uint2(pack_h2(wrow[k0],     wrow[k0 + 1]),
                           pack_h2(wrow[k0 + 8], wrow[k0 + 9]));
        }
    }
    // layer-0 proj frags: n-tile blocks [Wfd|Wsd|Wfs|Wss], flat = kc*512 + nt*32 + ln
    for (int i = t; i < 1024; i += 256) {
        int kc = i >> 9, nt = (i >> 5) & 15, ln = i & 31;
        int g2 = ln >> 2, c2 = ln & 3;
        int nl = (nt & 3) * 8 + g2;
        int sel = nt >> 2;
        const float* wrow =
            (sel == 0) ? (wf + nl * 96) :
            (sel == 1) ? (ws + nl * 96) :
            (sel == 2) ? (wf + nl * 96 + 32) :
                         (ws + nl * 96 + 32);
        int k0 = kc * 16 + 2 * c2;
        g_wfrag[2048 + i] = make_uint2(pack_h2(wrow[k0],     wrow[k0 + 1]),
                                       pack_h2(wrow[k0 + 8], wrow[k0 + 9]));
    }
}

// ---------------------------------------------------------------------------
// Kernel 1 (node embed + FUSED layer-0 projections):
//   h = lrelu(bn(x @ w_in^T + b))        -> hA (fp32) + pa/pb registers
//   P = h @ [Wfd|Wsd|Wfs|Wss]            -> Pd/Ps (fp16, bias folded into Pd)
// ---------------------------------------------------------------------------
__global__ __launch_bounds__(256) void node_embed_proj_kernel(
    const float4* __restrict__ in4, int M,
    const float* __restrict__ w,                      // [32][128] row-major
    const float* __restrict__ b,  const float* __restrict__ g,
    const float* __restrict__ be, const float* __restrict__ mm,
    const float* __restrict__ vv,
    const float* __restrict__ bf, const float* __restrict__ bs,
    const uint2* __restrict__ wfragP,                 // 1024 proj frags
    float* __restrict__ hout,
    unsigned* __restrict__ Pd, unsigned* __restrict__ Ps)
{
    __shared__ unsigned sX[128 * 68];
    __shared__ uint2 sB[8][4][32];
    __shared__ float s_scale[32], s_shift[32], s_bias[32], s_bf[32], s_bs[32];

    const int t    = threadIdx.x;
    const int lane = t & 31;
    const int wid  = t >> 5;
    const int gq   = lane >> 2;
    const int c4   = lane & 3;
    const int r0   = blockIdx.x * 128;
    const int m0   = wid * 16;

    if (t < 32) {
        float sc = g[t] * rsqrtf(vv[t] + EPS);
        s_scale[t] = sc;
        s_shift[t] = be[t] - mm[t] * sc;
        s_bias[t]  = b[t];
        s_bf[t]    = bf[t];
        s_bs[t]    = bs[t];
    }

#pragma unroll
    for (int i = t; i < 1024; i += 256) {
        int kc = i >> 7, nt = (i >> 5) & 3, ln = i & 31;
        int g2 = ln >> 2, c2 = ln & 3;
        const float* wrow = w + (nt * 8 + g2) * 128;
        int k0 = kc * 16 + 2 * c2;
        sB[kc][nt][ln] = make_uint2(pack_h2(wrow[k0],     wrow[k0 + 1]),
                                    pack_h2(wrow[k0 + 8], wrow[k0 + 9]));
    }
#pragma unroll
    for (int j = 0; j < 16; j++) {
        int idx = t + j * 256;
        int r = idx >> 5, q = idx & 31;
        int gr = r0 + r;
        float4 v = (gr < M) ? in4[(size_t)gr * 32 + q]
                            : make_float4(0.f, 0.f, 0.f, 0.f);
        *(uint2*)&sX[r * 68 + q * 2] = make_uint2(pack_h2(v.x, v.y), pack_h2(v.z, v.w));
    }
    __syncthreads();

    const int mi     = lane >> 3;
    const int rowoff = ((mi & 1) << 3) + (lane & 7);
    const int ku     = (mi >> 1) << 2;
    unsigned abase = smem_u32(sX) + (unsigned)(((m0 + rowoff) * 68 + ku) * 4);

    // MMA1: h = x @ w^T
    float d[4][4];
#pragma unroll
    for (int nt = 0; nt < 4; nt++)
#pragma unroll
        for (int i = 0; i < 4; i++) d[nt][i] = 0.f;

#pragma unroll
    for (int kc = 0; kc < 8; kc++) {
        unsigned a0, a1, a2, a3;
        asm volatile("ldmatrix.sync.aligned.m8n8.x4.shared.b16 {%0,%1,%2,%3}, [%4];"
            : "=r"(a0), "=r"(a1), "=r"(a2), "=r"(a3)
            : "r"(abase + kc * 32));
#pragma unroll
        for (int nt = 0; nt < 4; nt++) {
            uint2 bb = sB[kc][nt][lane];
            mma_f16(d[nt], a0, a1, a2, a3, bb.x, bb.y);
        }
    }

    // epilogue: BN + lrelu -> hA (fp32) + packed pa/pb (proj A-frags)
    const int row_lo = r0 + m0 + gq;
    const int row_hi = row_lo + 8;
    unsigned pa[4], pb[4];
#pragma unroll
    for (int nt = 0; nt < 4; nt++) {
        int col = nt * 8 + 2 * c4;
        float sc0 = s_scale[col],     sh0 = s_shift[col],     bb0 = s_bias[col];
        float sc1 = s_scale[col + 1], sh1 = s_shift[col + 1], bb1 = s_bias[col + 1];
        float v0 = (d[nt][0] + bb0) * sc0 + sh0;  v0 = v0 > 0.f ? v0 : SLOPE * v0;
        float v1 = (d[nt][1] + bb1) * sc1 + sh1;  v1 = v1 > 0.f ? v1 : SLOPE * v1;
        float v2 = (d[nt][2] + bb0) * sc0 + sh0;  v2 = v2 > 0.f ? v2 : SLOPE * v2;
        float v3 = (d[nt][3] + bb1) * sc1 + sh1;  v3 = v3 > 0.f ? v3 : SLOPE * v3;
        pa[nt] = pack_h2(v0, v1);
        pb[nt] = pack_h2(v2, v3);
        if (row_lo < M) *(float2*)&hout[(size_t)row_lo * HH + col] = make_float2(v0, v1);
        if (row_hi < M) *(float2*)&hout[(size_t)row_hi * HH + col] = make_float2(v2, v3);
    }

    // MMA2: P = h @ [Wfd|Wsd|Wfs|Wss] (B frags direct from global, L2-resident)
    float d2[16][4];
#pragma unroll
    for (int nt = 0; nt < 16; nt++)
#pragma unroll
        for (int i = 0; i < 4; i++) d2[nt][i] = 0.f;

#pragma unroll
    for (int kc = 0; kc < 2; kc++) {
        unsigned a0 = pa[2 * kc], a1 = pb[2 * kc];
        unsigned a2 = pa[2 * kc + 1], a3 = pb[2 * kc + 1];
#pragma unroll
        for (int nt = 0; nt < 16; nt++) {
            uint2 bb = wfragP[kc * 512 + nt * 32 + lane];
            mma_f16(d2[nt], a0, a1, a2, a3, bb.x, bb.y);
        }
    }

    // P epilogue: pair (fd,sd)->Pd (+bias), (fs,ss)->Ps
#pragma unroll
    for (int nt = 0; nt < 4; nt++) {
        int col = nt * 8 + 2 * c4;
        float bf0 = s_bf[col], bf1 = s_bf[col + 1];
        float bs0 = s_bs[col], bs1 = s_bs[col + 1];
        if (row_lo < M) {
            *(uint2*)&Pd[(size_t)row_lo * 32 + col] = make_uint2(
                pack_h2(d2[nt][0] + bf0, d2[nt + 4][0] + bs0),
                pack_h2(d2[nt][1] + bf1, d2[nt + 4][1] + bs1));
            *(uint2*)&Ps[(size_t)row_lo * 32 + col] = make_uint2(
                pack_h2(d2[nt + 8][0], d2[nt + 12][0]),
                pack_h2(d2[nt + 8][1], d2[nt + 12][1]));
        }
        if (row_hi < M) {
            *(uint2*)&Pd[(size_t)row_hi * 32 + col] = make_uint2(
                pack_h2(d2[nt][2] + bf0, d2[nt + 4][2] + bs0),
                pack_h2(d2[nt][3] + bf1, d2[nt + 4][3] + bs1));
            *(uint2*)&Ps[(size_t)row_hi * 32 + col] = make_uint2(
                pack_h2(d2[nt + 8][2], d2[nt + 12][2]),
                pack_h2(d2[nt + 8][3], d2[nt + 12][3]));
        }
    }
}

// ---------------------------------------------------------------------------
// Kernel 2: node projections (layer 1, fp32 FFMA), outputs packed fp16.
// ---------------------------------------------------------------------------
__global__ __launch_bounds__(256) void proj4_kernel(
    const float4* __restrict__ in4, int M,
    const float4* __restrict__ wfd, const float4* __restrict__ wfs,
    const float4* __restrict__ wsd, const float4* __restrict__ wss,
    const float* __restrict__ bf, const float* __restrict__ bs,
    unsigned* __restrict__ Pd, unsigned* __restrict__ Ps)
{
    __shared__ float4 wp[4][256];
    __shared__ float4 xs4[32 * 8];

    const int t = threadIdx.x;
    {
        int k4 = t >> 5, c = t & 31;
        wp[0][t] = wfd[c * 24 + k4];
        wp[1][t] = wsd[c * 24 + k4];
        wp[2][t] = wfs[c * 24 + k4];
        wp[3][t] = wss[c * 24 + k4];
    }
    const int r0 = blockIdx.x * 32;
    {
        int r = t >> 3, q = t & 7;
        int gr = r0 + r;
        xs4[t] = (gr < M) ? in4[(size_t)gr * 8 + q]
                          : make_float4(0.f, 0.f, 0.f, 0.f);
    }
    __syncthreads();

    const int c  = t & 31;
    const int rg = t >> 5;

    float acc[4][4];
#pragma unroll
    for (int m = 0; m < 4; m++)
#pragma unroll
        for (int i = 0; i < 4; i++) acc[m][i] = 0.f;

#pragma unroll
    for (int k4 = 0; k4 < 8; k4++) {
        float4 xv[4];
#pragma unroll
        for (int i = 0; i < 4; i++) xv[i] = xs4[(rg * 4 + i) * 8 + k4];
#pragma unroll
        for (int m = 0; m < 4; m++) {
            float4 wv = wp[m][k4 * 32 + c];
#pragma unroll
            for (int i = 0; i < 4; i++) {
                acc[m][i] = fmaf(xv[i].x, wv.x,
                            fmaf(xv[i].y, wv.y,
                            fmaf(xv[i].z, wv.z,
                            fmaf(xv[i].w, wv.w, acc[m][i]))));
            }
        }
    }

    const float bfc = bf[c], bsc = bs[c];
#pragma unroll
    for (int i = 0; i < 4; i++) {
        int row = r0 + rg * 4 + i;
        if (row < M) {
            Pd[(size_t)row * 32 + c] = pack_h2(acc[0][i] + bfc, acc[1][i] + bsc);
            Ps[(size_t)row * 32 + c] = pack_h2(acc[2][i], acc[3][i]);
        }
    }
}

// ---------------------------------------------------------------------------
// Kernel 3a (MERGED layer 0): edge embed + edge layer. minBlocks=4.
// ---------------------------------------------------------------------------
__global__ __launch_bounds__(256, 4) void fused_embed_edge_kernel(
    const int* __restrict__ ei,
    const float4* __restrict__ eattr4,        // [E][32] fp32
    const float* __restrict__ b,  const float* __restrict__ g,
    const float* __restrict__ be, const float* __restrict__ mm,
    const float* __restrict__ vv,
    const uint2* __restrict__ wfragE,          // 1024 entries (embed)
    const uint2* __restrict__ wfragL,          // 512 entries (edge, this layer)
    const unsigned* __restrict__ Pd, const unsigned* __restrict__ Ps,
    unsigned* __restrict__ eah_out,
    float* __restrict__ hinout)
{
    __shared__ union {
        unsigned X[128 * 68];
        unsigned Dh[128 * 36];
    } u;
    __shared__ uint2 sBe[8][4][32];
    __shared__ uint2 sB[2][8][32];
    __shared__ int s_src[128], s_dst[128];
    __shared__ float s_scale[32], s_shift[32], s_bias[32];

    const int t    = threadIdx.x;
    const int lane = t & 31;
    const int wid  = t >> 5;
    const int gq   = lane >> 2;
    const int c4   = lane & 3;
    const int e0   = blockIdx.x * 128;
    const int m0   = wid * 16;

    if (t < 32) {
        float sc = g[t] * rsqrtf(vv[t] + EPS);
        s_scale[t] = sc;
        s_shift[t] = be[t] - mm[t] * sc;
        s_bias[t]  = b[t];
    }
    {
        uint2* be_f = &sBe[0][0][0];
#pragma unroll
        for (int i = t; i < 1024; i += 256) be_f[i] = wfragE[i];
        uint2* b_f = &sB[0][0][0];
#pragma unroll
        for (int i = t; i < 512; i += 256) b_f[i] = wfragL[i];
    }
    if (t < 128)       s_src[t]       = ei[e0 + t];
    else               s_dst[t - 128] = ei[(size_t)EE + e0 + (t - 128)];

#pragma unroll
    for (int j = 0; j < 16; j++) {
        int idx = t + j * 256;
        int r = idx >> 5, q = idx & 31;
        float4 v = eattr4[(size_t)(e0 + r) * 32 + q];
        *(uint2*)&u.X[r * 68 + q * 2] = make_uint2(pack_h2(v.x, v.y), pack_h2(v.z, v.w));
    }
    __syncthreads();

    const int mi     = lane >> 3;
    const int rowoff = ((mi & 1) << 3) + (lane & 7);
    const int ku     = (mi >> 1) << 2;
    unsigned abase = smem_u32(u.X) + (unsigned)(((m0 + rowoff) * 68 + ku) * 4);

    float d[4][4];
#pragma unroll
    for (int nt = 0; nt < 4; nt++)
#pragma unroll
        for (int i = 0; i < 4; i++) d[nt][i] = 0.f;

#pragma unroll
    for (int kc = 0; kc < 8; kc++) {
        unsigned a0, a1, a2, a3;
        asm volatile("ldmatrix.sync.aligned.m8n8.x4.shared.b16 {%0,%1,%2,%3}, [%4];"
            : "=r"(a0), "=r"(a1), "=r"(a2), "=r"(a3)
            : "r"(abase + kc * 32));
#pragma unroll
        for (int nt = 0; nt < 4; nt++) {
            uint2 bb = sBe[kc][nt][lane];
            mma_f16(d[nt], a0, a1, a2, a3, bb.x, bb.y);
        }
    }

    unsigned pa[4], pb[4];
#pragma unroll
    for (int nt = 0; nt < 4; nt++) {
        int col = nt * 8 + 2 * c4;
        float sc0 = s_scale[col],     sh0 = s_shift[col],     bb0 = s_bias[col];
        float sc1 = s_scale[col + 1], sh1 = s_shift[col + 1], bb1 = s_bias[col + 1];
        float v0 = (d[nt][0] + bb0) * sc0 + sh0;  v0 = v0 > 0.f ? v0 : SLOPE * v0;
        float v1 = (d[nt][1] + bb1) * sc1 + sh1;  v1 = v1 > 0.f ? v1 : SLOPE * v1;
        float v2 = (d[nt][2] + bb0) * sc0 + sh0;  v2 = v2 > 0.f ? v2 : SLOPE * v2;
        float v3 = (d[nt][3] + bb1) * sc1 + sh1;  v3 = v3 > 0.f ? v3 : SLOPE * v3;
        pa[nt] = pack_h2(v0, v1);
        pb[nt] = pack_h2(v2, v3);
        size_t row_lo = (size_t)(e0 + m0 + gq);
        eah_out[row_lo * 16 + (col >> 1)]       = pa[nt];
        eah_out[(row_lo + 8) * 16 + (col >> 1)] = pb[nt];
    }

    float d2[8][4];
#pragma unroll
    for (int nt = 0; nt < 8; nt++)
#pragma unroll
        for (int i = 0; i < 4; i++) d2[nt][i] = 0.f;

#pragma unroll
    for (int kc = 0; kc < 2; kc++) {
        unsigned a0 = pa[2 * kc], a1 = pb[2 * kc];
        unsigned a2 = pa[2 * kc + 1], a3 = pb[2 * kc + 1];
#pragma unroll
        for (int nt = 0; nt < 8; nt++) {
            uint2 bb = sB[kc][nt][lane];
            mma_f16(d2[nt], a0, a1, a2, a3, bb.x, bb.y);
        }
    }

    __syncthreads();
    {
        const int row0 = m0 + gq;
#pragma unroll
        for (int nt = 0; nt < 8; nt++) {
            int cu = nt * 4 + c4;
            u.Dh[row0 * 36 + cu]       = pack_h2(d2[nt][0], d2[nt][1]);
            u.Dh[(row0 + 8) * 36 + cu] = pack_h2(d2[nt][2], d2[nt][3]);
        }
    }
    __syncthreads();

    const int l  = t & 7;
    const int eb = t >> 3;
#pragma unroll
    for (int it = 0; it < 4; it++) {
        int e   = eb + it * 32;
        int dst = s_dst[e];
        int src = s_src[e];
        uint2 Fu = *(uint2*)&u.Dh[e * 36 + 2 * l];
        uint2 Su = *(uint2*)&u.Dh[e * 36 + 16 + 2 * l];
        float2 Fa = unpack_h2(Fu.x), Fb = unpack_h2(Fu.y);
        float2 Sa = unpack_h2(Su.x), Sb = unpack_h2(Su.y);
        uint4 pdv = *(const uint4*)&Pd[(size_t)dst * 32 + 4 * l];
        uint4 pv  = *(const uint4*)&Ps[(size_t)src * 32 + 4 * l];
        float2 p0 = unpack_h2(pdv.x), p1 = unpack_h2(pdv.y);
        float2 p2 = unpack_h2(pdv.z), p3 = unpack_h2(pdv.w);
        float2 q0 = unpack_h2(pv.x),  q1 = unpack_h2(pv.y);
        float2 q2 = unpack_h2(pv.z),  q3 = unpack_h2(pv.w);

        float m0_ = gate_msg(Fa.x + p0.x + q0.x, Sa.x + p0.y + q0.y);
        float m1_ = gate_msg(Fa.y + p1.x + q1.x, Sa.y + p1.y + q1.y);
        float m2_ = gate_msg(Fb.x + p2.x + q2.x, Sb.x + p2.y + q2.y);
        float m3_ = gate_msg(Fb.y + p3.x + q3.x, Sb.y + p3.y + q3.y);

        asm volatile("red.global.add.v4.f32 [%0], {%1,%2,%3,%4};"
            :: "l"(hinout + (size_t)dst * HH + 4 * l),
               "f"(m0_), "f"(m1_), "f"(m2_), "f"(m3_)
            : "memory");
    }
}

// ---------------------------------------------------------------------------
// Kernel 3b (fused edge layer 1): cp.async A-tile; minBlocks=4.
// ---------------------------------------------------------------------------
__global__ __launch_bounds__(256, 4) void fused_edge_mma_kernel(
    const int* __restrict__ ei,
    const uint4* __restrict__ ea16,
    const uint2* __restrict__ wfragL,
    const unsigned* __restrict__ Pd, const unsigned* __restrict__ Ps,
    float* __restrict__ hinout)
{
    __shared__ union {
        unsigned A[128 * 20];
        unsigned Dh[128 * 36];
    } u;
    __shared__ uint2 sB[2][8][32];
    __shared__ int s_src[128], s_dst[128];

    const int t  = threadIdx.x;
    const int e0 = blockIdx.x * 128;

    {
        unsigned sa = smem_u32(u.A);
#pragma unroll
        for (int j = 0; j < 2; j++) {
            int idx = t + j * 256;
            int r = idx >> 2, q = idx & 3;
            unsigned dstp = sa + (unsigned)((r * 20 + q * 4) * 4);
            const uint4* gp = &ea16[(size_t)(e0 + r) * 4 + q];
            asm volatile("cp.async.ca.shared.global [%0], [%1], 16;"
                :: "r"(dstp), "l"(gp));
        }
        asm volatile("cp.async.commit_group;");
    }
    if (t < 128)       s_src[t]       = ei[e0 + t];
    else               s_dst[t - 128] = ei[(size_t)EE + e0 + (t - 128)];
    {
        uint2* b_f = &sB[0][0][0];
#pragma unroll
        for (int i = t; i < 512; i += 256) b_f[i] = wfragL[i];
    }
    asm volatile("cp.async.wait_group 0;" ::: "memory");
    __syncthreads();

    const int lane = t & 31;
    const int wid  = t >> 5;
    const int gq   = lane >> 2;
    const int c4   = lane & 3;
    const int m0   = wid * 16;

    float d[8][4];
#pragma unroll
    for (int nt = 0; nt < 8; nt++)
#pragma unroll
        for (int i = 0; i < 4; i++) d[nt][i] = 0.f;

#pragma unroll
    for (int kc = 0; kc < 2; kc++) {
        int base = (m0 + gq) * 20 + kc * 8 + c4;
        unsigned a0 = u.A[base];
        unsigned a1 = u.A[base + 8 * 20];
        unsigned a2 = u.A[base + 4];
        unsigned a3 = u.A[base + 8 * 20 + 4];
#pragma unroll
        for (int nt = 0; nt < 8; nt++) {
            uint2 bb = sB[kc][nt][lane];
            mma_f16(d[nt], a0, a1, a2, a3, bb.x, bb.y);
        }
    }

    __syncthreads();
    {
        const int row0 = m0 + gq;
#pragma unroll
        for (int nt = 0; nt < 8; nt++) {
            int cu = nt * 4 + c4;
            u.Dh[row0 * 36 + cu]       = pack_h2(d[nt][0], d[nt][1]);
            u.Dh[(row0 + 8) * 36 + cu] = pack_h2(d[nt][2], d[nt][3]);
        }
    }
    __syncthreads();

    const int l  = t & 7;
    const int eb = t >> 3;
#pragma unroll
    for (int it = 0; it < 4; it++) {
        int e   = eb + it * 32;
        int dst = s_dst[e];
        int src = s_src[e];
        uint2 Fu = *(uint2*)&u.Dh[e * 36 + 2 * l];
        uint2 Su = *(uint2*)&u.Dh[e * 36 + 16 + 2 * l];
        float2 Fa = unpack_h2(Fu.x), Fb = unpack_h2(Fu.y);
        float2 Sa = unpack_h2(Su.x), Sb = unpack_h2(Su.y);
        uint4 pdv = *(const uint4*)&Pd[(size_t)dst * 32 + 4 * l];
        uint4 pv  = *(const uint4*)&Ps[(size_t)src * 32 + 4 * l];
        float2 p0 = unpack_h2(pdv.x), p1 = unpack_h2(pdv.y);
        float2 p2 = unpack_h2(pdv.z), p3 = unpack_h2(pdv.w);
        float2 q0 = unpack_h2(pv.x),  q1 = unpack_h2(pv.y);
        float2 q2 = unpack_h2(pv.z),  q3 = unpack_h2(pv.w);

        float m0_ = gate_msg(Fa.x + p0.x + q0.x, Sa.x + p0.y + q0.y);
        float m1_ = gate_msg(Fa.y + p1.x + q1.x, Sa.y + p1.y + q1.y);
        float m2_ = gate_msg(Fb.x + p2.x + q2.x, Sb.x + p2.y + q2.y);
        float m3_ = gate_msg(Fb.y + p3.x + q3.x, Sb.y + p3.y + q3.y);

        asm volatile("red.global.add.v4.f32 [%0], {%1,%2,%3,%4};"
            :: "l"(hinout + (size_t)dst * HH + 4 * l),
               "f"(m0_), "f"(m1_), "f"(m2_), "f"(m3_)
            : "memory");
    }
}

// ---------------------------------------------------------------------------
// Kernel 4: out[N,128] = lrelu(bn( h[N,32] @ w_out[128,32]^T + b ))
// ---------------------------------------------------------------------------
__global__ __launch_bounds__(256) void out_kernel(
    const float4* __restrict__ h4,
    const float4* __restrict__ w4,
    const float* __restrict__ b,  const float* __restrict__ g,
    const float* __restrict__ be, const float* __restrict__ mm,
    const float* __restrict__ vv,
    float* __restrict__ out)
{
    __shared__ float4 wp[8 * 128];
    __shared__ float4 xs4[16 * 8];

    const int t = threadIdx.x;
#pragma unroll
    for (int j = 0; j < 4; j++) {
        int i = t + j * 256;
        int k4 = i >> 7, c = i & 127;
        wp[i] = w4[c * 8 + k4];
    }
    const int r0 = blockIdx.x * 16;
    if (t < 128) {
        int r = t >> 3, q = t & 7;
        int gr = r0 + r;
        xs4[t] = (gr < NN) ? h4[(size_t)gr * 8 + q]
                           : make_float4(0.f, 0.f, 0.f, 0.f);
    }
    __syncthreads();

    const int c  = t & 127;
    const int rg = t >> 7;

    float acc[8];
#pragma unroll
    for (int i = 0; i < 8; i++) acc[i] = 0.f;

#pragma unroll
    for (int k4 = 0; k4 < 8; k4++) {
        float4 wv = wp[k4 * 128 + c];
#pragma unroll
        for (int i = 0; i < 8; i++) {
            float4 xv = xs4[(rg * 8 + i) * 8 + k4];
            acc[i] = fmaf(xv.x, wv.x,
                     fmaf(xv.y, wv.y,
                     fmaf(xv.z, wv.z,
                     fmaf(xv.w, wv.w, acc[i]))));
        }
    }

    const float scale = g[c] * rsqrtf(vv[c] + EPS);
    const float shift = be[c] - mm[c] * scale;
    const float bc    = b[c];
#pragma unroll
    for (int i = 0; i < 8; i++) {
        int row = r0 + rg * 8 + i;
        if (row < NN) {
            float val = (acc[i] + bc) * scale + shift;
            out[(size_t)row * DOUT + c] = val > 0.f ? val : SLOPE * val;
        }
    }
}

// ---------------------------------------------------------------------------
// Launch
// ---------------------------------------------------------------------------
extern "C" void kernel_launch(void* const* d_in, const int* in_sizes, int n_in,
                              void* d_out, int out_size)
{
    const float* x     = (const float*)d_in[0];
    const int*   ei    = (const int*)  d_in[1];
    const float* eattr = (const float*)d_in[2];
    const float* w_in  = (const float*)d_in[3];
    const float* b_in  = (const float*)d_in[4];
    const float* g_in  = (const float*)d_in[5];
    const float* be_in = (const float*)d_in[6];
    const float* m_in  = (const float*)d_in[7];
    const float* v_in  = (const float*)d_in[8];
    const float* w_e   = (const float*)d_in[9];
    const float* b_e   = (const float*)d_in[10];
    const float* g_e   = (const float*)d_in[11];
    const float* be_e  = (const float*)d_in[12];
    const float* m_e   = (const float*)d_in[13];
    const float* v_e   = (const float*)d_in[14];
    const float* wf    = (const float*)d_in[15];   // [2,32,96]
    const float* bf    = (const float*)d_in[16];   // [2,32]
    const float* ws    = (const float*)d_in[17];
    const float* bs    = (const float*)d_in[18];
    const float* w_out = (const float*)d_in[19];   // [128,32]
    const float* b_out = (const float*)d_in[20];
    const float* g_out = (const float*)d_in[21];
    const float* be_out= (const float*)d_in[22];
    const float* m_out = (const float*)d_in[23];
    const float* v_out = (const float*)d_in[24];
    float* out = (float*)d_out;

    uint4* eah; float* hA; unsigned *Pd, *Ps; uint2* wfrag;
    cudaGetSymbolAddress((void**)&eah,   g_eah);
    cudaGetSymbolAddress((void**)&hA,    g_hA);
    cudaGetSymbolAddress((void**)&Pd,    g_Pd);
    cudaGetSymbolAddress((void**)&Ps,    g_Ps);
    cudaGetSymbolAddress((void**)&wfrag, g_wfrag);

    // 0) pack weight fragments (tiny)
    pack_wfrags_kernel<<<1, 256>>>(w_e, wf, ws);

    // 1) node embedding + fused layer-0 projections
    node_embed_proj_kernel<<<(NN + 127) / 128, 256>>>(
        (const float4*)x, NN, w_in,
        b_in, g_in, be_in, m_in, v_in,
        bf, bs, wfrag + 2048,
        hA, Pd, Ps);

    // 2) MERGED: edge embed + layer-0 message pass (writes eah for layer 1)
    fused_embed_edge_kernel<<<EE / 128, 256>>>(
        ei, (const float4*)eattr,
        b_e, g_e, be_e, m_e, v_e,
        wfrag, wfrag + 1024,
        Pd, Ps, (unsigned*)eah, hA);

    // 3) layer 1
    proj4_kernel<<<(NN + 31) / 32, 256>>>(
        (const float4*)hA, NN,
        (const float4*)(wf + 3072),      (const float4*)(wf + 3072 + 32),
        (const float4*)(ws + 3072),      (const float4*)(ws + 3072 + 32),
        bf + 32, bs + 32, Pd, Ps);
    fused_edge_mma_kernel<<<EE / 128, 256>>>(
        ei, eah, wfrag + 1536, Pd, Ps, hA);

    // 4) output
    out_kernel<<<(NN + 15) / 16, 256>>>(
        (const float4*)hA, (const float4*)w_out,
        b_out, g_out, be_out, m_out, v_out, out);
}